// round 5
// baseline (speedup 1.0000x reference)
#include <cuda_runtime.h>
#include <cuda_bf16.h>
#include <math.h>

#define NATOMS 8000
#define NEDGES 100000
#define NTRIP  500000
#define NGRAPHS 64
#define HD 128
#define NR 6
#define NSNR 42
#define NB 8
#define NBLK 6

// ---------------- device scratch (no allocation allowed) ----------------
__device__ float g_XSAVE[(size_t)(NBLK + 1) * NEDGES * HD];   // x snapshot per block
__device__ float g_XJI [NEDGES*HD];
__device__ float g_XKJ [NEDGES*HD];
__device__ float g_T1  [NEDGES*HD];
__device__ float g_SBFP[(size_t)NTRIP*NBLK*NB];
__device__ float g_AEMB[(size_t)NEDGES*3*HD];                  // embed input [E,384]
__device__ __nv_bfloat16 g_Gh[(size_t)NEDGES*NB*HD];           // G in bf16
__device__ float g_WT  [HD*NB*HD];
__device__ float g_ATOM7 [(size_t)7*NATOMS*HD];
__device__ float g_ATOM7B[(size_t)7*NATOMS*HD];
// pre-rounded (tf32) weight copies
#define WR_EMB   0
#define WR_JI    (WR_EMB  + 3*HD*HD)
#define WR_KJ    (WR_JI   + NBLK*HD*HD)
#define WR_BEF   (WR_KJ   + NBLK*HD*HD)
#define WR_LIN   (WR_BEF  + NBLK*2*HD*HD)
#define WR_AFT   (WR_LIN  + NBLK*HD*HD)
#define WR_OUT   (WR_AFT  + NBLK*4*HD*HD)
#define WR_TOTAL (WR_OUT  + 7*3*HD*HD)
__device__ float g_WR[WR_TOTAL];

__device__ __forceinline__ float silu(float x) { return x / (1.0f + expf(-x)); }

__device__ __forceinline__ float roundtf(float x) {
    unsigned r;
    asm("cvt.rna.tf32.f32 %0, %1;" : "=r"(r) : "f"(x));
    return __uint_as_float(r);
}

__device__ __forceinline__ void mma_tf32(float* c, const unsigned* a, const unsigned* b) {
    asm volatile(
        "mma.sync.aligned.m16n8k8.row.col.f32.tf32.tf32.f32 "
        "{%0,%1,%2,%3}, {%4,%5,%6,%7}, {%8,%9}, {%0,%1,%2,%3};"
        : "+f"(c[0]), "+f"(c[1]), "+f"(c[2]), "+f"(c[3])
        : "r"(a[0]), "r"(a[1]), "r"(a[2]), "r"(a[3]),
          "r"(b[0]), "r"(b[1]));
}

__device__ __forceinline__ void cp16(unsigned saddr, const float* g, int valid) {
    asm volatile("cp.async.cg.shared.global [%0], [%1], 16, %2;"
                 :: "r"(saddr), "l"(g), "r"(valid) : "memory");
}

// ---------------- round-copy: dst = tf32_round(src) ----------------
__global__ void round_copy_k(const float* __restrict__ src, float* __restrict__ dst, int n)
{
    int i = blockIdx.x * blockDim.x + threadIdx.x;
    if (i < n) dst[i] = roundtf(src[i]);
}

// ---------------- tf32 tensor-core GEMM: C = epi(A[M,K] @ B[K,N] + bias) ----------------
// Inputs assumed tf32-pre-rounded (no cvt in mainloop).
// epi: (optional silu) -> (optional * (rbf@rbfw)) -> (optional +addv);
// optional bf16 output; optional tf32 rounding of fp32 output.
#define AS_STRIDE 20
#define BS_STRIDE 136
__global__ __launch_bounds__(256, 2) void gemm_tf32(
    const float* __restrict__ A, const float* __restrict__ B,
    const float* __restrict__ bias, const float* __restrict__ addv,
    const float* __restrict__ rbfv, const float* __restrict__ rbfw,
    void* __restrict__ Cv,
    int M, int N, int K, int act, int outBf16, int roundOut,
    size_t aZ, size_t bZ, size_t biasZ, size_t cZ)
{
    __shared__ float As[2][128 * AS_STRIDE];
    __shared__ float Bs[2][16 * BS_STRIDE];

    A += blockIdx.z * aZ;
    B += blockIdx.z * bZ;
    if (bias) bias += blockIdx.z * biasZ;

    const int tid = threadIdx.x;
    const int bM = blockIdx.y * 128;
    const int bN = blockIdx.x * 128;
    const int lane = tid & 31, warp = tid >> 5;
    const int gid = lane >> 2, tig = lane & 3;
    const int wm = warp >> 2, wn = warp & 3;     // 2 x 4 warp grid; warp tile 64x32

    float c[4][4][4];
#pragma unroll
    for (int i = 0; i < 4; i++)
#pragma unroll
        for (int j = 0; j < 4; j++)
#pragma unroll
            for (int q = 0; q < 4; q++) c[i][j][q] = 0.f;

    const int ar0 = tid >> 2, ak0 = (tid & 3) * 4;     // rows 0..63
    const int ar1 = ar0 + 64;
    const int br0 = tid >> 5, bc0 = (tid & 31) * 4;    // rows 0..7
    const int br1 = br0 + 8;

    unsigned sA = (unsigned)__cvta_generic_to_shared(&As[0][0]);
    unsigned sB = (unsigned)__cvta_generic_to_shared(&Bs[0][0]);
    const unsigned aBufB = 128 * AS_STRIDE * 4;
    const unsigned bBufB = 16 * BS_STRIDE * 4;

    auto issue = [&](int buf, int k0) {
        cp16(sA + buf * aBufB + (ar0 * AS_STRIDE + ak0) * 4,
             A + (size_t)(bM + ar0) * K + k0 + ak0, (bM + ar0) < M ? 16 : 0);
        cp16(sA + buf * aBufB + (ar1 * AS_STRIDE + ak0) * 4,
             A + (size_t)(bM + ar1) * K + k0 + ak0, (bM + ar1) < M ? 16 : 0);
        cp16(sB + buf * bBufB + (br0 * BS_STRIDE + bc0) * 4,
             B + (size_t)(k0 + br0) * N + bN + bc0, 16);
        cp16(sB + buf * bBufB + (br1 * BS_STRIDE + bc0) * 4,
             B + (size_t)(k0 + br1) * N + bN + bc0, 16);
        asm volatile("cp.async.commit_group;" ::: "memory");
    };

    const int nk = K >> 4;
    issue(0, 0);

    for (int kt = 0; kt < nk; kt++) {
        if (kt + 1 < nk) {
            issue((kt + 1) & 1, (kt + 1) * 16);
            asm volatile("cp.async.wait_group 1;" ::: "memory");
        } else {
            asm volatile("cp.async.wait_group 0;" ::: "memory");
        }
        __syncthreads();

        const float* as = As[kt & 1];
        const float* bs = Bs[kt & 1];
#pragma unroll
        for (int kk = 0; kk < 16; kk += 8) {
            unsigned af[4][4], bf[4][2];
#pragma unroll
            for (int fm = 0; fm < 4; fm++) {
                int m0 = wm * 64 + fm * 16;
                af[fm][0] = __float_as_uint(as[(m0 + gid) * AS_STRIDE + kk + tig]);
                af[fm][1] = __float_as_uint(as[(m0 + gid + 8) * AS_STRIDE + kk + tig]);
                af[fm][2] = __float_as_uint(as[(m0 + gid) * AS_STRIDE + kk + tig + 4]);
                af[fm][3] = __float_as_uint(as[(m0 + gid + 8) * AS_STRIDE + kk + tig + 4]);
            }
#pragma unroll
            for (int fn = 0; fn < 4; fn++) {
                int n0 = wn * 32 + fn * 8;
                bf[fn][0] = __float_as_uint(bs[(kk + tig) * BS_STRIDE + n0 + gid]);
                bf[fn][1] = __float_as_uint(bs[(kk + tig + 4) * BS_STRIDE + n0 + gid]);
            }
#pragma unroll
            for (int fm = 0; fm < 4; fm++)
#pragma unroll
                for (int fn = 0; fn < 4; fn++)
                    mma_tf32(c[fm][fn], af[fm], bf[fn]);
        }
        __syncthreads();
    }

    // epilogue
    float* Cf = (float*)Cv + blockIdx.z * cZ;
    __nv_bfloat16* Ch = (__nv_bfloat16*)Cv + blockIdx.z * cZ;

#pragma unroll
    for (int fm = 0; fm < 4; fm++) {
#pragma unroll
        for (int half = 0; half < 2; half++) {
            int row = bM + wm * 64 + fm * 16 + gid + half * 8;
            if (row >= M) continue;
            float rr[NR];
            if (rbfv) {
#pragma unroll
                for (int r = 0; r < NR; r++) rr[r] = rbfv[(size_t)row * NR + r];
            }
#pragma unroll
            for (int fn = 0; fn < 4; fn++) {
                int col = bN + wn * 32 + fn * 8 + tig * 2;
                float v0 = c[fm][fn][half * 2 + 0] + (bias ? bias[col] : 0.f);
                float v1 = c[fm][fn][half * 2 + 1] + (bias ? bias[col + 1] : 0.f);
                if (act) { v0 = silu(v0); v1 = silu(v1); }
                size_t base = (size_t)row * N + col;
                if (rbfv) {
                    float rp0 = 0.f, rp1 = 0.f;
#pragma unroll
                    for (int r = 0; r < NR; r++) {
                        rp0 += rr[r] * rbfw[r * HD + col];
                        rp1 += rr[r] * rbfw[r * HD + col + 1];
                    }
                    v0 *= rp0; v1 *= rp1;
                }
                if (addv) {
                    float2 av = *(const float2*)(addv + base);
                    v0 += av.x; v1 += av.y;
                }
                if (outBf16) {
                    *(__nv_bfloat162*)(Ch + base) =
                        __float22bfloat162_rn(make_float2(v0, v1));
                } else {
                    if (roundOut) { v0 = roundtf(v0); v1 = roundtf(v1); }
                    *(float2*)(Cf + base) = make_float2(v0, v1);
                }
            }
        }
    }
}

// ---------------- embedding: build A_emb[E,384] = [h_i | h_j | silu(rbf@W+b)] (tf32) --------
__global__ void embed_fill_k(const int* __restrict__ z, const int* __restrict__ ei,
                             const int* __restrict__ ej, const float* __restrict__ rbf,
                             const float* __restrict__ emb_table,
                             const float* __restrict__ erw, const float* __restrict__ erb,
                             float* __restrict__ Aemb)
{
    int e = blockIdx.x, h = threadIdx.x;
    int zi = z[ei[e]], zj = z[ej[e]];
    float s = erb[h];
    const float* rr = rbf + (size_t)e * NR;
#pragma unroll
    for (int r = 0; r < NR; r++) s += rr[r] * erw[r * HD + h];
    size_t base = (size_t)e * (3 * HD);
    Aemb[base + h]           = roundtf(emb_table[(size_t)zi * HD + h]);
    Aemb[base + HD + h]      = roundtf(emb_table[(size_t)zj * HD + h]);
    Aemb[base + 2 * HD + h]  = roundtf(silu(s));
}

// ---------------- sbf projection, ALL blocks: SBFP[t, b*8+j] ----------------
__global__ void sbfp_all_k(const float* __restrict__ sbf, const float* __restrict__ w,
                           float* __restrict__ outp)
{
    __shared__ float ws[NBLK * NSNR * NB];   // 2016 floats
    for (int idx = threadIdx.x; idx < NBLK * NSNR * NB; idx += blockDim.x) ws[idx] = w[idx];
    __syncthreads();
    int t = blockIdx.x * blockDim.x + threadIdx.x;
    if (t >= NTRIP) return;
    float sr[NSNR];
    const float* s = sbf + (size_t)t * NSNR;
#pragma unroll
    for (int r = 0; r < NSNR; r++) sr[r] = s[r];
    float* op = outp + (size_t)t * (NBLK * NB);
#pragma unroll
    for (int b = 0; b < NBLK; b++) {
        float acc[NB];
#pragma unroll
        for (int j = 0; j < NB; j++) acc[j] = 0.f;
        for (int r = 0; r < NSNR; r++) {
            float sv = sr[r];
#pragma unroll
            for (int j = 0; j < NB; j++) acc[j] += sv * ws[b * NSNR * NB + r * NB + j];
        }
#pragma unroll
        for (int j = 0; j < NB; j++) op[b * NB + j] = acc[j];
    }
}

// ---------------- W transpose + tf32 round ----------------
__global__ void wt_k(const float* __restrict__ W, float* __restrict__ WT)
{
    int idx = blockIdx.x * blockDim.x + threadIdx.x;   // 131072 elems
    int l = idx >> 10;
    int rest = idx & 1023;
    int j = rest >> 7;
    int i = rest & 127;
    WT[idx] = roundtf(W[(size_t)i * (NB * HD) + j * HD + l]);
}

// ---------------- triplet scatter: M[idx_ji[w],:] += sum_j sbf_p[w,j] * Gh[idx_kj[w], j, :] --
__global__ __launch_bounds__(256) void trip_k(
    const __nv_bfloat16* __restrict__ Gh, const float* __restrict__ sbfp,
    const int* __restrict__ idx_kj, const int* __restrict__ idx_ji,
    float* __restrict__ Mo)
{
    int w = blockIdx.x * (blockDim.x >> 5) + (threadIdx.x >> 5);
    if (w >= NTRIP) return;
    int lane = threadIdx.x & 31;
    int kj = idx_kj[w], ji = idx_ji[w];
    float sv = (lane < NB) ? sbfp[(size_t)w * (NBLK * NB) + lane] : 0.f;
    const __nv_bfloat16* gr = Gh + (size_t)kj * (NB * HD) + lane * 4;
    float4 acc = make_float4(0.f, 0.f, 0.f, 0.f);
#pragma unroll
    for (int j = 0; j < NB; j++) {
        float s = __shfl_sync(0xffffffffu, sv, j);
        uint2 u = *(const uint2*)(gr + j * HD);
        __nv_bfloat162 p0 = *reinterpret_cast<__nv_bfloat162*>(&u.x);
        __nv_bfloat162 p1 = *reinterpret_cast<__nv_bfloat162*>(&u.y);
        float2 f0 = __bfloat1622float2(p0);
        float2 f1 = __bfloat1622float2(p1);
        acc.x += s * f0.x; acc.y += s * f0.y; acc.z += s * f1.x; acc.w += s * f1.y;
    }
    float* mo = Mo + (size_t)ji * HD + lane * 4;
    atomicAdd(mo + 0, acc.x);
    atomicAdd(mo + 1, acc.y);
    atomicAdd(mo + 2, acc.z);
    atomicAdd(mo + 3, acc.w);
}

// ---------------- batched out-block edge scatter over k=0..6 -----------------
__global__ void edge_scatter7_k(const float* __restrict__ rbf, const float* __restrict__ orw,
                                const float* __restrict__ xsave, const int* __restrict__ ei,
                                float* __restrict__ atom)
{
    int e = blockIdx.x, k = blockIdx.y, h = threadIdx.x;
    const float* rr = rbf + (size_t)e * NR;
    const float* w = orw + (size_t)k * NR * HD;
    float rp = 0.f;
#pragma unroll
    for (int r = 0; r < NR; r++) rp += rr[r] * w[r * HD + h];
    float v = rp * xsave[(size_t)k * NEDGES * HD + (size_t)e * HD + h];
    atomicAdd(&atom[(size_t)k * NATOMS * HD + (size_t)ei[e] * HD + h], v);
}

// ---------------- batched final per-atom dot + graph segment sum ----------------
__global__ void dot7_k(const float* __restrict__ atom2, const float* __restrict__ ow,
                       const int* __restrict__ batch, float* __restrict__ out)
{
    int a = blockIdx.x * (blockDim.x >> 5) + (threadIdx.x >> 5);
    if (a >= NATOMS) return;
    int k = blockIdx.y;
    int lane = threadIdx.x & 31;
    const float* ar = atom2 + (size_t)k * NATOMS * HD + (size_t)a * HD + lane * 4;
    const float* wr = ow + (size_t)k * HD + lane * 4;
    float s = ar[0] * wr[0] + ar[1] * wr[1] + ar[2] * wr[2] + ar[3] * wr[3];
#pragma unroll
    for (int o = 16; o > 0; o >>= 1) s += __shfl_down_sync(0xffffffffu, s, o);
    if (lane == 0) atomicAdd(&out[batch[a]], s);
}

// ==========================================================================================
extern "C" void kernel_launch(void* const* d_in, const int* in_sizes, int n_in,
                              void* d_out, int out_size)
{
    const int*   z        = (const int*)  d_in[0];
    const float* rbf      = (const float*)d_in[1];
    const float* sbf      = (const float*)d_in[2];
    const int*   ei       = (const int*)  d_in[3];
    const int*   ej       = (const int*)  d_in[4];
    const int*   idx_kj   = (const int*)  d_in[5];
    const int*   idx_ji   = (const int*)  d_in[6];
    const int*   batch    = (const int*)  d_in[7];
    const float* emb_table= (const float*)d_in[8];
    const float* emb_rbf_w= (const float*)d_in[9];
    const float* emb_rbf_b= (const float*)d_in[10];
    const float* emb_w    = (const float*)d_in[11];
    const float* emb_b    = (const float*)d_in[12];
    const float* int_rbf_w= (const float*)d_in[13];
    const float* int_sbf_w= (const float*)d_in[14];
    const float* int_kj_w = (const float*)d_in[15];
    const float* int_kj_b = (const float*)d_in[16];
    const float* int_ji_w = (const float*)d_in[17];
    const float* int_ji_b = (const float*)d_in[18];
    const float* int_W    = (const float*)d_in[19];
    const float* int_bef_w= (const float*)d_in[20];
    const float* int_bef_b= (const float*)d_in[21];
    const float* int_lin_w= (const float*)d_in[22];
    const float* int_lin_b= (const float*)d_in[23];
    const float* int_aft_w= (const float*)d_in[24];
    const float* int_aft_b= (const float*)d_in[25];
    const float* out_rbf_w= (const float*)d_in[26];
    const float* out_lins_w=(const float*)d_in[27];
    const float* out_lins_b=(const float*)d_in[28];
    const float* out_w    = (const float*)d_in[29];
    float* out = (float*)d_out;

    float *XSAVE, *XJI, *XKJ, *T1, *SBFP, *AEMB, *WT, *ATOM7, *ATOM7B, *WR;
    __nv_bfloat16* Gh;
    cudaGetSymbolAddress((void**)&XSAVE, g_XSAVE);
    cudaGetSymbolAddress((void**)&XJI,  g_XJI);
    cudaGetSymbolAddress((void**)&XKJ,  g_XKJ);
    cudaGetSymbolAddress((void**)&T1,   g_T1);
    cudaGetSymbolAddress((void**)&SBFP, g_SBFP);
    cudaGetSymbolAddress((void**)&AEMB, g_AEMB);
    cudaGetSymbolAddress((void**)&Gh,   g_Gh);
    cudaGetSymbolAddress((void**)&WT,   g_WT);
    cudaGetSymbolAddress((void**)&ATOM7, g_ATOM7);
    cudaGetSymbolAddress((void**)&ATOM7B,g_ATOM7B);
    cudaGetSymbolAddress((void**)&WR,   g_WR);

    const dim3 gE(1, (NEDGES + 127) / 128);
    const dim3 gEG(NB, (NEDGES + 127) / 128);
    const dim3 gA7(1, (NATOMS + 127) / 128, 7);

    const size_t EH = (size_t)NEDGES * HD;

    cudaMemsetAsync(out, 0, NGRAPHS * sizeof(float));
    cudaMemsetAsync(ATOM7, 0, (size_t)7 * NATOMS * HD * sizeof(float));

    // ---- pre-round all weight matrices to tf32 ----
    auto rc = [&](const float* src, float* dst, int n) {
        round_copy_k<<<(n + 255) / 256, 256>>>(src, dst, n);
    };
    rc(emb_w,      WR + WR_EMB, 3 * HD * HD);
    rc(int_ji_w,   WR + WR_JI,  NBLK * HD * HD);
    rc(int_kj_w,   WR + WR_KJ,  NBLK * HD * HD);
    rc(int_bef_w,  WR + WR_BEF, NBLK * 2 * HD * HD);
    rc(int_lin_w,  WR + WR_LIN, NBLK * HD * HD);
    rc(int_aft_w,  WR + WR_AFT, NBLK * 4 * HD * HD);
    rc(out_lins_w, WR + WR_OUT, 7 * 3 * HD * HD);

    // all sbf projections up front (read sbf once)
    sbfp_all_k<<<(NTRIP + 127) / 128, 128>>>(sbf, int_sbf_w, SBFP);

    // ---- embedding block -> XSAVE[0] ----
    embed_fill_k<<<NEDGES, HD>>>(z, ei, ej, rbf, emb_table, emb_rbf_w, emb_rbf_b, AEMB);
    gemm_tf32<<<gE, 256>>>(AEMB, WR + WR_EMB, emb_b, nullptr, nullptr, nullptr, XSAVE,
                           NEDGES, HD, 3 * HD, 1, 0, 1, 0, 0, 0, 0);

    for (int b = 0; b < NBLK; b++) {
        float* xa = XSAVE + (size_t)b * EH;
        float* xb = XSAVE + (size_t)(b + 1) * EH;

        gemm_tf32<<<gE, 256>>>(xa, WR + WR_JI + (size_t)b * HD * HD, int_ji_b + (size_t)b * HD,
                               nullptr, nullptr, nullptr, XJI,
                               NEDGES, HD, HD, 1, 0, 0, 0, 0, 0, 0);
        // kj with fused rbf projection multiply in epilogue
        gemm_tf32<<<gE, 256>>>(xa, WR + WR_KJ + (size_t)b * HD * HD, int_kj_b + (size_t)b * HD,
                               nullptr, rbf, int_rbf_w + (size_t)b * NR * HD, XKJ,
                               NEDGES, HD, HD, 1, 0, 1, 0, 0, 0, 0);

        wt_k<<<(HD * NB * HD) / 128, 128>>>(int_W + (size_t)b * HD * NB * HD, WT);
        gemm_tf32<<<gEG, 256>>>(XKJ, WT, nullptr, nullptr, nullptr, nullptr, Gh,
                                NEDGES, NB * HD, HD, 0, 1, 0, 0, 0, 0, 0);

        trip_k<<<(NTRIP + 7) / 8, 256>>>(Gh, SBFP + (size_t)b * NB, idx_kj, idx_ji, XJI);

        // residual before (1 layer)
        gemm_tf32<<<gE, 256>>>(XJI, WR + WR_BEF + ((size_t)b * 2 + 0) * HD * HD,
                               int_bef_b + ((size_t)b * 2 + 0) * HD, nullptr, nullptr, nullptr,
                               T1, NEDGES, HD, HD, 1, 0, 1, 0, 0, 0, 0);
        gemm_tf32<<<gE, 256>>>(T1, WR + WR_BEF + ((size_t)b * 2 + 1) * HD * HD,
                               int_bef_b + ((size_t)b * 2 + 1) * HD, XJI, nullptr, nullptr,
                               XJI, NEDGES, HD, HD, 1, 0, 1, 0, 0, 0, 0);

        // lin + skip -> xb
        gemm_tf32<<<gE, 256>>>(XJI, WR + WR_LIN + (size_t)b * HD * HD, int_lin_b + (size_t)b * HD,
                               xa, nullptr, nullptr, xb,
                               NEDGES, HD, HD, 1, 0, 1, 0, 0, 0, 0);

        // residual after (2 layers), in place on xb
        for (int r = 0; r < 2; r++) {
            gemm_tf32<<<gE, 256>>>(xb, WR + WR_AFT + ((size_t)b * 4 + 2 * r + 0) * HD * HD,
                                   int_aft_b + ((size_t)b * 4 + 2 * r + 0) * HD,
                                   nullptr, nullptr, nullptr,
                                   T1, NEDGES, HD, HD, 1, 0, 1, 0, 0, 0, 0);
            gemm_tf32<<<gE, 256>>>(T1, WR + WR_AFT + ((size_t)b * 4 + 2 * r + 1) * HD * HD,
                                   int_aft_b + ((size_t)b * 4 + 2 * r + 1) * HD,
                                   xb, nullptr, nullptr,
                                   xb, NEDGES, HD, HD, 1, 0, 1, 0, 0, 0, 0);
        }
    }

    // ---- all 7 out_blocks, batched at the end ----
    edge_scatter7_k<<<dim3(NEDGES, 7), HD>>>(rbf, out_rbf_w, XSAVE, ei, ATOM7);
    gemm_tf32<<<gA7, 256>>>(ATOM7, WR + WR_OUT + 0 * HD * HD, out_lins_b + 0 * HD,
                            nullptr, nullptr, nullptr, ATOM7B, NATOMS, HD, HD, 1, 0, 1,
                            (size_t)NATOMS * HD, (size_t)3 * HD * HD, (size_t)3 * HD,
                            (size_t)NATOMS * HD);
    gemm_tf32<<<gA7, 256>>>(ATOM7B, WR + WR_OUT + 1 * HD * HD, out_lins_b + 1 * HD,
                            nullptr, nullptr, nullptr, ATOM7, NATOMS, HD, HD, 1, 0, 1,
                            (size_t)NATOMS * HD, (size_t)3 * HD * HD, (size_t)3 * HD,
                            (size_t)NATOMS * HD);
    gemm_tf32<<<gA7, 256>>>(ATOM7, WR + WR_OUT + 2 * HD * HD, out_lins_b + 2 * HD,
                            nullptr, nullptr, nullptr, ATOM7B, NATOMS, HD, HD, 1, 0, 0,
                            (size_t)NATOMS * HD, (size_t)3 * HD * HD, (size_t)3 * HD,
                            (size_t)NATOMS * HD);
    dot7_k<<<dim3((NATOMS + 7) / 8, 7), 256>>>(ATOM7B, out_w, batch, out);
}

// round 9
// speedup vs baseline: 1.1800x; 1.1800x over previous
#include <cuda_runtime.h>
#include <cuda_fp16.h>
#include <cuda_bf16.h>
#include <math.h>

#define NATOMS 8000
#define NEDGES 100000
#define NTRIP  500000
#define NGRAPHS 64
#define HD 128
#define NR 6
#define NSNR 42
#define NB 8
#define NBLK 6

// ---------------- device scratch (no allocation allowed) ----------------
__device__ float g_XSAVE[(size_t)(NBLK + 1) * NEDGES * HD];   // x snapshot per block
__device__ float g_XJI [NEDGES*HD];
__device__ float g_XKJ [NEDGES*HD];
__device__ float g_T1  [NEDGES*HD];
__device__ float g_SBFP[(size_t)NTRIP*NBLK*NB];
__device__ float g_AEMB[(size_t)NEDGES*3*HD];                  // embed input [E,384]
__device__ __nv_bfloat16 g_Gh[(size_t)NEDGES*NB*HD];           // G in bf16
__device__ float g_ATOM7 [(size_t)7*NATOMS*HD];
__device__ float g_ATOM7B[(size_t)7*NATOMS*HD];

// half weight copies, transposed to [N][K]
#define WH_EMB  0
#define WH_JI   (WH_EMB + 3*HD*HD)
#define WH_KJ   (WH_JI  + NBLK*HD*HD)
#define WH_BEF  (WH_KJ  + NBLK*HD*HD)
#define WH_LIN  (WH_BEF + NBLK*2*HD*HD)
#define WH_AFT  (WH_LIN + NBLK*HD*HD)
#define WH_OUT  (WH_AFT + NBLK*4*HD*HD)
#define WH_G    (WH_OUT + 7*3*HD*HD)
#define WH_TOTAL (WH_G + NBLK*NB*HD*HD)
__device__ __half g_WH[WH_TOTAL];

__device__ __forceinline__ float silu(float x) { return x / (1.0f + expf(-x)); }

__device__ __forceinline__ unsigned packh2(float a, float b) {
    __half2 h = __floats2half2_rn(a, b);
    return *reinterpret_cast<unsigned*>(&h);
}

__device__ __forceinline__ void mma_f16(float* c, const unsigned* a, const unsigned* b) {
    asm volatile(
        "mma.sync.aligned.m16n8k16.row.col.f32.f16.f16.f32 "
        "{%0,%1,%2,%3}, {%4,%5,%6,%7}, {%8,%9}, {%0,%1,%2,%3};"
        : "+f"(c[0]), "+f"(c[1]), "+f"(c[2]), "+f"(c[3])
        : "r"(a[0]), "r"(a[1]), "r"(a[2]), "r"(a[3]),
          "r"(b[0]), "r"(b[1]));
}

// ---------------- weight convert: dst[m][n][k] = half(src[m][k][n]) ----------------
__global__ void convw_k(const float* __restrict__ src, __half* __restrict__ dst,
                        int K, int N, long total)
{
    long idx = (long)blockIdx.x * blockDim.x + threadIdx.x;
    if (idx >= total) return;
    long per = (long)K * N;
    long m = idx / per, r = idx % per;
    int n = (int)(r / K), k = (int)(r % K);
    dst[idx] = __float2half(src[m * per + (size_t)k * N + n]);
}

// ---------------- G weight convert: dst[b][j*128+i][l] = half(W[b][i][j][l]) -------
__global__ void convg_k(const float* __restrict__ W, __half* __restrict__ dst)
{
    int idx = blockIdx.x * blockDim.x + threadIdx.x;     // 6*131072
    int b = idx >> 17;
    int r = idx & 131071;
    int n = r >> 7, l = r & 127;
    int j = n >> 7, i = n & 127;
    dst[idx] = __float2half(W[(size_t)b * 131072 + (size_t)i * 1024 + j * 128 + l]);
}

// ---------------- fp16 tensor-core GEMM: C = epi(A[M,K] @ Bh^T + bias) ----------------
// Bh: [N][K] half (row n contiguous in k). K multiple of 64. N multiple of 128.
// epi: (optional silu) -> (optional * (rbf@rbfw)) -> (optional +addv); optional bf16 out.
// Static smem, K-chunks of 64.
#define AST 72   // halfs per smem row
__global__ __launch_bounds__(256, 2) void gemm_h(
    const float* __restrict__ A, const __half* __restrict__ Bh,
    const float* __restrict__ bias, const float* __restrict__ addv,
    const float* __restrict__ rbfv, const float* __restrict__ rbfw,
    void* __restrict__ Cv,
    int M, int N, int K, int act, int outBf16,
    size_t aZ, size_t bZ, size_t biasZ, size_t cZ)
{
    __shared__ __half As[128][AST];
    __shared__ __half Bs[128][AST];

    A  += blockIdx.z * aZ;
    Bh += blockIdx.z * bZ;
    if (bias) bias += blockIdx.z * biasZ;

    const int tid = threadIdx.x;
    const int bM = blockIdx.y * 128;
    const int bN = blockIdx.x * 128;
    const int lane = tid & 31, warp = tid >> 5;
    const int gid = lane >> 2, tig = lane & 3;
    const int wm = warp >> 2, wn = warp & 3;     // 2 x 4 warps; warp tile 64x32

    float c[4][4][4];
#pragma unroll
    for (int i = 0; i < 4; i++)
#pragma unroll
        for (int j = 0; j < 4; j++)
#pragma unroll
            for (int q = 0; q < 4; q++) c[i][j][q] = 0.f;

    for (int kc = 0; kc < K; kc += 64) {
        if (kc) __syncthreads();

        // B: 128 rows x 64 halfs, plain uint4 copy (1024 chunks of 8 halfs)
#pragma unroll
        for (int it = 0; it < 4; it++) {
            int f = it * 256 + tid;                 // 0..1023
            int row = f >> 3, c8 = (f & 7) * 8;     // 8 chunks of 8 halfs per row
            *(uint4*)&Bs[row][c8] =
                *(const uint4*)(Bh + (size_t)(bN + row) * K + kc + c8);
        }
        // A: 128 rows x 64 floats, LDG + cvt + STS (2048 chunks of 4 floats)
#pragma unroll
        for (int it = 0; it < 8; it++) {
            int f = it * 256 + tid;                 // 0..2047
            int row = f >> 4, c4 = (f & 15) * 4;
            float4 v = make_float4(0.f, 0.f, 0.f, 0.f);
            if (bM + row < M)
                v = *(const float4*)(A + (size_t)(bM + row) * K + kc + c4);
            *(uint2*)&As[row][c4] = make_uint2(packh2(v.x, v.y), packh2(v.z, v.w));
        }
        __syncthreads();

#pragma unroll
        for (int kk = 0; kk < 64; kk += 16) {
            unsigned af[4][4], bf[4][2];
#pragma unroll
            for (int fm = 0; fm < 4; fm++) {
                int m0 = wm * 64 + fm * 16 + gid;
                af[fm][0] = *(const unsigned*)&As[m0    ][kk + 2 * tig];
                af[fm][1] = *(const unsigned*)&As[m0 + 8][kk + 2 * tig];
                af[fm][2] = *(const unsigned*)&As[m0    ][kk + 2 * tig + 8];
                af[fm][3] = *(const unsigned*)&As[m0 + 8][kk + 2 * tig + 8];
            }
#pragma unroll
            for (int fn = 0; fn < 4; fn++) {
                int n0 = wn * 32 + fn * 8 + gid;
                bf[fn][0] = *(const unsigned*)&Bs[n0][kk + 2 * tig];
                bf[fn][1] = *(const unsigned*)&Bs[n0][kk + 2 * tig + 8];
            }
#pragma unroll
            for (int fm = 0; fm < 4; fm++)
#pragma unroll
                for (int fn = 0; fn < 4; fn++)
                    mma_f16(c[fm][fn], af[fm], bf[fn]);
        }
    }

    // epilogue
    float* Cf = (float*)Cv + blockIdx.z * cZ;
    __nv_bfloat16* Ch = (__nv_bfloat16*)Cv + blockIdx.z * cZ;

#pragma unroll
    for (int fm = 0; fm < 4; fm++) {
#pragma unroll
        for (int half_ = 0; half_ < 2; half_++) {
            int row = bM + wm * 64 + fm * 16 + gid + half_ * 8;
            if (row >= M) continue;
            float rr[NR];
            if (rbfv) {
#pragma unroll
                for (int r = 0; r < NR; r++) rr[r] = rbfv[(size_t)row * NR + r];
            }
#pragma unroll
            for (int fn = 0; fn < 4; fn++) {
                int col = bN + wn * 32 + fn * 8 + tig * 2;
                float v0 = c[fm][fn][half_ * 2 + 0] + (bias ? bias[col] : 0.f);
                float v1 = c[fm][fn][half_ * 2 + 1] + (bias ? bias[col + 1] : 0.f);
                if (act) { v0 = silu(v0); v1 = silu(v1); }
                size_t base = (size_t)row * N + col;
                if (rbfv) {
                    float rp0 = 0.f, rp1 = 0.f;
#pragma unroll
                    for (int r = 0; r < NR; r++) {
                        rp0 += rr[r] * rbfw[r * HD + col];
                        rp1 += rr[r] * rbfw[r * HD + col + 1];
                    }
                    v0 *= rp0; v1 *= rp1;
                }
                if (addv) {
                    float2 av = *(const float2*)(addv + base);
                    v0 += av.x; v1 += av.y;
                }
                if (outBf16) {
                    *(__nv_bfloat162*)(Ch + base) =
                        __float22bfloat162_rn(make_float2(v0, v1));
                } else {
                    *(float2*)(Cf + base) = make_float2(v0, v1);
                }
            }
        }
    }
}

// ---------------- embedding: build A_emb[E,384] = [h_i | h_j | silu(rbf@W+b)] --------
__global__ void embed_fill_k(const int* __restrict__ z, const int* __restrict__ ei,
                             const int* __restrict__ ej, const float* __restrict__ rbf,
                             const float* __restrict__ emb_table,
                             const float* __restrict__ erw, const float* __restrict__ erb,
                             float* __restrict__ Aemb)
{
    int e = blockIdx.x, h = threadIdx.x;
    int zi = z[ei[e]], zj = z[ej[e]];
    float s = erb[h];
    const float* rr = rbf + (size_t)e * NR;
#pragma unroll
    for (int r = 0; r < NR; r++) s += rr[r] * erw[r * HD + h];
    size_t base = (size_t)e * (3 * HD);
    Aemb[base + h]           = emb_table[(size_t)zi * HD + h];
    Aemb[base + HD + h]      = emb_table[(size_t)zj * HD + h];
    Aemb[base + 2 * HD + h]  = silu(s);
}

// ---------------- sbf projection, ALL blocks: SBFP[t, b*8+j] ----------------
__global__ void sbfp_all_k(const float* __restrict__ sbf, const float* __restrict__ w,
                           float* __restrict__ outp)
{
    __shared__ float ws[NBLK * NSNR * NB];   // 2016 floats
    for (int idx = threadIdx.x; idx < NBLK * NSNR * NB; idx += blockDim.x) ws[idx] = w[idx];
    __syncthreads();
    int t = blockIdx.x * blockDim.x + threadIdx.x;
    if (t >= NTRIP) return;
    float sr[NSNR];
    const float* s = sbf + (size_t)t * NSNR;
#pragma unroll
    for (int r = 0; r < NSNR; r++) sr[r] = s[r];
    float* op = outp + (size_t)t * (NBLK * NB);
#pragma unroll
    for (int b = 0; b < NBLK; b++) {
        float acc[NB];
#pragma unroll
        for (int j = 0; j < NB; j++) acc[j] = 0.f;
        for (int r = 0; r < NSNR; r++) {
            float sv = sr[r];
#pragma unroll
            for (int j = 0; j < NB; j++) acc[j] += sv * ws[b * NSNR * NB + r * NB + j];
        }
#pragma unroll
        for (int j = 0; j < NB; j++) op[b * NB + j] = acc[j];
    }
}

// ---------------- triplet scatter: M[idx_ji[w],:] += sum_j sbf_p[w,j] * Gh[idx_kj[w], j, :] --
__global__ __launch_bounds__(256) void trip_k(
    const __nv_bfloat16* __restrict__ Gh, const float* __restrict__ sbfp,
    const int* __restrict__ idx_kj, const int* __restrict__ idx_ji,
    float* __restrict__ Mo)
{
    int w = blockIdx.x * (blockDim.x >> 5) + (threadIdx.x >> 5);
    if (w >= NTRIP) return;
    int lane = threadIdx.x & 31;
    int kj = idx_kj[w], ji = idx_ji[w];
    float sv = (lane < NB) ? sbfp[(size_t)w * (NBLK * NB) + lane] : 0.f;
    const __nv_bfloat16* gr = Gh + (size_t)kj * (NB * HD) + lane * 4;
    float4 acc = make_float4(0.f, 0.f, 0.f, 0.f);
#pragma unroll
    for (int j = 0; j < NB; j++) {
        float s = __shfl_sync(0xffffffffu, sv, j);
        uint2 u = *(const uint2*)(gr + j * HD);
        __nv_bfloat162 p0 = *reinterpret_cast<__nv_bfloat162*>(&u.x);
        __nv_bfloat162 p1 = *reinterpret_cast<__nv_bfloat162*>(&u.y);
        float2 f0 = __bfloat1622float2(p0);
        float2 f1 = __bfloat1622float2(p1);
        acc.x += s * f0.x; acc.y += s * f0.y; acc.z += s * f1.x; acc.w += s * f1.y;
    }
    float* mo = Mo + (size_t)ji * HD + lane * 4;
    atomicAdd(mo + 0, acc.x);
    atomicAdd(mo + 1, acc.y);
    atomicAdd(mo + 2, acc.z);
    atomicAdd(mo + 3, acc.w);
}

// ---------------- batched out-block edge scatter over k=0..6 -----------------
__global__ void edge_scatter7_k(const float* __restrict__ rbf, const float* __restrict__ orw,
                                const float* __restrict__ xsave, const int* __restrict__ ei,
                                float* __restrict__ atom)
{
    int e = blockIdx.x, k = blockIdx.y, h = threadIdx.x;
    const float* rr = rbf + (size_t)e * NR;
    const float* w = orw + (size_t)k * NR * HD;
    float rp = 0.f;
#pragma unroll
    for (int r = 0; r < NR; r++) rp += rr[r] * w[r * HD + h];
    float v = rp * xsave[(size_t)k * NEDGES * HD + (size_t)e * HD + h];
    atomicAdd(&atom[(size_t)k * NATOMS * HD + (size_t)ei[e] * HD + h], v);
}

// ---------------- batched final per-atom dot + graph segment sum ----------------
__global__ void dot7_k(const float* __restrict__ atom2, const float* __restrict__ ow,
                       const int* __restrict__ batch, float* __restrict__ out)
{
    int a = blockIdx.x * (blockDim.x >> 5) + (threadIdx.x >> 5);
    if (a >= NATOMS) return;
    int k = blockIdx.y;
    int lane = threadIdx.x & 31;
    const float* ar = atom2 + (size_t)k * NATOMS * HD + (size_t)a * HD + lane * 4;
    const float* wr = ow + (size_t)k * HD + lane * 4;
    float s = ar[0] * wr[0] + ar[1] * wr[1] + ar[2] * wr[2] + ar[3] * wr[3];
#pragma unroll
    for (int o = 16; o > 0; o >>= 1) s += __shfl_down_sync(0xffffffffu, s, o);
    if (lane == 0) atomicAdd(&out[batch[a]], s);
}

// ==========================================================================================
extern "C" void kernel_launch(void* const* d_in, const int* in_sizes, int n_in,
                              void* d_out, int out_size)
{
    const int*   z        = (const int*)  d_in[0];
    const float* rbf      = (const float*)d_in[1];
    const float* sbf      = (const float*)d_in[2];
    const int*   ei       = (const int*)  d_in[3];
    const int*   ej       = (const int*)  d_in[4];
    const int*   idx_kj   = (const int*)  d_in[5];
    const int*   idx_ji   = (const int*)  d_in[6];
    const int*   batch    = (const int*)  d_in[7];
    const float* emb_table= (const float*)d_in[8];
    const float* emb_rbf_w= (const float*)d_in[9];
    const float* emb_rbf_b= (const float*)d_in[10];
    const float* emb_w    = (const float*)d_in[11];
    const float* emb_b    = (const float*)d_in[12];
    const float* int_rbf_w= (const float*)d_in[13];
    const float* int_sbf_w= (const float*)d_in[14];
    const float* int_kj_w = (const float*)d_in[15];
    const float* int_kj_b = (const float*)d_in[16];
    const float* int_ji_w = (const float*)d_in[17];
    const float* int_ji_b = (const float*)d_in[18];
    const float* int_W    = (const float*)d_in[19];
    const float* int_bef_w= (const float*)d_in[20];
    const float* int_bef_b= (const float*)d_in[21];
    const float* int_lin_w= (const float*)d_in[22];
    const float* int_lin_b= (const float*)d_in[23];
    const float* int_aft_w= (const float*)d_in[24];
    const float* int_aft_b= (const float*)d_in[25];
    const float* out_rbf_w= (const float*)d_in[26];
    const float* out_lins_w=(const float*)d_in[27];
    const float* out_lins_b=(const float*)d_in[28];
    const float* out_w    = (const float*)d_in[29];
    float* out = (float*)d_out;

    float *XSAVE, *XJI, *XKJ, *T1, *SBFP, *AEMB, *ATOM7, *ATOM7B;
    __nv_bfloat16* Gh;
    __half* WH;
    cudaGetSymbolAddress((void**)&XSAVE, g_XSAVE);
    cudaGetSymbolAddress((void**)&XJI,  g_XJI);
    cudaGetSymbolAddress((void**)&XKJ,  g_XKJ);
    cudaGetSymbolAddress((void**)&T1,   g_T1);
    cudaGetSymbolAddress((void**)&SBFP, g_SBFP);
    cudaGetSymbolAddress((void**)&AEMB, g_AEMB);
    cudaGetSymbolAddress((void**)&Gh,   g_Gh);
    cudaGetSymbolAddress((void**)&ATOM7, g_ATOM7);
    cudaGetSymbolAddress((void**)&ATOM7B,g_ATOM7B);
    cudaGetSymbolAddress((void**)&WH,   g_WH);

    const dim3 gE(1, (NEDGES + 127) / 128);
    const dim3 gEG(NB, (NEDGES + 127) / 128);
    const dim3 gA7(1, (NATOMS + 127) / 128, 7);
    const size_t EH = (size_t)NEDGES * HD;

    cudaMemsetAsync(out, 0, NGRAPHS * sizeof(float));
    cudaMemsetAsync(ATOM7, 0, (size_t)7 * NATOMS * HD * sizeof(float));

    // ---- convert all weights to half [N][K] ----
    auto cw = [&](const float* src, __half* dst, int K, int N, int cnt) {
        long total = (long)cnt * K * N;
        convw_k<<<(unsigned)((total + 255) / 256), 256>>>(src, dst, K, N, total);
    };
    cw(emb_w,      WH + WH_EMB, 3 * HD, HD, 1);
    cw(int_ji_w,   WH + WH_JI,  HD, HD, NBLK);
    cw(int_kj_w,   WH + WH_KJ,  HD, HD, NBLK);
    cw(int_bef_w,  WH + WH_BEF, HD, HD, NBLK * 2);
    cw(int_lin_w,  WH + WH_LIN, HD, HD, NBLK);
    cw(int_aft_w,  WH + WH_AFT, HD, HD, NBLK * 4);
    cw(out_lins_w, WH + WH_OUT, HD, HD, 7 * 3);
    convg_k<<<(NBLK * NB * HD * HD) / 256, 256>>>(int_W, WH + WH_G);

    // all sbf projections up front (read sbf once)
    sbfp_all_k<<<(NTRIP + 127) / 128, 128>>>(sbf, int_sbf_w, SBFP);

    // ---- embedding block -> XSAVE[0] ----
    embed_fill_k<<<NEDGES, HD>>>(z, ei, ej, rbf, emb_table, emb_rbf_w, emb_rbf_b, AEMB);
    gemm_h<<<gE, 256>>>(AEMB, WH + WH_EMB, emb_b, nullptr, nullptr, nullptr, XSAVE,
                        NEDGES, HD, 3 * HD, 1, 0, 0, 0, 0, 0);

    for (int b = 0; b < NBLK; b++) {
        float* xa = XSAVE + (size_t)b * EH;
        float* xb = XSAVE + (size_t)(b + 1) * EH;

        gemm_h<<<gE, 256>>>(xa, WH + WH_JI + (size_t)b * HD * HD,
                            int_ji_b + (size_t)b * HD,
                            nullptr, nullptr, nullptr, XJI,
                            NEDGES, HD, HD, 1, 0, 0, 0, 0, 0);
        // kj with fused rbf projection multiply in epilogue
        gemm_h<<<gE, 256>>>(xa, WH + WH_KJ + (size_t)b * HD * HD,
                            int_kj_b + (size_t)b * HD,
                            nullptr, rbf, int_rbf_w + (size_t)b * NR * HD, XKJ,
                            NEDGES, HD, HD, 1, 0, 0, 0, 0, 0);

        gemm_h<<<gEG, 256>>>(XKJ, WH + WH_G + (size_t)b * NB * HD * HD,
                             nullptr, nullptr, nullptr, nullptr, Gh,
                             NEDGES, NB * HD, HD, 0, 1, 0, 0, 0, 0);

        trip_k<<<(NTRIP + 7) / 8, 256>>>(Gh, SBFP + (size_t)b * NB, idx_kj, idx_ji, XJI);

        // residual before (1 layer)
        gemm_h<<<gE, 256>>>(XJI, WH + WH_BEF + ((size_t)b * 2 + 0) * HD * HD,
                            int_bef_b + ((size_t)b * 2 + 0) * HD,
                            nullptr, nullptr, nullptr,
                            T1, NEDGES, HD, HD, 1, 0, 0, 0, 0, 0);
        gemm_h<<<gE, 256>>>(T1, WH + WH_BEF + ((size_t)b * 2 + 1) * HD * HD,
                            int_bef_b + ((size_t)b * 2 + 1) * HD,
                            XJI, nullptr, nullptr,
                            XJI, NEDGES, HD, HD, 1, 0, 0, 0, 0, 0);

        // lin + skip -> xb
        gemm_h<<<gE, 256>>>(XJI, WH + WH_LIN + (size_t)b * HD * HD,
                            int_lin_b + (size_t)b * HD,
                            xa, nullptr, nullptr, xb,
                            NEDGES, HD, HD, 1, 0, 0, 0, 0, 0);

        // residual after (2 layers), in place on xb
        for (int r = 0; r < 2; r++) {
            gemm_h<<<gE, 256>>>(xb, WH + WH_AFT + ((size_t)b * 4 + 2 * r + 0) * HD * HD,
                                int_aft_b + ((size_t)b * 4 + 2 * r + 0) * HD,
                                nullptr, nullptr, nullptr,
                                T1, NEDGES, HD, HD, 1, 0, 0, 0, 0, 0);
            gemm_h<<<gE, 256>>>(T1, WH + WH_AFT + ((size_t)b * 4 + 2 * r + 1) * HD * HD,
                                int_aft_b + ((size_t)b * 4 + 2 * r + 1) * HD,
                                xb, nullptr, nullptr,
                                xb, NEDGES, HD, HD, 1, 0, 0, 0, 0, 0);
        }
    }

    // ---- all 7 out_blocks, batched at the end ----
    edge_scatter7_k<<<dim3(NEDGES, 7), HD>>>(rbf, out_rbf_w, XSAVE, ei, ATOM7);
    gemm_h<<<gA7, 256>>>(ATOM7, WH + WH_OUT + 0 * HD * HD, out_lins_b + 0 * HD,
                         nullptr, nullptr, nullptr, ATOM7B, NATOMS, HD, HD, 1, 0,
                         (size_t)NATOMS * HD, (size_t)3 * HD * HD, (size_t)3 * HD,
                         (size_t)NATOMS * HD);
    gemm_h<<<gA7, 256>>>(ATOM7B, WH + WH_OUT + 1 * HD * HD, out_lins_b + 1 * HD,
                         nullptr, nullptr, nullptr, ATOM7, NATOMS, HD, HD, 1, 0,
                         (size_t)NATOMS * HD, (size_t)3 * HD * HD, (size_t)3 * HD,
                         (size_t)NATOMS * HD);
    gemm_h<<<gA7, 256>>>(ATOM7, WH + WH_OUT + 2 * HD * HD, out_lins_b + 2 * HD,
                         nullptr, nullptr, nullptr, ATOM7B, NATOMS, HD, HD, 1, 0,
                         (size_t)NATOMS * HD, (size_t)3 * HD * HD, (size_t)3 * HD,
                         (size_t)NATOMS * HD);
    dot7_k<<<dim3((NATOMS + 7) / 8, 7), 256>>>(ATOM7B, out_w, batch, out);
}

// round 10
// speedup vs baseline: 1.2288x; 1.0413x over previous
#include <cuda_runtime.h>
#include <cuda_fp16.h>
#include <cuda_bf16.h>
#include <math.h>

#define NATOMS 8000
#define NEDGES 100000
#define NTRIP  500000
#define NGRAPHS 64
#define HD 128
#define NR 6
#define NSNR 42
#define NB 8
#define NBLK 6

// ---------------- device scratch (no allocation allowed) ----------------
__device__ float  g_XSAVE[(size_t)(NBLK + 1) * NEDGES * HD];   // f32 x per block
__device__ __half g_XSH  [(size_t)(NBLK + 1) * NEDGES * HD];   // half mirror of x
__device__ float  g_XJI [NEDGES*HD];                           // f32 (atomic target)
__device__ __half g_XJIh[NEDGES*HD];
__device__ __half g_XKJh[NEDGES*HD];
__device__ __half g_T1h [NEDGES*HD];
__device__ float  g_SBFP[(size_t)NTRIP*NBLK*NB];
__device__ __half g_AEMBh[(size_t)NEDGES*3*HD];                // embed input [E,384] half
__device__ __nv_bfloat16 g_Gh[(size_t)NEDGES*NB*HD];           // G in bf16
__device__ float  g_ATOM7 [(size_t)7*NATOMS*HD];
__device__ float  g_ATOM7B[(size_t)7*NATOMS*HD];
__device__ __half g_ATOMH [(size_t)7*NATOMS*HD];
__device__ __half g_ATOMH2[(size_t)7*NATOMS*HD];

// half weight copies, transposed to [N][K]
#define WH_EMB  0
#define WH_JI   (WH_EMB + 3*HD*HD)
#define WH_KJ   (WH_JI  + NBLK*HD*HD)
#define WH_BEF  (WH_KJ  + NBLK*HD*HD)
#define WH_LIN  (WH_BEF + NBLK*2*HD*HD)
#define WH_AFT  (WH_LIN + NBLK*HD*HD)
#define WH_OUT  (WH_AFT + NBLK*4*HD*HD)
#define WH_G    (WH_OUT + 7*3*HD*HD)
#define WH_TOTAL (WH_G + NBLK*NB*HD*HD)
__device__ __half g_WH[WH_TOTAL];

__device__ __forceinline__ float silu(float x) { return x / (1.0f + expf(-x)); }

__device__ __forceinline__ unsigned packh2(float a, float b) {
    __half2 h = __floats2half2_rn(a, b);
    return *reinterpret_cast<unsigned*>(&h);
}

__device__ __forceinline__ void mma_f16(float* c, const unsigned* a, const unsigned* b) {
    asm volatile(
        "mma.sync.aligned.m16n8k16.row.col.f32.f16.f16.f32 "
        "{%0,%1,%2,%3}, {%4,%5,%6,%7}, {%8,%9}, {%0,%1,%2,%3};"
        : "+f"(c[0]), "+f"(c[1]), "+f"(c[2]), "+f"(c[3])
        : "r"(a[0]), "r"(a[1]), "r"(a[2]), "r"(a[3]),
          "r"(b[0]), "r"(b[1]));
}

__device__ __forceinline__ void cp16(unsigned saddr, const void* g, int bytes) {
    asm volatile("cp.async.cg.shared.global [%0], [%1], 16, %2;"
                 :: "r"(saddr), "l"(g), "r"(bytes) : "memory");
}

__device__ __forceinline__ void ldsm4(unsigned& r0, unsigned& r1, unsigned& r2, unsigned& r3,
                                      const __half* p) {
    unsigned addr = (unsigned)__cvta_generic_to_shared(p);
    asm volatile("ldmatrix.sync.aligned.m8n8.x4.shared.b16 {%0,%1,%2,%3}, [%4];"
                 : "=r"(r0), "=r"(r1), "=r"(r2), "=r"(r3) : "r"(addr));
}

// ---------------- weight convert: dst[m][n][k] = half(src[m][k][n]) ----------------
__global__ void convw_k(const float* __restrict__ src, __half* __restrict__ dst,
                        int K, int N, long total)
{
    long idx = (long)blockIdx.x * blockDim.x + threadIdx.x;
    if (idx >= total) return;
    long per = (long)K * N;
    long m = idx / per, r = idx % per;
    int n = (int)(r / K), k = (int)(r % K);
    dst[idx] = __float2half(src[m * per + (size_t)k * N + n]);
}

// ---------------- G weight convert: dst[b][j*128+i][l] = half(W[b][i][j][l]) -------
__global__ void convg_k(const float* __restrict__ W, __half* __restrict__ dst)
{
    int idx = blockIdx.x * blockDim.x + threadIdx.x;     // 6*131072
    int b = idx >> 17;
    int r = idx & 131071;
    int n = r >> 7, l = r & 127;
    int j = n >> 7, i = n & 127;
    dst[idx] = __float2half(W[(size_t)b * 131072 + (size_t)i * 1024 + j * 128 + l]);
}

// ---------------- fp16 tensor-core GEMM: epi(A[M,K] @ Bh^T + bias) -> {f32, half, bf16} ----
// A either f32 or half per aHalf. Bh: [N][K] half. K multiple of 64, N multiple of 128.
// epi: (silu?) -> (* (rbf@rbfw))? -> (+addv)?; outputs written to every non-null C.
#define AST 72   // halfs per smem row
__global__ __launch_bounds__(256, 2) void gemm_h(
    const void* __restrict__ Av, int aHalf, const __half* __restrict__ Bh,
    const float* __restrict__ bias, const float* __restrict__ addv,
    const float* __restrict__ rbfv, const float* __restrict__ rbfw,
    float* __restrict__ Cf, __half* __restrict__ Chh, __nv_bfloat16* __restrict__ Cbf,
    int M, int N, int K, int act,
    size_t aZ, size_t bZ, size_t biasZ, size_t cZ)
{
    __shared__ __half As[128][AST];
    __shared__ __half Bs[128][AST];

    const float* Af = (const float*)Av + blockIdx.z * aZ;
    const __half* Ah = (const __half*)Av + blockIdx.z * aZ;
    Bh += blockIdx.z * bZ;
    if (bias) bias += blockIdx.z * biasZ;

    const int tid = threadIdx.x;
    const int bM = blockIdx.y * 128;
    const int bN = blockIdx.x * 128;
    const int lane = tid & 31, warp = tid >> 5;
    const int gid = lane >> 2, tig = lane & 3;
    const int wm = warp >> 2, wn = warp & 3;     // 2 x 4 warps; warp tile 64x32

    // ldmatrix lane offsets
    const int aRowO = (lane & 7) + ((lane >> 3) & 1) * 8;
    const int aColO = ((lane >> 4) & 1) * 8;
    const int bRowO = (lane & 7) + ((lane >> 4) & 1) * 8;
    const int bColO = ((lane >> 3) & 1) * 8;

    float c[4][4][4];
#pragma unroll
    for (int i = 0; i < 4; i++)
#pragma unroll
        for (int j = 0; j < 4; j++)
#pragma unroll
            for (int q = 0; q < 4; q++) c[i][j][q] = 0.f;

    unsigned sA = (unsigned)__cvta_generic_to_shared(&As[0][0]);
    unsigned sB = (unsigned)__cvta_generic_to_shared(&Bs[0][0]);

    for (int kc = 0; kc < K; kc += 64) {
        if (kc) __syncthreads();

        // B: 128 rows x 64 halfs = 128B/row = 8x16B chunks -> 1024 cp.async
#pragma unroll
        for (int it = 0; it < 4; it++) {
            int f = it * 256 + tid;
            int row = f >> 3, c8 = (f & 7) * 8;
            cp16(sB + (row * AST + c8) * 2,
                 Bh + (size_t)(bN + row) * K + kc + c8, 16);
        }
        if (aHalf) {
#pragma unroll
            for (int it = 0; it < 4; it++) {
                int f = it * 256 + tid;
                int row = f >> 3, c8 = (f & 7) * 8;
                cp16(sA + (row * AST + c8) * 2,
                     Ah + (size_t)(bM + row) * K + kc + c8,
                     (bM + row) < M ? 16 : 0);
            }
        } else {
#pragma unroll
            for (int it = 0; it < 8; it++) {
                int f = it * 256 + tid;
                int row = f >> 4, c4 = (f & 15) * 4;
                float4 v = make_float4(0.f, 0.f, 0.f, 0.f);
                if (bM + row < M)
                    v = *(const float4*)(Af + (size_t)(bM + row) * K + kc + c4);
                *(uint2*)&As[row][c4] = make_uint2(packh2(v.x, v.y), packh2(v.z, v.w));
            }
        }
        asm volatile("cp.async.commit_group;" ::: "memory");
        asm volatile("cp.async.wait_group 0;" ::: "memory");
        __syncthreads();

#pragma unroll
        for (int kk = 0; kk < 64; kk += 16) {
            unsigned af[4][4], bf[4][2];
#pragma unroll
            for (int fm = 0; fm < 4; fm++) {
                int m0 = wm * 64 + fm * 16;
                ldsm4(af[fm][0], af[fm][1], af[fm][2], af[fm][3],
                      &As[m0 + aRowO][kk + aColO]);
            }
#pragma unroll
            for (int p = 0; p < 2; p++) {
                int n0 = wn * 32 + p * 16;
                ldsm4(bf[2 * p][0], bf[2 * p][1], bf[2 * p + 1][0], bf[2 * p + 1][1],
                      &Bs[n0 + bRowO][kk + bColO]);
            }
#pragma unroll
            for (int fm = 0; fm < 4; fm++)
#pragma unroll
                for (int fn = 0; fn < 4; fn++)
                    mma_f16(c[fm][fn], af[fm], bf[fn]);
        }
    }

    // epilogue
    if (Cf)  Cf  += blockIdx.z * cZ;
    if (Chh) Chh += blockIdx.z * cZ;

#pragma unroll
    for (int fm = 0; fm < 4; fm++) {
#pragma unroll
        for (int half_ = 0; half_ < 2; half_++) {
            int row = bM + wm * 64 + fm * 16 + gid + half_ * 8;
            if (row >= M) continue;
            float rr[NR];
            if (rbfv) {
#pragma unroll
                for (int r = 0; r < NR; r++) rr[r] = rbfv[(size_t)row * NR + r];
            }
#pragma unroll
            for (int fn = 0; fn < 4; fn++) {
                int col = bN + wn * 32 + fn * 8 + tig * 2;
                float v0 = c[fm][fn][half_ * 2 + 0] + (bias ? bias[col] : 0.f);
                float v1 = c[fm][fn][half_ * 2 + 1] + (bias ? bias[col + 1] : 0.f);
                if (act) { v0 = silu(v0); v1 = silu(v1); }
                size_t base = (size_t)row * N + col;
                if (rbfv) {
                    float rp0 = 0.f, rp1 = 0.f;
#pragma unroll
                    for (int r = 0; r < NR; r++) {
                        rp0 += rr[r] * rbfw[r * HD + col];
                        rp1 += rr[r] * rbfw[r * HD + col + 1];
                    }
                    v0 *= rp0; v1 *= rp1;
                }
                if (addv) {
                    float2 av = *(const float2*)(addv + base);
                    v0 += av.x; v1 += av.y;
                }
                if (Cf)  *(float2*)(Cf + base) = make_float2(v0, v1);
                if (Chh) *(unsigned*)(Chh + base) = packh2(v0, v1);
                if (Cbf) *(__nv_bfloat162*)(Cbf + base) =
                             __float22bfloat162_rn(make_float2(v0, v1));
            }
        }
    }
}

// ---------------- embedding: build A_emb[E,384] = [h_i | h_j | silu(rbf@W+b)] half ----
__global__ void embed_fill_k(const int* __restrict__ z, const int* __restrict__ ei,
                             const int* __restrict__ ej, const float* __restrict__ rbf,
                             const float* __restrict__ emb_table,
                             const float* __restrict__ erw, const float* __restrict__ erb,
                             __half* __restrict__ Aemb)
{
    int e = blockIdx.x, h = threadIdx.x;
    int zi = z[ei[e]], zj = z[ej[e]];
    float s = erb[h];
    const float* rr = rbf + (size_t)e * NR;
#pragma unroll
    for (int r = 0; r < NR; r++) s += rr[r] * erw[r * HD + h];
    size_t base = (size_t)e * (3 * HD);
    Aemb[base + h]           = __float2half(emb_table[(size_t)zi * HD + h]);
    Aemb[base + HD + h]      = __float2half(emb_table[(size_t)zj * HD + h]);
    Aemb[base + 2 * HD + h]  = __float2half(silu(s));
}

// ---------------- sbf projection, ALL blocks: SBFP[t, b*8+j] ----------------
__global__ void sbfp_all_k(const float* __restrict__ sbf, const float* __restrict__ w,
                           float* __restrict__ outp)
{
    __shared__ float ws[NBLK * NSNR * NB];   // 2016 floats
    for (int idx = threadIdx.x; idx < NBLK * NSNR * NB; idx += blockDim.x) ws[idx] = w[idx];
    __syncthreads();
    int t = blockIdx.x * blockDim.x + threadIdx.x;
    if (t >= NTRIP) return;
    float sr[NSNR];
    const float* s = sbf + (size_t)t * NSNR;
#pragma unroll
    for (int r = 0; r < NSNR; r++) sr[r] = s[r];
    float* op = outp + (size_t)t * (NBLK * NB);
#pragma unroll
    for (int b = 0; b < NBLK; b++) {
        float acc[NB];
#pragma unroll
        for (int j = 0; j < NB; j++) acc[j] = 0.f;
        for (int r = 0; r < NSNR; r++) {
            float sv = sr[r];
#pragma unroll
            for (int j = 0; j < NB; j++) acc[j] += sv * ws[b * NSNR * NB + r * NB + j];
        }
#pragma unroll
        for (int j = 0; j < NB; j++) op[b * NB + j] = acc[j];
    }
}

// ---------------- triplet scatter: M[idx_ji[w],:] += sum_j sbf_p[w,j] * Gh[idx_kj[w], j, :] --
__global__ __launch_bounds__(256) void trip_k(
    const __nv_bfloat16* __restrict__ Gh, const float* __restrict__ sbfp,
    const int* __restrict__ idx_kj, const int* __restrict__ idx_ji,
    float* __restrict__ Mo)
{
    int w = blockIdx.x * (blockDim.x >> 5) + (threadIdx.x >> 5);
    if (w >= NTRIP) return;
    int lane = threadIdx.x & 31;
    int kj = idx_kj[w], ji = idx_ji[w];
    float sv = (lane < NB) ? sbfp[(size_t)w * (NBLK * NB) + lane] : 0.f;
    const __nv_bfloat16* gr = Gh + (size_t)kj * (NB * HD) + lane * 4;
    float4 acc = make_float4(0.f, 0.f, 0.f, 0.f);
#pragma unroll
    for (int j = 0; j < NB; j++) {
        float s = __shfl_sync(0xffffffffu, sv, j);
        uint2 u = *(const uint2*)(gr + j * HD);
        __nv_bfloat162 p0 = *reinterpret_cast<__nv_bfloat162*>(&u.x);
        __nv_bfloat162 p1 = *reinterpret_cast<__nv_bfloat162*>(&u.y);
        float2 f0 = __bfloat1622float2(p0);
        float2 f1 = __bfloat1622float2(p1);
        acc.x += s * f0.x; acc.y += s * f0.y; acc.z += s * f1.x; acc.w += s * f1.y;
    }
    float* mo = Mo + (size_t)ji * HD + lane * 4;
    atomicAdd(mo + 0, acc.x);
    atomicAdd(mo + 1, acc.y);
    atomicAdd(mo + 2, acc.z);
    atomicAdd(mo + 3, acc.w);
}

// ---------------- batched out-block edge scatter over k=0..6 -----------------
__global__ void edge_scatter7_k(const float* __restrict__ rbf, const float* __restrict__ orw,
                                const float* __restrict__ xsave, const int* __restrict__ ei,
                                float* __restrict__ atom)
{
    int e = blockIdx.x, k = blockIdx.y, h = threadIdx.x;
    const float* rr = rbf + (size_t)e * NR;
    const float* w = orw + (size_t)k * NR * HD;
    float rp = 0.f;
#pragma unroll
    for (int r = 0; r < NR; r++) rp += rr[r] * w[r * HD + h];
    float v = rp * xsave[(size_t)k * NEDGES * HD + (size_t)e * HD + h];
    atomicAdd(&atom[(size_t)k * NATOMS * HD + (size_t)ei[e] * HD + h], v);
}

// ---------------- batched final per-atom dot + graph segment sum ----------------
__global__ void dot7_k(const float* __restrict__ atom2, const float* __restrict__ ow,
                       const int* __restrict__ batch, float* __restrict__ out)
{
    int a = blockIdx.x * (blockDim.x >> 5) + (threadIdx.x >> 5);
    if (a >= NATOMS) return;
    int k = blockIdx.y;
    int lane = threadIdx.x & 31;
    const float* ar = atom2 + (size_t)k * NATOMS * HD + (size_t)a * HD + lane * 4;
    const float* wr = ow + (size_t)k * HD + lane * 4;
    float s = ar[0] * wr[0] + ar[1] * wr[1] + ar[2] * wr[2] + ar[3] * wr[3];
#pragma unroll
    for (int o = 16; o > 0; o >>= 1) s += __shfl_down_sync(0xffffffffu, s, o);
    if (lane == 0) atomicAdd(&out[batch[a]], s);
}

// ==========================================================================================
extern "C" void kernel_launch(void* const* d_in, const int* in_sizes, int n_in,
                              void* d_out, int out_size)
{
    const int*   z        = (const int*)  d_in[0];
    const float* rbf      = (const float*)d_in[1];
    const float* sbf      = (const float*)d_in[2];
    const int*   ei       = (const int*)  d_in[3];
    const int*   ej       = (const int*)  d_in[4];
    const int*   idx_kj   = (const int*)  d_in[5];
    const int*   idx_ji   = (const int*)  d_in[6];
    const int*   batch    = (const int*)  d_in[7];
    const float* emb_table= (const float*)d_in[8];
    const float* emb_rbf_w= (const float*)d_in[9];
    const float* emb_rbf_b= (const float*)d_in[10];
    const float* emb_w    = (const float*)d_in[11];
    const float* emb_b    = (const float*)d_in[12];
    const float* int_rbf_w= (const float*)d_in[13];
    const float* int_sbf_w= (const float*)d_in[14];
    const float* int_kj_w = (const float*)d_in[15];
    const float* int_kj_b = (const float*)d_in[16];
    const float* int_ji_w = (const float*)d_in[17];
    const float* int_ji_b = (const float*)d_in[18];
    const float* int_W    = (const float*)d_in[19];
    const float* int_bef_w= (const float*)d_in[20];
    const float* int_bef_b= (const float*)d_in[21];
    const float* int_lin_w= (const float*)d_in[22];
    const float* int_lin_b= (const float*)d_in[23];
    const float* int_aft_w= (const float*)d_in[24];
    const float* int_aft_b= (const float*)d_in[25];
    const float* out_rbf_w= (const float*)d_in[26];
    const float* out_lins_w=(const float*)d_in[27];
    const float* out_lins_b=(const float*)d_in[28];
    const float* out_w    = (const float*)d_in[29];
    float* out = (float*)d_out;

    float *XSAVE, *XJI, *SBFP, *ATOM7, *ATOM7B;
    __half *XSH, *XJIh, *XKJh, *T1h, *AEMBh, *ATOMH, *ATOMH2, *WH;
    __nv_bfloat16* Gh;
    cudaGetSymbolAddress((void**)&XSAVE, g_XSAVE);
    cudaGetSymbolAddress((void**)&XSH,   g_XSH);
    cudaGetSymbolAddress((void**)&XJI,   g_XJI);
    cudaGetSymbolAddress((void**)&XJIh,  g_XJIh);
    cudaGetSymbolAddress((void**)&XKJh,  g_XKJh);
    cudaGetSymbolAddress((void**)&T1h,   g_T1h);
    cudaGetSymbolAddress((void**)&SBFP,  g_SBFP);
    cudaGetSymbolAddress((void**)&AEMBh, g_AEMBh);
    cudaGetSymbolAddress((void**)&Gh,    g_Gh);
    cudaGetSymbolAddress((void**)&ATOM7, g_ATOM7);
    cudaGetSymbolAddress((void**)&ATOM7B,g_ATOM7B);
    cudaGetSymbolAddress((void**)&ATOMH, g_ATOMH);
    cudaGetSymbolAddress((void**)&ATOMH2,g_ATOMH2);
    cudaGetSymbolAddress((void**)&WH,    g_WH);

    const dim3 gE(1, (NEDGES + 127) / 128);
    const dim3 gEG(NB, (NEDGES + 127) / 128);
    const dim3 gA7(1, (NATOMS + 127) / 128, 7);
    const size_t EH = (size_t)NEDGES * HD;
    const size_t AH7 = (size_t)NATOMS * HD;

    cudaMemsetAsync(out, 0, NGRAPHS * sizeof(float));
    cudaMemsetAsync(ATOM7, 0, (size_t)7 * AH7 * sizeof(float));

    // ---- convert all weights to half [N][K] ----
    auto cw = [&](const float* src, __half* dst, int K, int N, int cnt) {
        long total = (long)cnt * K * N;
        convw_k<<<(unsigned)((total + 255) / 256), 256>>>(src, dst, K, N, total);
    };
    cw(emb_w,      WH + WH_EMB, 3 * HD, HD, 1);
    cw(int_ji_w,   WH + WH_JI,  HD, HD, NBLK);
    cw(int_kj_w,   WH + WH_KJ,  HD, HD, NBLK);
    cw(int_bef_w,  WH + WH_BEF, HD, HD, NBLK * 2);
    cw(int_lin_w,  WH + WH_LIN, HD, HD, NBLK);
    cw(int_aft_w,  WH + WH_AFT, HD, HD, NBLK * 4);
    cw(out_lins_w, WH + WH_OUT, HD, HD, 7 * 3);
    convg_k<<<(NBLK * NB * HD * HD) / 256, 256>>>(int_W, WH + WH_G);

    sbfp_all_k<<<(NTRIP + 127) / 128, 128>>>(sbf, int_sbf_w, SBFP);

    // ---- embedding block -> XSAVE[0] (f32) + XSH[0] (half) ----
    embed_fill_k<<<NEDGES, HD>>>(z, ei, ej, rbf, emb_table, emb_rbf_w, emb_rbf_b, AEMBh);
    gemm_h<<<gE, 256>>>(AEMBh, 1, WH + WH_EMB, emb_b, nullptr, nullptr, nullptr,
                        XSAVE, XSH, nullptr, NEDGES, HD, 3 * HD, 1, 0, 0, 0, 0);

    for (int b = 0; b < NBLK; b++) {
        float*  xa  = XSAVE + (size_t)b * EH;
        float*  xb  = XSAVE + (size_t)(b + 1) * EH;
        __half* xah = XSH   + (size_t)b * EH;
        __half* xbh = XSH   + (size_t)(b + 1) * EH;

        // ji: f32 out (atomic target)
        gemm_h<<<gE, 256>>>(xah, 1, WH + WH_JI + (size_t)b * HD * HD,
                            int_ji_b + (size_t)b * HD, nullptr, nullptr, nullptr,
                            XJI, nullptr, nullptr, NEDGES, HD, HD, 1, 0, 0, 0, 0);
        // kj (fused rbf-proj multiply): half out only
        gemm_h<<<gE, 256>>>(xah, 1, WH + WH_KJ + (size_t)b * HD * HD,
                            int_kj_b + (size_t)b * HD, nullptr,
                            rbf, int_rbf_w + (size_t)b * NR * HD,
                            nullptr, XKJh, nullptr, NEDGES, HD, HD, 1, 0, 0, 0, 0);
        // G: bf16 out
        gemm_h<<<gEG, 256>>>(XKJh, 1, WH + WH_G + (size_t)b * NB * HD * HD,
                             nullptr, nullptr, nullptr, nullptr,
                             nullptr, nullptr, Gh, NEDGES, NB * HD, HD, 0, 0, 0, 0, 0);

        trip_k<<<(NTRIP + 7) / 8, 256>>>(Gh, SBFP + (size_t)b * NB, idx_kj, idx_ji, XJI);

        // residual before: XJI (f32 A) -> T1h -> XJI (+= via addv), dual out
        gemm_h<<<gE, 256>>>(XJI, 0, WH + WH_BEF + ((size_t)b * 2 + 0) * HD * HD,
                            int_bef_b + ((size_t)b * 2 + 0) * HD, nullptr, nullptr, nullptr,
                            nullptr, T1h, nullptr, NEDGES, HD, HD, 1, 0, 0, 0, 0);
        gemm_h<<<gE, 256>>>(T1h, 1, WH + WH_BEF + ((size_t)b * 2 + 1) * HD * HD,
                            int_bef_b + ((size_t)b * 2 + 1) * HD, XJI, nullptr, nullptr,
                            XJI, XJIh, nullptr, NEDGES, HD, HD, 1, 0, 0, 0, 0);

        // lin + skip -> xb (f32) + xbh (half)
        gemm_h<<<gE, 256>>>(XJIh, 1, WH + WH_LIN + (size_t)b * HD * HD,
                            int_lin_b + (size_t)b * HD, xa, nullptr, nullptr,
                            xb, xbh, nullptr, NEDGES, HD, HD, 1, 0, 0, 0, 0);

        // residual after (2 layers), in place on xb/xbh
        for (int r = 0; r < 2; r++) {
            gemm_h<<<gE, 256>>>(xbh, 1, WH + WH_AFT + ((size_t)b * 4 + 2 * r + 0) * HD * HD,
                                int_aft_b + ((size_t)b * 4 + 2 * r + 0) * HD,
                                nullptr, nullptr, nullptr,
                                nullptr, T1h, nullptr, NEDGES, HD, HD, 1, 0, 0, 0, 0);
            gemm_h<<<gE, 256>>>(T1h, 1, WH + WH_AFT + ((size_t)b * 4 + 2 * r + 1) * HD * HD,
                                int_aft_b + ((size_t)b * 4 + 2 * r + 1) * HD,
                                xb, nullptr, nullptr,
                                xb, xbh, nullptr, NEDGES, HD, HD, 1, 0, 0, 0, 0);
        }
    }

    // ---- all 7 out_blocks, batched at the end ----
    edge_scatter7_k<<<dim3(NEDGES, 7), HD>>>(rbf, out_rbf_w, XSAVE, ei, ATOM7);
    gemm_h<<<gA7, 256>>>(ATOM7, 0, WH + WH_OUT + 0 * HD * HD, out_lins_b + 0 * HD,
                         nullptr, nullptr, nullptr, nullptr, ATOMH, nullptr,
                         NATOMS, HD, HD, 1, AH7, (size_t)3 * HD * HD, (size_t)3 * HD, AH7);
    gemm_h<<<gA7, 256>>>(ATOMH, 1, WH + WH_OUT + 1 * HD * HD, out_lins_b + 1 * HD,
                         nullptr, nullptr, nullptr, nullptr, ATOMH2, nullptr,
                         NATOMS, HD, HD, 1, AH7, (size_t)3 * HD * HD, (size_t)3 * HD, AH7);
    gemm_h<<<gA7, 256>>>(ATOMH2, 1, WH + WH_OUT + 2 * HD * HD, out_lins_b + 2 * HD,
                         nullptr, nullptr, nullptr, ATOM7B, nullptr, nullptr,
                         NATOMS, HD, HD, 1, AH7, (size_t)3 * HD * HD, (size_t)3 * HD, AH7);
    dot7_k<<<dim3((NATOMS + 7) / 8, 7), 256>>>(ATOM7B, out_w, batch, out);
}

// round 11
// speedup vs baseline: 1.3673x; 1.1128x over previous
#include <cuda_runtime.h>
#include <cuda_fp16.h>
#include <cuda_bf16.h>
#include <math.h>

#define NATOMS 8000
#define NEDGES 100000
#define NTRIP  500000
#define NGRAPHS 64
#define HD 128
#define NR 6
#define NSNR 42
#define NB 8
#define NBLK 6
#define HDHD (HD*HD)

// ---------------- device scratch (no allocation allowed) ----------------
__device__ float  g_XSAVE[(size_t)(NBLK + 1) * NEDGES * HD];   // f32 x per block
__device__ __half g_XSH  [(size_t)(NBLK + 1) * NEDGES * HD];   // half mirror of x
__device__ float  g_XJI [NEDGES*HD];                           // f32 (atomic target)
__device__ __half g_XKJh[NEDGES*HD];
__device__ float  g_SBFP[(size_t)NTRIP*NBLK*NB];
__device__ __half g_AEMBh[(size_t)NEDGES*3*HD];                // embed input [E,384] half
__device__ __nv_bfloat16 g_Gh[(size_t)NEDGES*NB*HD];           // G in bf16
__device__ float  g_ATOM7 [(size_t)7*NATOMS*HD];
__device__ float  g_ATOM7B[(size_t)7*NATOMS*HD];
__device__ __half g_ATOMH [(size_t)7*NATOMS*HD];
__device__ __half g_ATOMH2[(size_t)7*NATOMS*HD];

// half weight copies, transposed to [N][K]
#define WH_EMB  0
#define WH_JI   (WH_EMB + 3*HDHD)
#define WH_KJ   (WH_JI  + NBLK*HDHD)
#define WH_BEF  (WH_KJ  + NBLK*HDHD)
#define WH_LIN  (WH_BEF + NBLK*2*HDHD)
#define WH_AFT  (WH_LIN + NBLK*HDHD)
#define WH_OUT  (WH_AFT + NBLK*4*HDHD)
#define WH_G    (WH_OUT + 7*3*HDHD)
#define WH_TOTAL (WH_G + NBLK*NB*HDHD)
__device__ __half g_WH[WH_TOTAL];

__device__ __forceinline__ float silu(float x) { return x / (1.0f + expf(-x)); }

__device__ __forceinline__ unsigned packh2(float a, float b) {
    __half2 h = __floats2half2_rn(a, b);
    return *reinterpret_cast<unsigned*>(&h);
}

__device__ __forceinline__ void mma_f16(float* c, const unsigned* a, const unsigned* b) {
    asm volatile(
        "mma.sync.aligned.m16n8k16.row.col.f32.f16.f16.f32 "
        "{%0,%1,%2,%3}, {%4,%5,%6,%7}, {%8,%9}, {%0,%1,%2,%3};"
        : "+f"(c[0]), "+f"(c[1]), "+f"(c[2]), "+f"(c[3])
        : "r"(a[0]), "r"(a[1]), "r"(a[2]), "r"(a[3]),
          "r"(b[0]), "r"(b[1]));
}

__device__ __forceinline__ void cp16(unsigned saddr, const void* g, int bytes) {
    asm volatile("cp.async.cg.shared.global [%0], [%1], 16, %2;"
                 :: "r"(saddr), "l"(g), "r"(bytes) : "memory");
}

__device__ __forceinline__ void ldsm4(unsigned& r0, unsigned& r1, unsigned& r2, unsigned& r3,
                                      const __half* p) {
    unsigned addr = (unsigned)__cvta_generic_to_shared(p);
    asm volatile("ldmatrix.sync.aligned.m8n8.x4.shared.b16 {%0,%1,%2,%3}, [%4];"
                 : "=r"(r0), "=r"(r1), "=r"(r2), "=r"(r3) : "r"(addr));
}

// ---------------- weight convert: dst[m][n][k] = half(src[m][k][n]) ----------------
__global__ void convw_k(const float* __restrict__ src, __half* __restrict__ dst,
                        int K, int N, long total)
{
    long idx = (long)blockIdx.x * blockDim.x + threadIdx.x;
    if (idx >= total) return;
    long per = (long)K * N;
    long m = idx / per, r = idx % per;
    int n = (int)(r / K), k = (int)(r % K);
    dst[idx] = __float2half(src[m * per + (size_t)k * N + n]);
}

// ---------------- G weight convert: dst[b][j*128+i][l] = half(W[b][i][j][l]) -------
__global__ void convg_k(const float* __restrict__ W, __half* __restrict__ dst)
{
    int idx = blockIdx.x * blockDim.x + threadIdx.x;     // 6*131072
    int b = idx >> 17;
    int r = idx & 131071;
    int n = r >> 7, l = r & 127;
    int j = n >> 7, i = n & 127;
    dst[idx] = __float2half(W[(size_t)b * 131072 + (size_t)i * 1024 + j * 128 + l]);
}

// ---------------- fp16 tensor-core GEMM: epi(A[M,K] @ Bh^T + bias) -> {f32, half, bf16} ----
#define AST 72   // halfs per smem row
__global__ __launch_bounds__(256, 2) void gemm_h(
    const void* __restrict__ Av, int aHalf, const __half* __restrict__ Bh,
    const float* __restrict__ bias, const float* __restrict__ addv,
    const float* __restrict__ rbfv, const float* __restrict__ rbfw,
    float* __restrict__ Cf, __half* __restrict__ Chh, __nv_bfloat16* __restrict__ Cbf,
    int M, int N, int K, int act,
    size_t aZ, size_t bZ, size_t biasZ, size_t cZ)
{
    __shared__ __half As[128][AST];
    __shared__ __half Bs[128][AST];

    const float* Af = (const float*)Av + blockIdx.z * aZ;
    const __half* Ah = (const __half*)Av + blockIdx.z * aZ;
    Bh += blockIdx.z * bZ;
    if (bias) bias += blockIdx.z * biasZ;

    const int tid = threadIdx.x;
    const int bM = blockIdx.y * 128;
    const int bN = blockIdx.x * 128;
    const int lane = tid & 31, warp = tid >> 5;
    const int gid = lane >> 2, tig = lane & 3;
    const int wm = warp >> 2, wn = warp & 3;     // 2 x 4 warps; warp tile 64x32

    const int aRowO = (lane & 7) + ((lane >> 3) & 1) * 8;
    const int aColO = ((lane >> 4) & 1) * 8;
    const int bRowO = (lane & 7) + ((lane >> 4) & 1) * 8;
    const int bColO = ((lane >> 3) & 1) * 8;

    float c[4][4][4];
#pragma unroll
    for (int i = 0; i < 4; i++)
#pragma unroll
        for (int j = 0; j < 4; j++)
#pragma unroll
            for (int q = 0; q < 4; q++) c[i][j][q] = 0.f;

    unsigned sA = (unsigned)__cvta_generic_to_shared(&As[0][0]);
    unsigned sB = (unsigned)__cvta_generic_to_shared(&Bs[0][0]);

    for (int kc = 0; kc < K; kc += 64) {
        if (kc) __syncthreads();

#pragma unroll
        for (int it = 0; it < 4; it++) {
            int f = it * 256 + tid;
            int row = f >> 3, c8 = (f & 7) * 8;
            cp16(sB + (row * AST + c8) * 2,
                 Bh + (size_t)(bN + row) * K + kc + c8, 16);
        }
        if (aHalf) {
#pragma unroll
            for (int it = 0; it < 4; it++) {
                int f = it * 256 + tid;
                int row = f >> 3, c8 = (f & 7) * 8;
                cp16(sA + (row * AST + c8) * 2,
                     Ah + (size_t)(bM + row) * K + kc + c8,
                     (bM + row) < M ? 16 : 0);
            }
        } else {
#pragma unroll
            for (int it = 0; it < 8; it++) {
                int f = it * 256 + tid;
                int row = f >> 4, c4 = (f & 15) * 4;
                float4 v = make_float4(0.f, 0.f, 0.f, 0.f);
                if (bM + row < M)
                    v = *(const float4*)(Af + (size_t)(bM + row) * K + kc + c4);
                *(uint2*)&As[row][c4] = make_uint2(packh2(v.x, v.y), packh2(v.z, v.w));
            }
        }
        asm volatile("cp.async.commit_group;" ::: "memory");
        asm volatile("cp.async.wait_group 0;" ::: "memory");
        __syncthreads();

#pragma unroll
        for (int kk = 0; kk < 64; kk += 16) {
            unsigned af[4][4], bf[4][2];
#pragma unroll
            for (int fm = 0; fm < 4; fm++) {
                int m0 = wm * 64 + fm * 16;
                ldsm4(af[fm][0], af[fm][1], af[fm][2], af[fm][3],
                      &As[m0 + aRowO][kk + aColO]);
            }
#pragma unroll
            for (int p = 0; p < 2; p++) {
                int n0 = wn * 32 + p * 16;
                ldsm4(bf[2 * p][0], bf[2 * p][1], bf[2 * p + 1][0], bf[2 * p + 1][1],
                      &Bs[n0 + bRowO][kk + bColO]);
            }
#pragma unroll
            for (int fm = 0; fm < 4; fm++)
#pragma unroll
                for (int fn = 0; fn < 4; fn++)
                    mma_f16(c[fm][fn], af[fm], bf[fn]);
        }
    }

    if (Cf)  Cf  += blockIdx.z * cZ;
    if (Chh) Chh += blockIdx.z * cZ;

#pragma unroll
    for (int fm = 0; fm < 4; fm++) {
#pragma unroll
        for (int half_ = 0; half_ < 2; half_++) {
            int row = bM + wm * 64 + fm * 16 + gid + half_ * 8;
            if (row >= M) continue;
            float rr[NR];
            if (rbfv) {
#pragma unroll
                for (int r = 0; r < NR; r++) rr[r] = rbfv[(size_t)row * NR + r];
            }
#pragma unroll
            for (int fn = 0; fn < 4; fn++) {
                int col = bN + wn * 32 + fn * 8 + tig * 2;
                float v0 = c[fm][fn][half_ * 2 + 0] + (bias ? bias[col] : 0.f);
                float v1 = c[fm][fn][half_ * 2 + 1] + (bias ? bias[col + 1] : 0.f);
                if (act) { v0 = silu(v0); v1 = silu(v1); }
                size_t base = (size_t)row * N + col;
                if (rbfv) {
                    float rp0 = 0.f, rp1 = 0.f;
#pragma unroll
                    for (int r = 0; r < NR; r++) {
                        rp0 += rr[r] * rbfw[r * HD + col];
                        rp1 += rr[r] * rbfw[r * HD + col + 1];
                    }
                    v0 *= rp0; v1 *= rp1;
                }
                if (addv) {
                    float2 av = *(const float2*)(addv + base);
                    v0 += av.x; v1 += av.y;
                }
                if (Cf)  *(float2*)(Cf + base) = make_float2(v0, v1);
                if (Chh) *(unsigned*)(Chh + base) = packh2(v0, v1);
                if (Cbf) *(__nv_bfloat162*)(Cbf + base) =
                             __float22bfloat162_rn(make_float2(v0, v1));
            }
        }
    }
}

// ---------------- fused 7-layer residual chain (64-row tiles, K=N=128) ---------------
// stages: 0 bef1, 1 bef2(+XJI), 2 lin(+xa, skip:=v), 3 aft1, 4 aft2(+skip, skip:=v),
//         5 aft3, 6 aft4(+skip) -> xb f32 + xbh half
#define CST 136   // Act stride (halfs); 272B row = 17x16B (ldmatrix-aligned)
__global__ __launch_bounds__(256) void chain_k(
    const float* __restrict__ XJI, const float* __restrict__ xa,
    const __half* __restrict__ Wbef, const __half* __restrict__ Wlin,
    const __half* __restrict__ Waft,
    const float* __restrict__ bbef, const float* __restrict__ blin,
    const float* __restrict__ baft,
    float* __restrict__ xb, __half* __restrict__ xbh, int M)
{
    __shared__ __half Act[64][CST];   // 17.4 KB
    __shared__ __half Wb[128][AST];   // 18.4 KB

    const int tid = threadIdx.x;
    const int bM = blockIdx.x * 64;
    const int lane = tid & 31, warp = tid >> 5;
    const int gid = lane >> 2, tig = lane & 3;
    const int wm = warp >> 2, wn = warp & 3;   // warp tile 32x32

    const int aRowO = (lane & 7) + ((lane >> 3) & 1) * 8;
    const int aColO = ((lane >> 4) & 1) * 8;
    const int bRowO = (lane & 7) + ((lane >> 4) & 1) * 8;
    const int bColO = ((lane >> 3) & 1) * 8;

    unsigned sW = (unsigned)__cvta_generic_to_shared(&Wb[0][0]);

    // load XJI tile -> Act (half)
#pragma unroll
    for (int it = 0; it < 8; it++) {
        int f = it * 256 + tid;
        int row = f >> 5, c4 = (f & 31) * 4;
        float4 v = make_float4(0.f, 0.f, 0.f, 0.f);
        if (bM + row < M)
            v = *(const float4*)(XJI + (size_t)(bM + row) * HD + c4);
        *(uint2*)&Act[row][c4] = make_uint2(packh2(v.x, v.y), packh2(v.z, v.w));
    }

    float skip[2][4][4];

    for (int s = 0; s < 7; s++) {
        const __half* Wp;
        const float* bp;
        if (s == 0)      { Wp = Wbef;              bp = bbef; }
        else if (s == 1) { Wp = Wbef + HDHD;       bp = bbef + HD; }
        else if (s == 2) { Wp = Wlin;              bp = blin; }
        else             { Wp = Waft + (s-3)*HDHD; bp = baft + (s-3)*HD; }

        float acc[2][4][4];
#pragma unroll
        for (int i = 0; i < 2; i++)
#pragma unroll
            for (int j = 0; j < 4; j++)
#pragma unroll
                for (int q = 0; q < 4; q++) acc[i][j][q] = 0.f;

        for (int kc = 0; kc < HD; kc += 64) {
            __syncthreads();   // Wb reuse / Act writes visible
#pragma unroll
            for (int it = 0; it < 4; it++) {
                int f = it * 256 + tid;
                int row = f >> 3, c8 = (f & 7) * 8;
                cp16(sW + (row * AST + c8) * 2, Wp + (size_t)row * HD + kc + c8, 16);
            }
            asm volatile("cp.async.commit_group;" ::: "memory");
            asm volatile("cp.async.wait_group 0;" ::: "memory");
            __syncthreads();

#pragma unroll
            for (int kk = 0; kk < 64; kk += 16) {
                unsigned af[2][4], bf[4][2];
#pragma unroll
                for (int fm = 0; fm < 2; fm++) {
                    int m0 = wm * 32 + fm * 16;
                    ldsm4(af[fm][0], af[fm][1], af[fm][2], af[fm][3],
                          &Act[m0 + aRowO][kc + kk + aColO]);
                }
#pragma unroll
                for (int p = 0; p < 2; p++) {
                    int n0 = wn * 32 + p * 16;
                    ldsm4(bf[2*p][0], bf[2*p][1], bf[2*p+1][0], bf[2*p+1][1],
                          &Wb[n0 + bRowO][kk + bColO]);
                }
#pragma unroll
                for (int fm = 0; fm < 2; fm++)
#pragma unroll
                    for (int fn = 0; fn < 4; fn++)
                        mma_f16(acc[fm][fn], af[fm], bf[fn]);
            }
        }
        __syncthreads();   // all Act reads done before overwrite

        // epilogue
#pragma unroll
        for (int fm = 0; fm < 2; fm++) {
#pragma unroll
            for (int half_ = 0; half_ < 2; half_++) {
                int lrow = wm * 32 + fm * 16 + gid + half_ * 8;
                int grow = bM + lrow;
                int inb = grow < M;
#pragma unroll
                for (int fn = 0; fn < 4; fn++) {
                    int col = wn * 32 + fn * 8 + tig * 2;
                    float v0 = silu(acc[fm][fn][half_*2+0] + bp[col]);
                    float v1 = silu(acc[fm][fn][half_*2+1] + bp[col+1]);
                    size_t base = (size_t)grow * HD + col;
                    if (s == 1 && inb) {
                        float2 av = *(const float2*)(XJI + base);
                        v0 += av.x; v1 += av.y;
                    } else if (s == 2) {
                        if (inb) {
                            float2 av = *(const float2*)(xa + base);
                            v0 += av.x; v1 += av.y;
                        }
                        skip[fm][fn][half_*2+0] = v0;
                        skip[fm][fn][half_*2+1] = v1;
                    } else if (s == 4) {
                        v0 += skip[fm][fn][half_*2+0];
                        v1 += skip[fm][fn][half_*2+1];
                        skip[fm][fn][half_*2+0] = v0;
                        skip[fm][fn][half_*2+1] = v1;
                    } else if (s == 6) {
                        v0 += skip[fm][fn][half_*2+0];
                        v1 += skip[fm][fn][half_*2+1];
                    }
                    if (s < 6) {
                        *(unsigned*)&Act[lrow][col] = packh2(v0, v1);
                    } else if (inb) {
                        *(float2*)(xb + base) = make_float2(v0, v1);
                        *(unsigned*)(xbh + base) = packh2(v0, v1);
                    }
                }
            }
        }
    }
}

// ---------------- embedding: build A_emb[E,384] = [h_i | h_j | silu(rbf@W+b)] half ----
__global__ void embed_fill_k(const int* __restrict__ z, const int* __restrict__ ei,
                             const int* __restrict__ ej, const float* __restrict__ rbf,
                             const float* __restrict__ emb_table,
                             const float* __restrict__ erw, const float* __restrict__ erb,
                             __half* __restrict__ Aemb)
{
    int e = blockIdx.x, h = threadIdx.x;
    int zi = z[ei[e]], zj = z[ej[e]];
    float s = erb[h];
    const float* rr = rbf + (size_t)e * NR;
#pragma unroll
    for (int r = 0; r < NR; r++) s += rr[r] * erw[r * HD + h];
    size_t base = (size_t)e * (3 * HD);
    Aemb[base + h]           = __float2half(emb_table[(size_t)zi * HD + h]);
    Aemb[base + HD + h]      = __float2half(emb_table[(size_t)zj * HD + h]);
    Aemb[base + 2 * HD + h]  = __float2half(silu(s));
}

// ---------------- sbf projection, ALL blocks ----------------
__global__ void sbfp_all_k(const float* __restrict__ sbf, const float* __restrict__ w,
                           float* __restrict__ outp)
{
    __shared__ float ws[NBLK * NSNR * NB];
    for (int idx = threadIdx.x; idx < NBLK * NSNR * NB; idx += blockDim.x) ws[idx] = w[idx];
    __syncthreads();
    int t = blockIdx.x * blockDim.x + threadIdx.x;
    if (t >= NTRIP) return;
    float sr[NSNR];
    const float* s = sbf + (size_t)t * NSNR;
#pragma unroll
    for (int r = 0; r < NSNR; r++) sr[r] = s[r];
    float* op = outp + (size_t)t * (NBLK * NB);
#pragma unroll
    for (int b = 0; b < NBLK; b++) {
        float acc[NB];
#pragma unroll
        for (int j = 0; j < NB; j++) acc[j] = 0.f;
        for (int r = 0; r < NSNR; r++) {
            float sv = sr[r];
#pragma unroll
            for (int j = 0; j < NB; j++) acc[j] += sv * ws[b * NSNR * NB + r * NB + j];
        }
#pragma unroll
        for (int j = 0; j < NB; j++) op[b * NB + j] = acc[j];
    }
}

// ---------------- triplet scatter ----------------
__global__ __launch_bounds__(256) void trip_k(
    const __nv_bfloat16* __restrict__ Gh, const float* __restrict__ sbfp,
    const int* __restrict__ idx_kj, const int* __restrict__ idx_ji,
    float* __restrict__ Mo)
{
    int w = blockIdx.x * (blockDim.x >> 5) + (threadIdx.x >> 5);
    if (w >= NTRIP) return;
    int lane = threadIdx.x & 31;
    int kj = idx_kj[w], ji = idx_ji[w];
    float sv = (lane < NB) ? sbfp[(size_t)w * (NBLK * NB) + lane] : 0.f;
    const __nv_bfloat16* gr = Gh + (size_t)kj * (NB * HD) + lane * 4;
    float4 acc = make_float4(0.f, 0.f, 0.f, 0.f);
#pragma unroll
    for (int j = 0; j < NB; j++) {
        float s = __shfl_sync(0xffffffffu, sv, j);
        uint2 u = *(const uint2*)(gr + j * HD);
        __nv_bfloat162 p0 = *reinterpret_cast<__nv_bfloat162*>(&u.x);
        __nv_bfloat162 p1 = *reinterpret_cast<__nv_bfloat162*>(&u.y);
        float2 f0 = __bfloat1622float2(p0);
        float2 f1 = __bfloat1622float2(p1);
        acc.x += s * f0.x; acc.y += s * f0.y; acc.z += s * f1.x; acc.w += s * f1.y;
    }
    float* mo = Mo + (size_t)ji * HD + lane * 4;
    atomicAdd(mo + 0, acc.x);
    atomicAdd(mo + 1, acc.y);
    atomicAdd(mo + 2, acc.z);
    atomicAdd(mo + 3, acc.w);
}

// ---------------- batched out-block edge scatter ----------------
__global__ void edge_scatter7_k(const float* __restrict__ rbf, const float* __restrict__ orw,
                                const float* __restrict__ xsave, const int* __restrict__ ei,
                                float* __restrict__ atom)
{
    int e = blockIdx.x, k = blockIdx.y, h = threadIdx.x;
    const float* rr = rbf + (size_t)e * NR;
    const float* w = orw + (size_t)k * NR * HD;
    float rp = 0.f;
#pragma unroll
    for (int r = 0; r < NR; r++) rp += rr[r] * w[r * HD + h];
    float v = rp * xsave[(size_t)k * NEDGES * HD + (size_t)e * HD + h];
    atomicAdd(&atom[(size_t)k * NATOMS * HD + (size_t)ei[e] * HD + h], v);
}

// ---------------- batched final per-atom dot + graph segment sum ----------------
__global__ void dot7_k(const float* __restrict__ atom2, const float* __restrict__ ow,
                       const int* __restrict__ batch, float* __restrict__ out)
{
    int a = blockIdx.x * (blockDim.x >> 5) + (threadIdx.x >> 5);
    if (a >= NATOMS) return;
    int k = blockIdx.y;
    int lane = threadIdx.x & 31;
    const float* ar = atom2 + (size_t)k * NATOMS * HD + (size_t)a * HD + lane * 4;
    const float* wr = ow + (size_t)k * HD + lane * 4;
    float s = ar[0] * wr[0] + ar[1] * wr[1] + ar[2] * wr[2] + ar[3] * wr[3];
#pragma unroll
    for (int o = 16; o > 0; o >>= 1) s += __shfl_down_sync(0xffffffffu, s, o);
    if (lane == 0) atomicAdd(&out[batch[a]], s);
}

// ==========================================================================================
extern "C" void kernel_launch(void* const* d_in, const int* in_sizes, int n_in,
                              void* d_out, int out_size)
{
    const int*   z        = (const int*)  d_in[0];
    const float* rbf      = (const float*)d_in[1];
    const float* sbf      = (const float*)d_in[2];
    const int*   ei       = (const int*)  d_in[3];
    const int*   ej       = (const int*)  d_in[4];
    const int*   idx_kj   = (const int*)  d_in[5];
    const int*   idx_ji   = (const int*)  d_in[6];
    const int*   batch    = (const int*)  d_in[7];
    const float* emb_table= (const float*)d_in[8];
    const float* emb_rbf_w= (const float*)d_in[9];
    const float* emb_rbf_b= (const float*)d_in[10];
    const float* emb_w    = (const float*)d_in[11];
    const float* emb_b    = (const float*)d_in[12];
    const float* int_rbf_w= (const float*)d_in[13];
    const float* int_sbf_w= (const float*)d_in[14];
    const float* int_kj_w = (const float*)d_in[15];
    const float* int_kj_b = (const float*)d_in[16];
    const float* int_ji_w = (const float*)d_in[17];
    const float* int_ji_b = (const float*)d_in[18];
    const float* int_W    = (const float*)d_in[19];
    const float* int_bef_w= (const float*)d_in[20];
    const float* int_bef_b= (const float*)d_in[21];
    const float* int_lin_w= (const float*)d_in[22];
    const float* int_lin_b= (const float*)d_in[23];
    const float* int_aft_w= (const float*)d_in[24];
    const float* int_aft_b= (const float*)d_in[25];
    const float* out_rbf_w= (const float*)d_in[26];
    const float* out_lins_w=(const float*)d_in[27];
    const float* out_lins_b=(const float*)d_in[28];
    const float* out_w    = (const float*)d_in[29];
    float* out = (float*)d_out;

    float *XSAVE, *XJI, *SBFP, *ATOM7, *ATOM7B;
    __half *XSH, *XKJh, *AEMBh, *ATOMH, *ATOMH2, *WH;
    __nv_bfloat16* Gh;
    cudaGetSymbolAddress((void**)&XSAVE, g_XSAVE);
    cudaGetSymbolAddress((void**)&XSH,   g_XSH);
    cudaGetSymbolAddress((void**)&XJI,   g_XJI);
    cudaGetSymbolAddress((void**)&XKJh,  g_XKJh);
    cudaGetSymbolAddress((void**)&SBFP,  g_SBFP);
    cudaGetSymbolAddress((void**)&AEMBh, g_AEMBh);
    cudaGetSymbolAddress((void**)&Gh,    g_Gh);
    cudaGetSymbolAddress((void**)&ATOM7, g_ATOM7);
    cudaGetSymbolAddress((void**)&ATOM7B,g_ATOM7B);
    cudaGetSymbolAddress((void**)&ATOMH, g_ATOMH);
    cudaGetSymbolAddress((void**)&ATOMH2,g_ATOMH2);
    cudaGetSymbolAddress((void**)&WH,    g_WH);

    const dim3 gE(1, (NEDGES + 127) / 128);
    const dim3 gEG(NB, (NEDGES + 127) / 128);
    const dim3 gA7(1, (NATOMS + 127) / 128, 7);
    const size_t EH = (size_t)NEDGES * HD;
    const size_t AH7 = (size_t)NATOMS * HD;

    cudaMemsetAsync(out, 0, NGRAPHS * sizeof(float));
    cudaMemsetAsync(ATOM7, 0, (size_t)7 * AH7 * sizeof(float));

    auto cw = [&](const float* src, __half* dst, int K, int N, int cnt) {
        long total = (long)cnt * K * N;
        convw_k<<<(unsigned)((total + 255) / 256), 256>>>(src, dst, K, N, total);
    };
    cw(emb_w,      WH + WH_EMB, 3 * HD, HD, 1);
    cw(int_ji_w,   WH + WH_JI,  HD, HD, NBLK);
    cw(int_kj_w,   WH + WH_KJ,  HD, HD, NBLK);
    cw(int_bef_w,  WH + WH_BEF, HD, HD, NBLK * 2);
    cw(int_lin_w,  WH + WH_LIN, HD, HD, NBLK);
    cw(int_aft_w,  WH + WH_AFT, HD, HD, NBLK * 4);
    cw(out_lins_w, WH + WH_OUT, HD, HD, 7 * 3);
    convg_k<<<(NBLK * NB * HD * HD) / 256, 256>>>(int_W, WH + WH_G);

    sbfp_all_k<<<(NTRIP + 127) / 128, 128>>>(sbf, int_sbf_w, SBFP);

    // ---- embedding block -> XSAVE[0] (f32) + XSH[0] (half) ----
    embed_fill_k<<<NEDGES, HD>>>(z, ei, ej, rbf, emb_table, emb_rbf_w, emb_rbf_b, AEMBh);
    gemm_h<<<gE, 256>>>(AEMBh, 1, WH + WH_EMB, emb_b, nullptr, nullptr, nullptr,
                        XSAVE, XSH, nullptr, NEDGES, HD, 3 * HD, 1, 0, 0, 0, 0);

    for (int b = 0; b < NBLK; b++) {
        float*  xa  = XSAVE + (size_t)b * EH;
        float*  xb  = XSAVE + (size_t)(b + 1) * EH;
        __half* xah = XSH   + (size_t)b * EH;
        __half* xbh = XSH   + (size_t)(b + 1) * EH;

        // ji: f32 out (atomic target)
        gemm_h<<<gE, 256>>>(xah, 1, WH + WH_JI + (size_t)b * HDHD,
                            int_ji_b + (size_t)b * HD, nullptr, nullptr, nullptr,
                            XJI, nullptr, nullptr, NEDGES, HD, HD, 1, 0, 0, 0, 0);
        // kj (fused rbf-proj multiply): half out only
        gemm_h<<<gE, 256>>>(xah, 1, WH + WH_KJ + (size_t)b * HDHD,
                            int_kj_b + (size_t)b * HD, nullptr,
                            rbf, int_rbf_w + (size_t)b * NR * HD,
                            nullptr, XKJh, nullptr, NEDGES, HD, HD, 1, 0, 0, 0, 0);
        // G: bf16 out
        gemm_h<<<gEG, 256>>>(XKJh, 1, WH + WH_G + (size_t)b * NB * HDHD,
                             nullptr, nullptr, nullptr, nullptr,
                             nullptr, nullptr, Gh, NEDGES, NB * HD, HD, 0, 0, 0, 0, 0);

        trip_k<<<(NTRIP + 7) / 8, 256>>>(Gh, SBFP + (size_t)b * NB, idx_kj, idx_ji, XJI);

        // fused 7-layer chain -> xb (f32) + xbh (half)
        chain_k<<<(NEDGES + 63) / 64, 256>>>(
            XJI, xa,
            WH + WH_BEF + (size_t)b * 2 * HDHD,
            WH + WH_LIN + (size_t)b * HDHD,
            WH + WH_AFT + (size_t)b * 4 * HDHD,
            int_bef_b + (size_t)b * 2 * HD,
            int_lin_b + (size_t)b * HD,
            int_aft_b + (size_t)b * 4 * HD,
            xb, xbh, NEDGES);
    }

    // ---- all 7 out_blocks, batched at the end ----
    edge_scatter7_k<<<dim3(NEDGES, 7), HD>>>(rbf, out_rbf_w, XSAVE, ei, ATOM7);
    gemm_h<<<gA7, 256>>>(ATOM7, 0, WH + WH_OUT + 0 * HDHD, out_lins_b + 0 * HD,
                         nullptr, nullptr, nullptr, nullptr, ATOMH, nullptr,
                         NATOMS, HD, HD, 1, AH7, (size_t)3 * HDHD, (size_t)3 * HD, AH7);
    gemm_h<<<gA7, 256>>>(ATOMH, 1, WH + WH_OUT + 1 * HDHD, out_lins_b + 1 * HD,
                         nullptr, nullptr, nullptr, nullptr, ATOMH2, nullptr,
                         NATOMS, HD, HD, 1, AH7, (size_t)3 * HDHD, (size_t)3 * HD, AH7);
    gemm_h<<<gA7, 256>>>(ATOMH2, 1, WH + WH_OUT + 2 * HDHD, out_lins_b + 2 * HD,
                         nullptr, nullptr, nullptr, ATOM7B, nullptr, nullptr,
                         NATOMS, HD, HD, 1, AH7, (size_t)3 * HDHD, (size_t)3 * HD, AH7);
    dot7_k<<<dim3((NATOMS + 7) / 8, 7), 256>>>(ATOM7B, out_w, batch, out);
}

// round 12
// speedup vs baseline: 1.3841x; 1.0123x over previous
#include <cuda_runtime.h>
#include <cuda_fp16.h>
#include <cuda_bf16.h>
#include <math.h>

#define NATOMS 8000
#define NEDGES 100000
#define NTRIP  500000
#define NGRAPHS 64
#define HD 128
#define NR 6
#define NSNR 42
#define NB 8
#define NBLK 6
#define HDHD (HD*HD)

// ---------------- device scratch (no allocation allowed) ----------------
__device__ float  g_XSAVE[(size_t)(NBLK + 1) * NEDGES * HD];   // f32 x per block
__device__ __half g_XSH  [(size_t)(NBLK + 1) * NEDGES * HD];   // half mirror of x
__device__ float  g_XJI [NEDGES*HD];
__device__ __half g_XKJh[NEDGES*HD];
__device__ float  g_SBFP[(size_t)NTRIP*NBLK*NB];
__device__ __half g_AEMBh[(size_t)NEDGES*3*HD];                // embed input [E,384] half
__device__ __nv_bfloat16 g_Gh[(size_t)NEDGES*NB*HD];           // G in bf16
__device__ float  g_ATOM7 [(size_t)7*NATOMS*HD];
__device__ float  g_ATOM7B[(size_t)7*NATOMS*HD];
__device__ __half g_ATOMH [(size_t)7*NATOMS*HD];
__device__ __half g_ATOMH2[(size_t)7*NATOMS*HD];
// CSR of triplets by idx_ji
__device__ int    g_CNT [NEDGES];
__device__ int    g_OFF [NEDGES + 1];
__device__ int    g_POS [NEDGES];
__device__ int    g_PERM[NTRIP];

// half weight copies, transposed to [N][K]
#define WH_EMB  0
#define WH_JI   (WH_EMB + 3*HDHD)
#define WH_KJ   (WH_JI  + NBLK*HDHD)
#define WH_BEF  (WH_KJ  + NBLK*HDHD)
#define WH_LIN  (WH_BEF + NBLK*2*HDHD)
#define WH_AFT  (WH_LIN + NBLK*HDHD)
#define WH_OUT  (WH_AFT + NBLK*4*HDHD)
#define WH_G    (WH_OUT + 7*3*HDHD)
#define WH_TOTAL (WH_G + NBLK*NB*HDHD)
__device__ __half g_WH[WH_TOTAL];

__device__ __forceinline__ float silu(float x) { return x / (1.0f + expf(-x)); }

__device__ __forceinline__ unsigned packh2(float a, float b) {
    __half2 h = __floats2half2_rn(a, b);
    return *reinterpret_cast<unsigned*>(&h);
}

__device__ __forceinline__ void mma_f16(float* c, const unsigned* a, const unsigned* b) {
    asm volatile(
        "mma.sync.aligned.m16n8k16.row.col.f32.f16.f16.f32 "
        "{%0,%1,%2,%3}, {%4,%5,%6,%7}, {%8,%9}, {%0,%1,%2,%3};"
        : "+f"(c[0]), "+f"(c[1]), "+f"(c[2]), "+f"(c[3])
        : "r"(a[0]), "r"(a[1]), "r"(a[2]), "r"(a[3]),
          "r"(b[0]), "r"(b[1]));
}

__device__ __forceinline__ void cp16(unsigned saddr, const void* g, int bytes) {
    asm volatile("cp.async.cg.shared.global [%0], [%1], 16, %2;"
                 :: "r"(saddr), "l"(g), "r"(bytes) : "memory");
}

__device__ __forceinline__ void ldsm4(unsigned& r0, unsigned& r1, unsigned& r2, unsigned& r3,
                                      const __half* p) {
    unsigned addr = (unsigned)__cvta_generic_to_shared(p);
    asm volatile("ldmatrix.sync.aligned.m8n8.x4.shared.b16 {%0,%1,%2,%3}, [%4];"
                 : "=r"(r0), "=r"(r1), "=r"(r2), "=r"(r3) : "r"(addr));
}

// ---------------- weight convert: dst[m][n][k] = half(src[m][k][n]) ----------------
__global__ void convw_k(const float* __restrict__ src, __half* __restrict__ dst,
                        int K, int N, long total)
{
    long idx = (long)blockIdx.x * blockDim.x + threadIdx.x;
    if (idx >= total) return;
    long per = (long)K * N;
    long m = idx / per, r = idx % per;
    int n = (int)(r / K), k = (int)(r % K);
    dst[idx] = __float2half(src[m * per + (size_t)k * N + n]);
}

// ---------------- G weight convert ----------------
__global__ void convg_k(const float* __restrict__ W, __half* __restrict__ dst)
{
    int idx = blockIdx.x * blockDim.x + threadIdx.x;     // 6*131072
    int b = idx >> 17;
    int r = idx & 131071;
    int n = r >> 7, l = r & 127;
    int j = n >> 7, i = n & 127;
    dst[idx] = __float2half(W[(size_t)b * 131072 + (size_t)i * 1024 + j * 128 + l]);
}

// ---------------- CSR build: count / scan / place ----------------
__global__ void count_k(const int* __restrict__ idx_ji, int* __restrict__ cnt)
{
    int w = blockIdx.x * blockDim.x + threadIdx.x;
    if (w < NTRIP) atomicAdd(&cnt[idx_ji[w]], 1);
}

__global__ void scan_k(const int* __restrict__ cnt, int* __restrict__ off)
{
    __shared__ int buf[1024];
    __shared__ int carry;
    if (threadIdx.x == 0) carry = 0;
    __syncthreads();
    for (int base = 0; base < NEDGES; base += 1024) {
        int i = base + threadIdx.x;
        int v = (i < NEDGES) ? cnt[i] : 0;
        buf[threadIdx.x] = v;
        __syncthreads();
        for (int d = 1; d < 1024; d <<= 1) {
            int t = (threadIdx.x >= d) ? buf[threadIdx.x - d] : 0;
            __syncthreads();
            buf[threadIdx.x] += t;
            __syncthreads();
        }
        if (i < NEDGES) off[i] = carry + buf[threadIdx.x] - v;
        int total = buf[1023];
        __syncthreads();
        if (threadIdx.x == 0) carry += total;
        __syncthreads();
    }
    if (threadIdx.x == 0) off[NEDGES] = carry;
}

__global__ void place_k(const int* __restrict__ idx_ji, const int* __restrict__ off,
                        int* __restrict__ pos, int* __restrict__ perm)
{
    int w = blockIdx.x * blockDim.x + threadIdx.x;
    if (w >= NTRIP) return;
    int e = idx_ji[w];
    int p = off[e] + atomicAdd(&pos[e], 1);
    perm[p] = w;
}

// ---------------- fp16 tensor-core GEMM ----------------
#define AST 72   // halfs per smem row
__global__ __launch_bounds__(256, 2) void gemm_h(
    const void* __restrict__ Av, int aHalf, const __half* __restrict__ Bh,
    const float* __restrict__ bias, const float* __restrict__ addv,
    const float* __restrict__ rbfv, const float* __restrict__ rbfw,
    float* __restrict__ Cf, __half* __restrict__ Chh, __nv_bfloat16* __restrict__ Cbf,
    int M, int N, int K, int act,
    size_t aZ, size_t bZ, size_t biasZ, size_t cZ)
{
    __shared__ __half As[128][AST];
    __shared__ __half Bs[128][AST];

    const float* Af = (const float*)Av + blockIdx.z * aZ;
    const __half* Ah = (const __half*)Av + blockIdx.z * aZ;
    Bh += blockIdx.z * bZ;
    if (bias) bias += blockIdx.z * biasZ;

    const int tid = threadIdx.x;
    const int bM = blockIdx.y * 128;
    const int bN = blockIdx.x * 128;
    const int lane = tid & 31, warp = tid >> 5;
    const int gid = lane >> 2, tig = lane & 3;
    const int wm = warp >> 2, wn = warp & 3;

    const int aRowO = (lane & 7) + ((lane >> 3) & 1) * 8;
    const int aColO = ((lane >> 4) & 1) * 8;
    const int bRowO = (lane & 7) + ((lane >> 4) & 1) * 8;
    const int bColO = ((lane >> 3) & 1) * 8;

    float c[4][4][4];
#pragma unroll
    for (int i = 0; i < 4; i++)
#pragma unroll
        for (int j = 0; j < 4; j++)
#pragma unroll
            for (int q = 0; q < 4; q++) c[i][j][q] = 0.f;

    unsigned sA = (unsigned)__cvta_generic_to_shared(&As[0][0]);
    unsigned sB = (unsigned)__cvta_generic_to_shared(&Bs[0][0]);

    for (int kc = 0; kc < K; kc += 64) {
        if (kc) __syncthreads();

#pragma unroll
        for (int it = 0; it < 4; it++) {
            int f = it * 256 + tid;
            int row = f >> 3, c8 = (f & 7) * 8;
            cp16(sB + (row * AST + c8) * 2,
                 Bh + (size_t)(bN + row) * K + kc + c8, 16);
        }
        if (aHalf) {
#pragma unroll
            for (int it = 0; it < 4; it++) {
                int f = it * 256 + tid;
                int row = f >> 3, c8 = (f & 7) * 8;
                cp16(sA + (row * AST + c8) * 2,
                     Ah + (size_t)(bM + row) * K + kc + c8,
                     (bM + row) < M ? 16 : 0);
            }
        } else {
#pragma unroll
            for (int it = 0; it < 8; it++) {
                int f = it * 256 + tid;
                int row = f >> 4, c4 = (f & 15) * 4;
                float4 v = make_float4(0.f, 0.f, 0.f, 0.f);
                if (bM + row < M)
                    v = *(const float4*)(Af + (size_t)(bM + row) * K + kc + c4);
                *(uint2*)&As[row][c4] = make_uint2(packh2(v.x, v.y), packh2(v.z, v.w));
            }
        }
        asm volatile("cp.async.commit_group;" ::: "memory");
        asm volatile("cp.async.wait_group 0;" ::: "memory");
        __syncthreads();

#pragma unroll
        for (int kk = 0; kk < 64; kk += 16) {
            unsigned af[4][4], bf[4][2];
#pragma unroll
            for (int fm = 0; fm < 4; fm++) {
                int m0 = wm * 64 + fm * 16;
                ldsm4(af[fm][0], af[fm][1], af[fm][2], af[fm][3],
                      &As[m0 + aRowO][kk + aColO]);
            }
#pragma unroll
            for (int p = 0; p < 2; p++) {
                int n0 = wn * 32 + p * 16;
                ldsm4(bf[2 * p][0], bf[2 * p][1], bf[2 * p + 1][0], bf[2 * p + 1][1],
                      &Bs[n0 + bRowO][kk + bColO]);
            }
#pragma unroll
            for (int fm = 0; fm < 4; fm++)
#pragma unroll
                for (int fn = 0; fn < 4; fn++)
                    mma_f16(c[fm][fn], af[fm], bf[fn]);
        }
    }

    if (Cf)  Cf  += blockIdx.z * cZ;
    if (Chh) Chh += blockIdx.z * cZ;

#pragma unroll
    for (int fm = 0; fm < 4; fm++) {
#pragma unroll
        for (int half_ = 0; half_ < 2; half_++) {
            int row = bM + wm * 64 + fm * 16 + gid + half_ * 8;
            if (row >= M) continue;
            float rr[NR];
            if (rbfv) {
#pragma unroll
                for (int r = 0; r < NR; r++) rr[r] = rbfv[(size_t)row * NR + r];
            }
#pragma unroll
            for (int fn = 0; fn < 4; fn++) {
                int col = bN + wn * 32 + fn * 8 + tig * 2;
                float v0 = c[fm][fn][half_ * 2 + 0] + (bias ? bias[col] : 0.f);
                float v1 = c[fm][fn][half_ * 2 + 1] + (bias ? bias[col + 1] : 0.f);
                if (act) { v0 = silu(v0); v1 = silu(v1); }
                size_t base = (size_t)row * N + col;
                if (rbfv) {
                    float rp0 = 0.f, rp1 = 0.f;
#pragma unroll
                    for (int r = 0; r < NR; r++) {
                        rp0 += rr[r] * rbfw[r * HD + col];
                        rp1 += rr[r] * rbfw[r * HD + col + 1];
                    }
                    v0 *= rp0; v1 *= rp1;
                }
                if (addv) {
                    float2 av = *(const float2*)(addv + base);
                    v0 += av.x; v1 += av.y;
                }
                if (Cf)  *(float2*)(Cf + base) = make_float2(v0, v1);
                if (Chh) *(unsigned*)(Chh + base) = packh2(v0, v1);
                if (Cbf) *(__nv_bfloat162*)(Cbf + base) =
                             __float22bfloat162_rn(make_float2(v0, v1));
            }
        }
    }
}

// ---------------- fused 7-layer residual chain ----------------
#define CST 136
__global__ __launch_bounds__(256) void chain_k(
    const float* __restrict__ XJI, const float* __restrict__ xa,
    const __half* __restrict__ Wbef, const __half* __restrict__ Wlin,
    const __half* __restrict__ Waft,
    const float* __restrict__ bbef, const float* __restrict__ blin,
    const float* __restrict__ baft,
    float* __restrict__ xb, __half* __restrict__ xbh, int M)
{
    __shared__ __half Act[64][CST];
    __shared__ __half Wb[128][AST];

    const int tid = threadIdx.x;
    const int bM = blockIdx.x * 64;
    const int lane = tid & 31, warp = tid >> 5;
    const int gid = lane >> 2, tig = lane & 3;
    const int wm = warp >> 2, wn = warp & 3;

    const int aRowO = (lane & 7) + ((lane >> 3) & 1) * 8;
    const int aColO = ((lane >> 4) & 1) * 8;
    const int bRowO = (lane & 7) + ((lane >> 4) & 1) * 8;
    const int bColO = ((lane >> 3) & 1) * 8;

    unsigned sW = (unsigned)__cvta_generic_to_shared(&Wb[0][0]);

#pragma unroll
    for (int it = 0; it < 8; it++) {
        int f = it * 256 + tid;
        int row = f >> 5, c4 = (f & 31) * 4;
        float4 v = make_float4(0.f, 0.f, 0.f, 0.f);
        if (bM + row < M)
            v = *(const float4*)(XJI + (size_t)(bM + row) * HD + c4);
        *(uint2*)&Act[row][c4] = make_uint2(packh2(v.x, v.y), packh2(v.z, v.w));
    }

    float skip[2][4][4];

    for (int s = 0; s < 7; s++) {
        const __half* Wp;
        const float* bp;
        if (s == 0)      { Wp = Wbef;              bp = bbef; }
        else if (s == 1) { Wp = Wbef + HDHD;       bp = bbef + HD; }
        else if (s == 2) { Wp = Wlin;              bp = blin; }
        else             { Wp = Waft + (s-3)*HDHD; bp = baft + (s-3)*HD; }

        float acc[2][4][4];
#pragma unroll
        for (int i = 0; i < 2; i++)
#pragma unroll
            for (int j = 0; j < 4; j++)
#pragma unroll
                for (int q = 0; q < 4; q++) acc[i][j][q] = 0.f;

        for (int kc = 0; kc < HD; kc += 64) {
            __syncthreads();
#pragma unroll
            for (int it = 0; it < 4; it++) {
                int f = it * 256 + tid;
                int row = f >> 3, c8 = (f & 7) * 8;
                cp16(sW + (row * AST + c8) * 2, Wp + (size_t)row * HD + kc + c8, 16);
            }
            asm volatile("cp.async.commit_group;" ::: "memory");
            asm volatile("cp.async.wait_group 0;" ::: "memory");
            __syncthreads();

#pragma unroll
            for (int kk = 0; kk < 64; kk += 16) {
                unsigned af[2][4], bf[4][2];
#pragma unroll
                for (int fm = 0; fm < 2; fm++) {
                    int m0 = wm * 32 + fm * 16;
                    ldsm4(af[fm][0], af[fm][1], af[fm][2], af[fm][3],
                          &Act[m0 + aRowO][kc + kk + aColO]);
                }
#pragma unroll
                for (int p = 0; p < 2; p++) {
                    int n0 = wn * 32 + p * 16;
                    ldsm4(bf[2*p][0], bf[2*p][1], bf[2*p+1][0], bf[2*p+1][1],
                          &Wb[n0 + bRowO][kk + bColO]);
                }
#pragma unroll
                for (int fm = 0; fm < 2; fm++)
#pragma unroll
                    for (int fn = 0; fn < 4; fn++)
                        mma_f16(acc[fm][fn], af[fm], bf[fn]);
            }
        }
        __syncthreads();

#pragma unroll
        for (int fm = 0; fm < 2; fm++) {
#pragma unroll
            for (int half_ = 0; half_ < 2; half_++) {
                int lrow = wm * 32 + fm * 16 + gid + half_ * 8;
                int grow = bM + lrow;
                int inb = grow < M;
#pragma unroll
                for (int fn = 0; fn < 4; fn++) {
                    int col = wn * 32 + fn * 8 + tig * 2;
                    float v0 = silu(acc[fm][fn][half_*2+0] + bp[col]);
                    float v1 = silu(acc[fm][fn][half_*2+1] + bp[col+1]);
                    size_t base = (size_t)grow * HD + col;
                    if (s == 1 && inb) {
                        float2 av = *(const float2*)(XJI + base);
                        v0 += av.x; v1 += av.y;
                    } else if (s == 2) {
                        if (inb) {
                            float2 av = *(const float2*)(xa + base);
                            v0 += av.x; v1 += av.y;
                        }
                        skip[fm][fn][half_*2+0] = v0;
                        skip[fm][fn][half_*2+1] = v1;
                    } else if (s == 4) {
                        v0 += skip[fm][fn][half_*2+0];
                        v1 += skip[fm][fn][half_*2+1];
                        skip[fm][fn][half_*2+0] = v0;
                        skip[fm][fn][half_*2+1] = v1;
                    } else if (s == 6) {
                        v0 += skip[fm][fn][half_*2+0];
                        v1 += skip[fm][fn][half_*2+1];
                    }
                    if (s < 6) {
                        *(unsigned*)&Act[lrow][col] = packh2(v0, v1);
                    } else if (inb) {
                        *(float2*)(xb + base) = make_float2(v0, v1);
                        *(unsigned*)(xbh + base) = packh2(v0, v1);
                    }
                }
            }
        }
    }
}

// ---------------- embedding ----------------
__global__ void embed_fill_k(const int* __restrict__ z, const int* __restrict__ ei,
                             const int* __restrict__ ej, const float* __restrict__ rbf,
                             const float* __restrict__ emb_table,
                             const float* __restrict__ erw, const float* __restrict__ erb,
                             __half* __restrict__ Aemb)
{
    int e = blockIdx.x, h = threadIdx.x;
    int zi = z[ei[e]], zj = z[ej[e]];
    float s = erb[h];
    const float* rr = rbf + (size_t)e * NR;
#pragma unroll
    for (int r = 0; r < NR; r++) s += rr[r] * erw[r * HD + h];
    size_t base = (size_t)e * (3 * HD);
    Aemb[base + h]           = __float2half(emb_table[(size_t)zi * HD + h]);
    Aemb[base + HD + h]      = __float2half(emb_table[(size_t)zj * HD + h]);
    Aemb[base + 2 * HD + h]  = __float2half(silu(s));
}

// ---------------- sbf projection, ALL blocks ----------------
__global__ void sbfp_all_k(const float* __restrict__ sbf, const float* __restrict__ w,
                           float* __restrict__ outp)
{
    __shared__ float ws[NBLK * NSNR * NB];
    for (int idx = threadIdx.x; idx < NBLK * NSNR * NB; idx += blockDim.x) ws[idx] = w[idx];
    __syncthreads();
    int t = blockIdx.x * blockDim.x + threadIdx.x;
    if (t >= NTRIP) return;
    float sr[NSNR];
    const float* s = sbf + (size_t)t * NSNR;
#pragma unroll
    for (int r = 0; r < NSNR; r++) sr[r] = s[r];
    float* op = outp + (size_t)t * (NBLK * NB);
#pragma unroll
    for (int b = 0; b < NBLK; b++) {
        float acc[NB];
#pragma unroll
        for (int j = 0; j < NB; j++) acc[j] = 0.f;
        for (int r = 0; r < NSNR; r++) {
            float sv = sr[r];
#pragma unroll
            for (int j = 0; j < NB; j++) acc[j] += sv * ws[b * NSNR * NB + r * NB + j];
        }
#pragma unroll
        for (int j = 0; j < NB; j++) op[b * NB + j] = acc[j];
    }
}

// ---------------- CSR triplet gather: one warp per edge, no atomics ----------------
__global__ __launch_bounds__(256) void trip_csr_k(
    const __nv_bfloat16* __restrict__ Gh, const float* __restrict__ sbfp,
    const int* __restrict__ idx_kj, const int* __restrict__ off,
    const int* __restrict__ perm, float* __restrict__ Mo)
{
    int e = blockIdx.x * (blockDim.x >> 5) + (threadIdx.x >> 5);
    if (e >= NEDGES) return;
    int lane = threadIdx.x & 31;
    int s0 = off[e], s1 = off[e + 1];
    float4 acc = make_float4(0.f, 0.f, 0.f, 0.f);
    for (int idx = s0; idx < s1; idx++) {
        int w = perm[idx];
        int kj = idx_kj[w];
        float sv = (lane < NB) ? sbfp[(size_t)w * (NBLK * NB) + lane] : 0.f;
        const __nv_bfloat16* gr = Gh + (size_t)kj * (NB * HD) + lane * 4;
#pragma unroll
        for (int j = 0; j < NB; j++) {
            float s = __shfl_sync(0xffffffffu, sv, j);
            uint2 u = *(const uint2*)(gr + j * HD);
            __nv_bfloat162 p0 = *reinterpret_cast<__nv_bfloat162*>(&u.x);
            __nv_bfloat162 p1 = *reinterpret_cast<__nv_bfloat162*>(&u.y);
            float2 f0 = __bfloat1622float2(p0);
            float2 f1 = __bfloat1622float2(p1);
            acc.x += s * f0.x; acc.y += s * f0.y; acc.z += s * f1.x; acc.w += s * f1.y;
        }
    }
    float* mo = Mo + (size_t)e * HD + lane * 4;
    float4 old = *(const float4*)mo;
    old.x += acc.x; old.y += acc.y; old.z += acc.z; old.w += acc.w;
    *(float4*)mo = old;
}

// ---------------- batched out-block edge scatter ----------------
__global__ void edge_scatter7_k(const float* __restrict__ rbf, const float* __restrict__ orw,
                                const float* __restrict__ xsave, const int* __restrict__ ei,
                                float* __restrict__ atom)
{
    int e = blockIdx.x, k = blockIdx.y, h = threadIdx.x;
    const float* rr = rbf + (size_t)e * NR;
    const float* w = orw + (size_t)k * NR * HD;
    float rp = 0.f;
#pragma unroll
    for (int r = 0; r < NR; r++) rp += rr[r] * w[r * HD + h];
    float v = rp * xsave[(size_t)k * NEDGES * HD + (size_t)e * HD + h];
    atomicAdd(&atom[(size_t)k * NATOMS * HD + (size_t)ei[e] * HD + h], v);
}

// ---------------- batched final per-atom dot + graph segment sum ----------------
__global__ void dot7_k(const float* __restrict__ atom2, const float* __restrict__ ow,
                       const int* __restrict__ batch, float* __restrict__ out)
{
    int a = blockIdx.x * (blockDim.x >> 5) + (threadIdx.x >> 5);
    if (a >= NATOMS) return;
    int k = blockIdx.y;
    int lane = threadIdx.x & 31;
    const float* ar = atom2 + (size_t)k * NATOMS * HD + (size_t)a * HD + lane * 4;
    const float* wr = ow + (size_t)k * HD + lane * 4;
    float s = ar[0] * wr[0] + ar[1] * wr[1] + ar[2] * wr[2] + ar[3] * wr[3];
#pragma unroll
    for (int o = 16; o > 0; o >>= 1) s += __shfl_down_sync(0xffffffffu, s, o);
    if (lane == 0) atomicAdd(&out[batch[a]], s);
}

// ==========================================================================================
extern "C" void kernel_launch(void* const* d_in, const int* in_sizes, int n_in,
                              void* d_out, int out_size)
{
    const int*   z        = (const int*)  d_in[0];
    const float* rbf      = (const float*)d_in[1];
    const float* sbf      = (const float*)d_in[2];
    const int*   ei       = (const int*)  d_in[3];
    const int*   ej       = (const int*)  d_in[4];
    const int*   idx_kj   = (const int*)  d_in[5];
    const int*   idx_ji   = (const int*)  d_in[6];
    const int*   batch    = (const int*)  d_in[7];
    const float* emb_table= (const float*)d_in[8];
    const float* emb_rbf_w= (const float*)d_in[9];
    const float* emb_rbf_b= (const float*)d_in[10];
    const float* emb_w    = (const float*)d_in[11];
    const float* emb_b    = (const float*)d_in[12];
    const float* int_rbf_w= (const float*)d_in[13];
    const float* int_sbf_w= (const float*)d_in[14];
    const float* int_kj_w = (const float*)d_in[15];
    const float* int_kj_b = (const float*)d_in[16];
    const float* int_ji_w = (const float*)d_in[17];
    const float* int_ji_b = (const float*)d_in[18];
    const float* int_W    = (const float*)d_in[19];
    const float* int_bef_w= (const float*)d_in[20];
    const float* int_bef_b= (const float*)d_in[21];
    const float* int_lin_w= (const float*)d_in[22];
    const float* int_lin_b= (const float*)d_in[23];
    const float* int_aft_w= (const float*)d_in[24];
    const float* int_aft_b= (const float*)d_in[25];
    const float* out_rbf_w= (const float*)d_in[26];
    const float* out_lins_w=(const float*)d_in[27];
    const float* out_lins_b=(const float*)d_in[28];
    const float* out_w    = (const float*)d_in[29];
    float* out = (float*)d_out;

    float *XSAVE, *XJI, *SBFP, *ATOM7, *ATOM7B;
    __half *XSH, *XKJh, *AEMBh, *ATOMH, *ATOMH2, *WH;
    __nv_bfloat16* Gh;
    int *CNT, *OFF, *POS, *PERM;
    cudaGetSymbolAddress((void**)&XSAVE, g_XSAVE);
    cudaGetSymbolAddress((void**)&XSH,   g_XSH);
    cudaGetSymbolAddress((void**)&XJI,   g_XJI);
    cudaGetSymbolAddress((void**)&XKJh,  g_XKJh);
    cudaGetSymbolAddress((void**)&SBFP,  g_SBFP);
    cudaGetSymbolAddress((void**)&AEMBh, g_AEMBh);
    cudaGetSymbolAddress((void**)&Gh,    g_Gh);
    cudaGetSymbolAddress((void**)&ATOM7, g_ATOM7);
    cudaGetSymbolAddress((void**)&ATOM7B,g_ATOM7B);
    cudaGetSymbolAddress((void**)&ATOMH, g_ATOMH);
    cudaGetSymbolAddress((void**)&ATOMH2,g_ATOMH2);
    cudaGetSymbolAddress((void**)&WH,    g_WH);
    cudaGetSymbolAddress((void**)&CNT,   g_CNT);
    cudaGetSymbolAddress((void**)&OFF,   g_OFF);
    cudaGetSymbolAddress((void**)&POS,   g_POS);
    cudaGetSymbolAddress((void**)&PERM,  g_PERM);

    const dim3 gE(1, (NEDGES + 127) / 128);
    const dim3 gEG(NB, (NEDGES + 127) / 128);
    const dim3 gA7(1, (NATOMS + 127) / 128, 7);
    const size_t EH = (size_t)NEDGES * HD;
    const size_t AH7 = (size_t)NATOMS * HD;

    cudaMemsetAsync(out, 0, NGRAPHS * sizeof(float));
    cudaMemsetAsync(ATOM7, 0, (size_t)7 * AH7 * sizeof(float));
    cudaMemsetAsync(CNT, 0, NEDGES * sizeof(int));
    cudaMemsetAsync(POS, 0, NEDGES * sizeof(int));

    // ---- CSR build (once per launch) ----
    count_k<<<(NTRIP + 255) / 256, 256>>>(idx_ji, CNT);
    scan_k<<<1, 1024>>>(CNT, OFF);
    place_k<<<(NTRIP + 255) / 256, 256>>>(idx_ji, OFF, POS, PERM);

    auto cw = [&](const float* src, __half* dst, int K, int N, int cnt) {
        long total = (long)cnt * K * N;
        convw_k<<<(unsigned)((total + 255) / 256), 256>>>(src, dst, K, N, total);
    };
    cw(emb_w,      WH + WH_EMB, 3 * HD, HD, 1);
    cw(int_ji_w,   WH + WH_JI,  HD, HD, NBLK);
    cw(int_kj_w,   WH + WH_KJ,  HD, HD, NBLK);
    cw(int_bef_w,  WH + WH_BEF, HD, HD, NBLK * 2);
    cw(int_lin_w,  WH + WH_LIN, HD, HD, NBLK);
    cw(int_aft_w,  WH + WH_AFT, HD, HD, NBLK * 4);
    cw(out_lins_w, WH + WH_OUT, HD, HD, 7 * 3);
    convg_k<<<(NBLK * NB * HD * HD) / 256, 256>>>(int_W, WH + WH_G);

    sbfp_all_k<<<(NTRIP + 127) / 128, 128>>>(sbf, int_sbf_w, SBFP);

    // ---- embedding block -> XSAVE[0] (f32) + XSH[0] (half) ----
    embed_fill_k<<<NEDGES, HD>>>(z, ei, ej, rbf, emb_table, emb_rbf_w, emb_rbf_b, AEMBh);
    gemm_h<<<gE, 256>>>(AEMBh, 1, WH + WH_EMB, emb_b, nullptr, nullptr, nullptr,
                        XSAVE, XSH, nullptr, NEDGES, HD, 3 * HD, 1, 0, 0, 0, 0);

    for (int b = 0; b < NBLK; b++) {
        float*  xa  = XSAVE + (size_t)b * EH;
        float*  xb  = XSAVE + (size_t)(b + 1) * EH;
        __half* xah = XSH   + (size_t)b * EH;
        __half* xbh = XSH   + (size_t)(b + 1) * EH;

        gemm_h<<<gE, 256>>>(xah, 1, WH + WH_JI + (size_t)b * HDHD,
                            int_ji_b + (size_t)b * HD, nullptr, nullptr, nullptr,
                            XJI, nullptr, nullptr, NEDGES, HD, HD, 1, 0, 0, 0, 0);
        gemm_h<<<gE, 256>>>(xah, 1, WH + WH_KJ + (size_t)b * HDHD,
                            int_kj_b + (size_t)b * HD, nullptr,
                            rbf, int_rbf_w + (size_t)b * NR * HD,
                            nullptr, XKJh, nullptr, NEDGES, HD, HD, 1, 0, 0, 0, 0);
        gemm_h<<<gEG, 256>>>(XKJh, 1, WH + WH_G + (size_t)b * NB * HDHD,
                             nullptr, nullptr, nullptr, nullptr,
                             nullptr, nullptr, Gh, NEDGES, NB * HD, HD, 0, 0, 0, 0, 0);

        trip_csr_k<<<(NEDGES + 7) / 8, 256>>>(Gh, SBFP + (size_t)b * NB,
                                              idx_kj, OFF, PERM, XJI);

        chain_k<<<(NEDGES + 63) / 64, 256>>>(
            XJI, xa,
            WH + WH_BEF + (size_t)b * 2 * HDHD,
            WH + WH_LIN + (size_t)b * HDHD,
            WH + WH_AFT + (size_t)b * 4 * HDHD,
            int_bef_b + (size_t)b * 2 * HD,
            int_lin_b + (size_t)b * HD,
            int_aft_b + (size_t)b * 4 * HD,
            xb, xbh, NEDGES);
    }

    // ---- all 7 out_blocks, batched at the end ----
    edge_scatter7_k<<<dim3(NEDGES, 7), HD>>>(rbf, out_rbf_w, XSAVE, ei, ATOM7);
    gemm_h<<<gA7, 256>>>(ATOM7, 0, WH + WH_OUT + 0 * HDHD, out_lins_b + 0 * HD,
                         nullptr, nullptr, nullptr, nullptr, ATOMH, nullptr,
                         NATOMS, HD, HD, 1, AH7, (size_t)3 * HDHD, (size_t)3 * HD, AH7);
    gemm_h<<<gA7, 256>>>(ATOMH, 1, WH + WH_OUT + 1 * HDHD, out_lins_b + 1 * HD,
                         nullptr, nullptr, nullptr, nullptr, ATOMH2, nullptr,
                         NATOMS, HD, HD, 1, AH7, (size_t)3 * HDHD, (size_t)3 * HD, AH7);
    gemm_h<<<gA7, 256>>>(ATOMH2, 1, WH + WH_OUT + 2 * HDHD, out_lins_b + 2 * HD,
                         nullptr, nullptr, nullptr, ATOM7B, nullptr, nullptr,
                         NATOMS, HD, HD, 1, AH7, (size_t)3 * HDHD, (size_t)3 * HD, AH7);
    dot7_k<<<dim3((NATOMS + 7) / 8, 7), 256>>>(ATOM7B, out_w, batch, out);
}

// round 13
// speedup vs baseline: 1.4099x; 1.0186x over previous
#include <cuda_runtime.h>
#include <cuda_fp16.h>
#include <cuda_bf16.h>
#include <math.h>

#define NATOMS 8000
#define NEDGES 100000
#define NTRIP  500000
#define NGRAPHS 64
#define HD 128
#define NR 6
#define NSNR 42
#define NB 8
#define NBLK 6
#define HDHD (HD*HD)

// ---------------- device scratch (no allocation allowed) ----------------
__device__ float  g_XSAVE[(size_t)(NBLK + 1) * NEDGES * HD];   // f32 x per block
__device__ __half g_XSH  [(size_t)(NBLK + 1) * NEDGES * HD];   // half mirror of x
__device__ float  g_XJI [NEDGES*HD];
__device__ __half g_XKJh[NEDGES*HD];
__device__ float  g_SBFP[(size_t)NTRIP*NBLK*NB];
__device__ __half g_AEMBh[(size_t)NEDGES*3*HD];                // embed input [E,384] half
__device__ __nv_bfloat16 g_Gh[(size_t)NEDGES*NB*HD];           // G in bf16
__device__ float  g_ATOM7 [(size_t)7*NATOMS*HD];
__device__ float  g_ATOM7B[(size_t)7*NATOMS*HD];
__device__ __half g_ATOMH [(size_t)7*NATOMS*HD];
__device__ __half g_ATOMH2[(size_t)7*NATOMS*HD];
// CSR of triplets by idx_kj
__device__ int    g_CNT [NEDGES];
__device__ int    g_OFF [NEDGES + 1];
__device__ int    g_POS [NEDGES];
__device__ int    g_PERM[NTRIP];

// half weight copies, transposed to [N][K]
#define WH_EMB  0
#define WH_JI   (WH_EMB + 3*HDHD)
#define WH_KJ   (WH_JI  + NBLK*HDHD)
#define WH_BEF  (WH_KJ  + NBLK*HDHD)
#define WH_LIN  (WH_BEF + NBLK*2*HDHD)
#define WH_AFT  (WH_LIN + NBLK*HDHD)
#define WH_OUT  (WH_AFT + NBLK*4*HDHD)
#define WH_G    (WH_OUT + 7*3*HDHD)
#define WH_TOTAL (WH_G + NBLK*NB*HDHD)
__device__ __half g_WH[WH_TOTAL];

__device__ __forceinline__ float silu(float x) { return x / (1.0f + expf(-x)); }

__device__ __forceinline__ unsigned packh2(float a, float b) {
    __half2 h = __floats2half2_rn(a, b);
    return *reinterpret_cast<unsigned*>(&h);
}

__device__ __forceinline__ void mma_f16(float* c, const unsigned* a, const unsigned* b) {
    asm volatile(
        "mma.sync.aligned.m16n8k16.row.col.f32.f16.f16.f32 "
        "{%0,%1,%2,%3}, {%4,%5,%6,%7}, {%8,%9}, {%0,%1,%2,%3};"
        : "+f"(c[0]), "+f"(c[1]), "+f"(c[2]), "+f"(c[3])
        : "r"(a[0]), "r"(a[1]), "r"(a[2]), "r"(a[3]),
          "r"(b[0]), "r"(b[1]));
}

__device__ __forceinline__ void cp16(unsigned saddr, const void* g, int bytes) {
    asm volatile("cp.async.cg.shared.global [%0], [%1], 16, %2;"
                 :: "r"(saddr), "l"(g), "r"(bytes) : "memory");
}

__device__ __forceinline__ void ldsm4(unsigned& r0, unsigned& r1, unsigned& r2, unsigned& r3,
                                      const __half* p) {
    unsigned addr = (unsigned)__cvta_generic_to_shared(p);
    asm volatile("ldmatrix.sync.aligned.m8n8.x4.shared.b16 {%0,%1,%2,%3}, [%4];"
                 : "=r"(r0), "=r"(r1), "=r"(r2), "=r"(r3) : "r"(addr));
}

// ---------------- weight convert: dst[m][n][k] = half(src[m][k][n]) ----------------
__global__ void convw_k(const float* __restrict__ src, __half* __restrict__ dst,
                        int K, int N, long total)
{
    long idx = (long)blockIdx.x * blockDim.x + threadIdx.x;
    if (idx >= total) return;
    long per = (long)K * N;
    long m = idx / per, r = idx % per;
    int n = (int)(r / K), k = (int)(r % K);
    dst[idx] = __float2half(src[m * per + (size_t)k * N + n]);
}

// ---------------- G weight convert ----------------
__global__ void convg_k(const float* __restrict__ W, __half* __restrict__ dst)
{
    int idx = blockIdx.x * blockDim.x + threadIdx.x;     // 6*131072
    int b = idx >> 17;
    int r = idx & 131071;
    int n = r >> 7, l = r & 127;
    int j = n >> 7, i = n & 127;
    dst[idx] = __float2half(W[(size_t)b * 131072 + (size_t)i * 1024 + j * 128 + l]);
}

// ---------------- CSR build: count / scan / place (keyed on idx_kj) ----------------
__global__ void count_k(const int* __restrict__ key, int* __restrict__ cnt)
{
    int w = blockIdx.x * blockDim.x + threadIdx.x;
    if (w < NTRIP) atomicAdd(&cnt[key[w]], 1);
}

__global__ void scan_k(const int* __restrict__ cnt, int* __restrict__ off)
{
    __shared__ int buf[1024];
    __shared__ int carry;
    if (threadIdx.x == 0) carry = 0;
    __syncthreads();
    for (int base = 0; base < NEDGES; base += 1024) {
        int i = base + threadIdx.x;
        int v = (i < NEDGES) ? cnt[i] : 0;
        buf[threadIdx.x] = v;
        __syncthreads();
        for (int d = 1; d < 1024; d <<= 1) {
            int t = (threadIdx.x >= d) ? buf[threadIdx.x - d] : 0;
            __syncthreads();
            buf[threadIdx.x] += t;
            __syncthreads();
        }
        if (i < NEDGES) off[i] = carry + buf[threadIdx.x] - v;
        int total = buf[1023];
        __syncthreads();
        if (threadIdx.x == 0) carry += total;
        __syncthreads();
    }
    if (threadIdx.x == 0) off[NEDGES] = carry;
}

__global__ void place_k(const int* __restrict__ key, const int* __restrict__ off,
                        int* __restrict__ pos, int* __restrict__ perm)
{
    int w = blockIdx.x * blockDim.x + threadIdx.x;
    if (w >= NTRIP) return;
    int e = key[w];
    int p = off[e] + atomicAdd(&pos[e], 1);
    perm[p] = w;
}

// ---------------- fp16 tensor-core GEMM ----------------
#define AST 72   // halfs per smem row
__global__ __launch_bounds__(256, 2) void gemm_h(
    const void* __restrict__ Av, int aHalf, const __half* __restrict__ Bh,
    const float* __restrict__ bias, const float* __restrict__ addv,
    const float* __restrict__ rbfv, const float* __restrict__ rbfw,
    float* __restrict__ Cf, __half* __restrict__ Chh, __nv_bfloat16* __restrict__ Cbf,
    int M, int N, int K, int act,
    size_t aZ, size_t bZ, size_t biasZ, size_t cZ)
{
    __shared__ __half As[128][AST];
    __shared__ __half Bs[128][AST];

    const float* Af = (const float*)Av + blockIdx.z * aZ;
    const __half* Ah = (const __half*)Av + blockIdx.z * aZ;
    Bh += blockIdx.z * bZ;
    if (bias) bias += blockIdx.z * biasZ;

    const int tid = threadIdx.x;
    const int bM = blockIdx.y * 128;
    const int bN = blockIdx.x * 128;
    const int lane = tid & 31, warp = tid >> 5;
    const int gid = lane >> 2, tig = lane & 3;
    const int wm = warp >> 2, wn = warp & 3;

    const int aRowO = (lane & 7) + ((lane >> 3) & 1) * 8;
    const int aColO = ((lane >> 4) & 1) * 8;
    const int bRowO = (lane & 7) + ((lane >> 4) & 1) * 8;
    const int bColO = ((lane >> 3) & 1) * 8;

    float c[4][4][4];
#pragma unroll
    for (int i = 0; i < 4; i++)
#pragma unroll
        for (int j = 0; j < 4; j++)
#pragma unroll
            for (int q = 0; q < 4; q++) c[i][j][q] = 0.f;

    unsigned sA = (unsigned)__cvta_generic_to_shared(&As[0][0]);
    unsigned sB = (unsigned)__cvta_generic_to_shared(&Bs[0][0]);

    for (int kc = 0; kc < K; kc += 64) {
        if (kc) __syncthreads();

#pragma unroll
        for (int it = 0; it < 4; it++) {
            int f = it * 256 + tid;
            int row = f >> 3, c8 = (f & 7) * 8;
            cp16(sB + (row * AST + c8) * 2,
                 Bh + (size_t)(bN + row) * K + kc + c8, 16);
        }
        if (aHalf) {
#pragma unroll
            for (int it = 0; it < 4; it++) {
                int f = it * 256 + tid;
                int row = f >> 3, c8 = (f & 7) * 8;
                cp16(sA + (row * AST + c8) * 2,
                     Ah + (size_t)(bM + row) * K + kc + c8,
                     (bM + row) < M ? 16 : 0);
            }
        } else {
#pragma unroll
            for (int it = 0; it < 8; it++) {
                int f = it * 256 + tid;
                int row = f >> 4, c4 = (f & 15) * 4;
                float4 v = make_float4(0.f, 0.f, 0.f, 0.f);
                if (bM + row < M)
                    v = *(const float4*)(Af + (size_t)(bM + row) * K + kc + c4);
                *(uint2*)&As[row][c4] = make_uint2(packh2(v.x, v.y), packh2(v.z, v.w));
            }
        }
        asm volatile("cp.async.commit_group;" ::: "memory");
        asm volatile("cp.async.wait_group 0;" ::: "memory");
        __syncthreads();

#pragma unroll
        for (int kk = 0; kk < 64; kk += 16) {
            unsigned af[4][4], bf[4][2];
#pragma unroll
            for (int fm = 0; fm < 4; fm++) {
                int m0 = wm * 64 + fm * 16;
                ldsm4(af[fm][0], af[fm][1], af[fm][2], af[fm][3],
                      &As[m0 + aRowO][kk + aColO]);
            }
#pragma unroll
            for (int p = 0; p < 2; p++) {
                int n0 = wn * 32 + p * 16;
                ldsm4(bf[2 * p][0], bf[2 * p][1], bf[2 * p + 1][0], bf[2 * p + 1][1],
                      &Bs[n0 + bRowO][kk + bColO]);
            }
#pragma unroll
            for (int fm = 0; fm < 4; fm++)
#pragma unroll
                for (int fn = 0; fn < 4; fn++)
                    mma_f16(c[fm][fn], af[fm], bf[fn]);
        }
    }

    if (Cf)  Cf  += blockIdx.z * cZ;
    if (Chh) Chh += blockIdx.z * cZ;

#pragma unroll
    for (int fm = 0; fm < 4; fm++) {
#pragma unroll
        for (int half_ = 0; half_ < 2; half_++) {
            int row = bM + wm * 64 + fm * 16 + gid + half_ * 8;
            if (row >= M) continue;
            float rr[NR];
            if (rbfv) {
#pragma unroll
                for (int r = 0; r < NR; r++) rr[r] = rbfv[(size_t)row * NR + r];
            }
#pragma unroll
            for (int fn = 0; fn < 4; fn++) {
                int col = bN + wn * 32 + fn * 8 + tig * 2;
                float v0 = c[fm][fn][half_ * 2 + 0] + (bias ? bias[col] : 0.f);
                float v1 = c[fm][fn][half_ * 2 + 1] + (bias ? bias[col + 1] : 0.f);
                if (act) { v0 = silu(v0); v1 = silu(v1); }
                size_t base = (size_t)row * N + col;
                if (rbfv) {
                    float rp0 = 0.f, rp1 = 0.f;
#pragma unroll
                    for (int r = 0; r < NR; r++) {
                        rp0 += rr[r] * rbfw[r * HD + col];
                        rp1 += rr[r] * rbfw[r * HD + col + 1];
                    }
                    v0 *= rp0; v1 *= rp1;
                }
                if (addv) {
                    float2 av = *(const float2*)(addv + base);
                    v0 += av.x; v1 += av.y;
                }
                if (Cf)  *(float2*)(Cf + base) = make_float2(v0, v1);
                if (Chh) *(unsigned*)(Chh + base) = packh2(v0, v1);
                if (Cbf) *(__nv_bfloat162*)(Cbf + base) =
                             __float22bfloat162_rn(make_float2(v0, v1));
            }
        }
    }
}

// ---------------- fused 7-layer residual chain ----------------
#define CST 136
__global__ __launch_bounds__(256) void chain_k(
    const float* __restrict__ XJI, const float* __restrict__ xa,
    const __half* __restrict__ Wbef, const __half* __restrict__ Wlin,
    const __half* __restrict__ Waft,
    const float* __restrict__ bbef, const float* __restrict__ blin,
    const float* __restrict__ baft,
    float* __restrict__ xb, __half* __restrict__ xbh, int M)
{
    __shared__ __half Act[64][CST];
    __shared__ __half Wb[128][AST];

    const int tid = threadIdx.x;
    const int bM = blockIdx.x * 64;
    const int lane = tid & 31, warp = tid >> 5;
    const int gid = lane >> 2, tig = lane & 3;
    const int wm = warp >> 2, wn = warp & 3;

    const int aRowO = (lane & 7) + ((lane >> 3) & 1) * 8;
    const int aColO = ((lane >> 4) & 1) * 8;
    const int bRowO = (lane & 7) + ((lane >> 4) & 1) * 8;
    const int bColO = ((lane >> 3) & 1) * 8;

    unsigned sW = (unsigned)__cvta_generic_to_shared(&Wb[0][0]);

#pragma unroll
    for (int it = 0; it < 8; it++) {
        int f = it * 256 + tid;
        int row = f >> 5, c4 = (f & 31) * 4;
        float4 v = make_float4(0.f, 0.f, 0.f, 0.f);
        if (bM + row < M)
            v = *(const float4*)(XJI + (size_t)(bM + row) * HD + c4);
        *(uint2*)&Act[row][c4] = make_uint2(packh2(v.x, v.y), packh2(v.z, v.w));
    }

    float skip[2][4][4];

    for (int s = 0; s < 7; s++) {
        const __half* Wp;
        const float* bp;
        if (s == 0)      { Wp = Wbef;              bp = bbef; }
        else if (s == 1) { Wp = Wbef + HDHD;       bp = bbef + HD; }
        else if (s == 2) { Wp = Wlin;              bp = blin; }
        else             { Wp = Waft + (s-3)*HDHD; bp = baft + (s-3)*HD; }

        float acc[2][4][4];
#pragma unroll
        for (int i = 0; i < 2; i++)
#pragma unroll
            for (int j = 0; j < 4; j++)
#pragma unroll
                for (int q = 0; q < 4; q++) acc[i][j][q] = 0.f;

        for (int kc = 0; kc < HD; kc += 64) {
            __syncthreads();
#pragma unroll
            for (int it = 0; it < 4; it++) {
                int f = it * 256 + tid;
                int row = f >> 3, c8 = (f & 7) * 8;
                cp16(sW + (row * AST + c8) * 2, Wp + (size_t)row * HD + kc + c8, 16);
            }
            asm volatile("cp.async.commit_group;" ::: "memory");
            asm volatile("cp.async.wait_group 0;" ::: "memory");
            __syncthreads();

#pragma unroll
            for (int kk = 0; kk < 64; kk += 16) {
                unsigned af[2][4], bf[4][2];
#pragma unroll
                for (int fm = 0; fm < 2; fm++) {
                    int m0 = wm * 32 + fm * 16;
                    ldsm4(af[fm][0], af[fm][1], af[fm][2], af[fm][3],
                          &Act[m0 + aRowO][kc + kk + aColO]);
                }
#pragma unroll
                for (int p = 0; p < 2; p++) {
                    int n0 = wn * 32 + p * 16;
                    ldsm4(bf[2*p][0], bf[2*p][1], bf[2*p+1][0], bf[2*p+1][1],
                          &Wb[n0 + bRowO][kk + bColO]);
                }
#pragma unroll
                for (int fm = 0; fm < 2; fm++)
#pragma unroll
                    for (int fn = 0; fn < 4; fn++)
                        mma_f16(acc[fm][fn], af[fm], bf[fn]);
            }
        }
        __syncthreads();

#pragma unroll
        for (int fm = 0; fm < 2; fm++) {
#pragma unroll
            for (int half_ = 0; half_ < 2; half_++) {
                int lrow = wm * 32 + fm * 16 + gid + half_ * 8;
                int grow = bM + lrow;
                int inb = grow < M;
#pragma unroll
                for (int fn = 0; fn < 4; fn++) {
                    int col = wn * 32 + fn * 8 + tig * 2;
                    float v0 = silu(acc[fm][fn][half_*2+0] + bp[col]);
                    float v1 = silu(acc[fm][fn][half_*2+1] + bp[col+1]);
                    size_t base = (size_t)grow * HD + col;
                    if (s == 1 && inb) {
                        float2 av = *(const float2*)(XJI + base);
                        v0 += av.x; v1 += av.y;
                    } else if (s == 2) {
                        if (inb) {
                            float2 av = *(const float2*)(xa + base);
                            v0 += av.x; v1 += av.y;
                        }
                        skip[fm][fn][half_*2+0] = v0;
                        skip[fm][fn][half_*2+1] = v1;
                    } else if (s == 4) {
                        v0 += skip[fm][fn][half_*2+0];
                        v1 += skip[fm][fn][half_*2+1];
                        skip[fm][fn][half_*2+0] = v0;
                        skip[fm][fn][half_*2+1] = v1;
                    } else if (s == 6) {
                        v0 += skip[fm][fn][half_*2+0];
                        v1 += skip[fm][fn][half_*2+1];
                    }
                    if (s < 6) {
                        *(unsigned*)&Act[lrow][col] = packh2(v0, v1);
                    } else if (inb) {
                        *(float2*)(xb + base) = make_float2(v0, v1);
                        *(unsigned*)(xbh + base) = packh2(v0, v1);
                    }
                }
            }
        }
    }
}

// ---------------- embedding ----------------
__global__ void embed_fill_k(const int* __restrict__ z, const int* __restrict__ ei,
                             const int* __restrict__ ej, const float* __restrict__ rbf,
                             const float* __restrict__ emb_table,
                             const float* __restrict__ erw, const float* __restrict__ erb,
                             __half* __restrict__ Aemb)
{
    int e = blockIdx.x, h = threadIdx.x;
    int zi = z[ei[e]], zj = z[ej[e]];
    float s = erb[h];
    const float* rr = rbf + (size_t)e * NR;
#pragma unroll
    for (int r = 0; r < NR; r++) s += rr[r] * erw[r * HD + h];
    size_t base = (size_t)e * (3 * HD);
    Aemb[base + h]           = __float2half(emb_table[(size_t)zi * HD + h]);
    Aemb[base + HD + h]      = __float2half(emb_table[(size_t)zj * HD + h]);
    Aemb[base + 2 * HD + h]  = __float2half(silu(s));
}

// ---------------- sbf projection, ALL blocks ----------------
__global__ void sbfp_all_k(const float* __restrict__ sbf, const float* __restrict__ w,
                           float* __restrict__ outp)
{
    __shared__ float ws[NBLK * NSNR * NB];
    for (int idx = threadIdx.x; idx < NBLK * NSNR * NB; idx += blockDim.x) ws[idx] = w[idx];
    __syncthreads();
    int t = blockIdx.x * blockDim.x + threadIdx.x;
    if (t >= NTRIP) return;
    float sr[NSNR];
    const float* s = sbf + (size_t)t * NSNR;
#pragma unroll
    for (int r = 0; r < NSNR; r++) sr[r] = s[r];
    float* op = outp + (size_t)t * (NBLK * NB);
#pragma unroll
    for (int b = 0; b < NBLK; b++) {
        float acc[NB];
#pragma unroll
        for (int j = 0; j < NB; j++) acc[j] = 0.f;
        for (int r = 0; r < NSNR; r++) {
            float sv = sr[r];
#pragma unroll
            for (int j = 0; j < NB; j++) acc[j] += sv * ws[b * NSNR * NB + r * NB + j];
        }
#pragma unroll
        for (int j = 0; j < NB; j++) op[b * NB + j] = acc[j];
    }
}

// ---------------- CSR-by-kj triplet scatter: warp owns source edge, G read once ------
__global__ __launch_bounds__(256) void trip_kj_k(
    const __nv_bfloat16* __restrict__ Gh, const float* __restrict__ sbfp,
    const int* __restrict__ idx_ji, const int* __restrict__ off,
    const int* __restrict__ perm, float* __restrict__ Mo)
{
    int e = blockIdx.x * (blockDim.x >> 5) + (threadIdx.x >> 5);
    if (e >= NEDGES) return;
    int lane = threadIdx.x & 31;
    int s0 = off[e], s1 = off[e + 1];
    if (s0 == s1) return;

    // load G[e, :, lane*4 .. +3] once: 8 j rows
    float f[NB][4];
    const __nv_bfloat16* gr = Gh + (size_t)e * (NB * HD) + lane * 4;
#pragma unroll
    for (int j = 0; j < NB; j++) {
        uint2 u = *(const uint2*)(gr + j * HD);
        __nv_bfloat162 p0 = *reinterpret_cast<__nv_bfloat162*>(&u.x);
        __nv_bfloat162 p1 = *reinterpret_cast<__nv_bfloat162*>(&u.y);
        float2 a = __bfloat1622float2(p0);
        float2 b = __bfloat1622float2(p1);
        f[j][0] = a.x; f[j][1] = a.y; f[j][2] = b.x; f[j][3] = b.y;
    }

    for (int idx = s0; idx < s1; idx++) {
        int w = perm[idx];
        int ji = idx_ji[w];
        float sv = (lane < NB) ? sbfp[(size_t)w * (NBLK * NB) + lane] : 0.f;
        float4 acc = make_float4(0.f, 0.f, 0.f, 0.f);
#pragma unroll
        for (int j = 0; j < NB; j++) {
            float s = __shfl_sync(0xffffffffu, sv, j);
            acc.x += s * f[j][0]; acc.y += s * f[j][1];
            acc.z += s * f[j][2]; acc.w += s * f[j][3];
        }
        float* mo = Mo + (size_t)ji * HD + lane * 4;
        atomicAdd(mo + 0, acc.x);
        atomicAdd(mo + 1, acc.y);
        atomicAdd(mo + 2, acc.z);
        atomicAdd(mo + 3, acc.w);
    }
}

// ---------------- batched out-block edge scatter ----------------
__global__ void edge_scatter7_k(const float* __restrict__ rbf, const float* __restrict__ orw,
                                const float* __restrict__ xsave, const int* __restrict__ ei,
                                float* __restrict__ atom)
{
    int e = blockIdx.x, k = blockIdx.y, h = threadIdx.x;
    const float* rr = rbf + (size_t)e * NR;
    const float* w = orw + (size_t)k * NR * HD;
    float rp = 0.f;
#pragma unroll
    for (int r = 0; r < NR; r++) rp += rr[r] * w[r * HD + h];
    float v = rp * xsave[(size_t)k * NEDGES * HD + (size_t)e * HD + h];
    atomicAdd(&atom[(size_t)k * NATOMS * HD + (size_t)ei[e] * HD + h], v);
}

// ---------------- batched final per-atom dot + graph segment sum ----------------
__global__ void dot7_k(const float* __restrict__ atom2, const float* __restrict__ ow,
                       const int* __restrict__ batch, float* __restrict__ out)
{
    int a = blockIdx.x * (blockDim.x >> 5) + (threadIdx.x >> 5);
    if (a >= NATOMS) return;
    int k = blockIdx.y;
    int lane = threadIdx.x & 31;
    const float* ar = atom2 + (size_t)k * NATOMS * HD + (size_t)a * HD + lane * 4;
    const float* wr = ow + (size_t)k * HD + lane * 4;
    float s = ar[0] * wr[0] + ar[1] * wr[1] + ar[2] * wr[2] + ar[3] * wr[3];
#pragma unroll
    for (int o = 16; o > 0; o >>= 1) s += __shfl_down_sync(0xffffffffu, s, o);
    if (lane == 0) atomicAdd(&out[batch[a]], s);
}

// ==========================================================================================
extern "C" void kernel_launch(void* const* d_in, const int* in_sizes, int n_in,
                              void* d_out, int out_size)
{
    const int*   z        = (const int*)  d_in[0];
    const float* rbf      = (const float*)d_in[1];
    const float* sbf      = (const float*)d_in[2];
    const int*   ei       = (const int*)  d_in[3];
    const int*   ej       = (const int*)  d_in[4];
    const int*   idx_kj   = (const int*)  d_in[5];
    const int*   idx_ji   = (const int*)  d_in[6];
    const int*   batch    = (const int*)  d_in[7];
    const float* emb_table= (const float*)d_in[8];
    const float* emb_rbf_w= (const float*)d_in[9];
    const float* emb_rbf_b= (const float*)d_in[10];
    const float* emb_w    = (const float*)d_in[11];
    const float* emb_b    = (const float*)d_in[12];
    const float* int_rbf_w= (const float*)d_in[13];
    const float* int_sbf_w= (const float*)d_in[14];
    const float* int_kj_w = (const float*)d_in[15];
    const float* int_kj_b = (const float*)d_in[16];
    const float* int_ji_w = (const float*)d_in[17];
    const float* int_ji_b = (const float*)d_in[18];
    const float* int_W    = (const float*)d_in[19];
    const float* int_bef_w= (const float*)d_in[20];
    const float* int_bef_b= (const float*)d_in[21];
    const float* int_lin_w= (const float*)d_in[22];
    const float* int_lin_b= (const float*)d_in[23];
    const float* int_aft_w= (const float*)d_in[24];
    const float* int_aft_b= (const float*)d_in[25];
    const float* out_rbf_w= (const float*)d_in[26];
    const float* out_lins_w=(const float*)d_in[27];
    const float* out_lins_b=(const float*)d_in[28];
    const float* out_w    = (const float*)d_in[29];
    float* out = (float*)d_out;

    float *XSAVE, *XJI, *SBFP, *ATOM7, *ATOM7B;
    __half *XSH, *XKJh, *AEMBh, *ATOMH, *ATOMH2, *WH;
    __nv_bfloat16* Gh;
    int *CNT, *OFF, *POS, *PERM;
    cudaGetSymbolAddress((void**)&XSAVE, g_XSAVE);
    cudaGetSymbolAddress((void**)&XSH,   g_XSH);
    cudaGetSymbolAddress((void**)&XJI,   g_XJI);
    cudaGetSymbolAddress((void**)&XKJh,  g_XKJh);
    cudaGetSymbolAddress((void**)&SBFP,  g_SBFP);
    cudaGetSymbolAddress((void**)&AEMBh, g_AEMBh);
    cudaGetSymbolAddress((void**)&Gh,    g_Gh);
    cudaGetSymbolAddress((void**)&ATOM7, g_ATOM7);
    cudaGetSymbolAddress((void**)&ATOM7B,g_ATOM7B);
    cudaGetSymbolAddress((void**)&ATOMH, g_ATOMH);
    cudaGetSymbolAddress((void**)&ATOMH2,g_ATOMH2);
    cudaGetSymbolAddress((void**)&WH,    g_WH);
    cudaGetSymbolAddress((void**)&CNT,   g_CNT);
    cudaGetSymbolAddress((void**)&OFF,   g_OFF);
    cudaGetSymbolAddress((void**)&POS,   g_POS);
    cudaGetSymbolAddress((void**)&PERM,  g_PERM);

    const dim3 gE(1, (NEDGES + 127) / 128);
    const dim3 gEG(NB, (NEDGES + 127) / 128);
    const dim3 gA7(1, (NATOMS + 127) / 128, 7);
    const size_t EH = (size_t)NEDGES * HD;
    const size_t AH7 = (size_t)NATOMS * HD;

    cudaMemsetAsync(out, 0, NGRAPHS * sizeof(float));
    cudaMemsetAsync(ATOM7, 0, (size_t)7 * AH7 * sizeof(float));
    cudaMemsetAsync(CNT, 0, NEDGES * sizeof(int));
    cudaMemsetAsync(POS, 0, NEDGES * sizeof(int));

    // ---- CSR build by idx_kj (once per launch) ----
    count_k<<<(NTRIP + 255) / 256, 256>>>(idx_kj, CNT);
    scan_k<<<1, 1024>>>(CNT, OFF);
    place_k<<<(NTRIP + 255) / 256, 256>>>(idx_kj, OFF, POS, PERM);

    auto cw = [&](const float* src, __half* dst, int K, int N, int cnt) {
        long total = (long)cnt * K * N;
        convw_k<<<(unsigned)((total + 255) / 256), 256>>>(src, dst, K, N, total);
    };
    cw(emb_w,      WH + WH_EMB, 3 * HD, HD, 1);
    cw(int_ji_w,   WH + WH_JI,  HD, HD, NBLK);
    cw(int_kj_w,   WH + WH_KJ,  HD, HD, NBLK);
    cw(int_bef_w,  WH + WH_BEF, HD, HD, NBLK * 2);
    cw(int_lin_w,  WH + WH_LIN, HD, HD, NBLK);
    cw(int_aft_w,  WH + WH_AFT, HD, HD, NBLK * 4);
    cw(out_lins_w, WH + WH_OUT, HD, HD, 7 * 3);
    convg_k<<<(NBLK * NB * HD * HD) / 256, 256>>>(int_W, WH + WH_G);

    sbfp_all_k<<<(NTRIP + 127) / 128, 128>>>(sbf, int_sbf_w, SBFP);

    // ---- embedding block -> XSAVE[0] (f32) + XSH[0] (half) ----
    embed_fill_k<<<NEDGES, HD>>>(z, ei, ej, rbf, emb_table, emb_rbf_w, emb_rbf_b, AEMBh);
    gemm_h<<<gE, 256>>>(AEMBh, 1, WH + WH_EMB, emb_b, nullptr, nullptr, nullptr,
                        XSAVE, XSH, nullptr, NEDGES, HD, 3 * HD, 1, 0, 0, 0, 0);

    for (int b = 0; b < NBLK; b++) {
        float*  xa  = XSAVE + (size_t)b * EH;
        float*  xb  = XSAVE + (size_t)(b + 1) * EH;
        __half* xah = XSH   + (size_t)b * EH;
        __half* xbh = XSH   + (size_t)(b + 1) * EH;

        gemm_h<<<gE, 256>>>(xah, 1, WH + WH_JI + (size_t)b * HDHD,
                            int_ji_b + (size_t)b * HD, nullptr, nullptr, nullptr,
                            XJI, nullptr, nullptr, NEDGES, HD, HD, 1, 0, 0, 0, 0);
        gemm_h<<<gE, 256>>>(xah, 1, WH + WH_KJ + (size_t)b * HDHD,
                            int_kj_b + (size_t)b * HD, nullptr,
                            rbf, int_rbf_w + (size_t)b * NR * HD,
                            nullptr, XKJh, nullptr, NEDGES, HD, HD, 1, 0, 0, 0, 0);
        gemm_h<<<gEG, 256>>>(XKJh, 1, WH + WH_G + (size_t)b * NB * HDHD,
                             nullptr, nullptr, nullptr, nullptr,
                             nullptr, nullptr, Gh, NEDGES, NB * HD, HD, 0, 0, 0, 0, 0);

        trip_kj_k<<<(NEDGES + 7) / 8, 256>>>(Gh, SBFP + (size_t)b * NB,
                                             idx_ji, OFF, PERM, XJI);

        chain_k<<<(NEDGES + 63) / 64, 256>>>(
            XJI, xa,
            WH + WH_BEF + (size_t)b * 2 * HDHD,
            WH + WH_LIN + (size_t)b * HDHD,
            WH + WH_AFT + (size_t)b * 4 * HDHD,
            int_bef_b + (size_t)b * 2 * HD,
            int_lin_b + (size_t)b * HD,
            int_aft_b + (size_t)b * 4 * HD,
            xb, xbh, NEDGES);
    }

    // ---- all 7 out_blocks, batched at the end ----
    edge_scatter7_k<<<dim3(NEDGES, 7), HD>>>(rbf, out_rbf_w, XSAVE, ei, ATOM7);
    gemm_h<<<gA7, 256>>>(ATOM7, 0, WH + WH_OUT + 0 * HDHD, out_lins_b + 0 * HD,
                         nullptr, nullptr, nullptr, nullptr, ATOMH, nullptr,
                         NATOMS, HD, HD, 1, AH7, (size_t)3 * HDHD, (size_t)3 * HD, AH7);
    gemm_h<<<gA7, 256>>>(ATOMH, 1, WH + WH_OUT + 1 * HDHD, out_lins_b + 1 * HD,
                         nullptr, nullptr, nullptr, nullptr, ATOMH2, nullptr,
                         NATOMS, HD, HD, 1, AH7, (size_t)3 * HDHD, (size_t)3 * HD, AH7);
    gemm_h<<<gA7, 256>>>(ATOMH2, 1, WH + WH_OUT + 2 * HDHD, out_lins_b + 2 * HD,
                         nullptr, nullptr, nullptr, ATOM7B, nullptr, nullptr,
                         NATOMS, HD, HD, 1, AH7, (size_t)3 * HDHD, (size_t)3 * HD, AH7);
    dot7_k<<<dim3((NATOMS + 7) / 8, 7), 256>>>(ATOM7B, out_w, batch, out);
}

// round 16
// speedup vs baseline: 1.4607x; 1.0360x over previous
#include <cuda_runtime.h>
#include <cuda_fp16.h>
#include <cuda_bf16.h>
#include <math.h>

#define NATOMS 8000
#define NEDGES 100000
#define NTRIP  500000
#define NGRAPHS 64
#define HD 128
#define NR 6
#define NSNR 42
#define NB 8
#define NBLK 6
#define HDHD (HD*HD)

// ---------------- device scratch ----------------
__device__ float  g_XSAVE[(size_t)(NBLK + 1) * NEDGES * HD];
__device__ __half g_XSH  [(size_t)(NBLK + 1) * NEDGES * HD];
__device__ float  g_XJI [NEDGES*HD];
__device__ float  g_SBFP[(size_t)NTRIP*NBLK*NB];
__device__ __half g_AEMBh[(size_t)NEDGES*3*HD];
__device__ __nv_bfloat16 g_Gh[(size_t)NEDGES*NB*HD];
__device__ float  g_ATOM7 [(size_t)7*NATOMS*HD];
__device__ float  g_ATOM7B[(size_t)7*NATOMS*HD];
__device__ __half g_ATOMH [(size_t)7*NATOMS*HD];
__device__ __half g_ATOMH2[(size_t)7*NATOMS*HD];
__device__ int    g_CNT [NEDGES];
__device__ int    g_OFF [NEDGES + 1];
__device__ int    g_POS [NEDGES];
__device__ int    g_PERM[NTRIP];

#define WH_EMB  0
#define WH_JI   (WH_EMB + 3*HDHD)
#define WH_KJ   (WH_JI  + NBLK*HDHD)
#define WH_BEF  (WH_KJ  + NBLK*HDHD)
#define WH_LIN  (WH_BEF + NBLK*2*HDHD)
#define WH_AFT  (WH_LIN + NBLK*HDHD)
#define WH_OUT  (WH_AFT + NBLK*4*HDHD)
#define WH_G    (WH_OUT + 7*3*HDHD)
#define WH_TOTAL (WH_G + NBLK*NB*HDHD)
__device__ __half g_WH[WH_TOTAL];

__device__ __forceinline__ float silu(float x) { return x / (1.0f + expf(-x)); }

__device__ __forceinline__ unsigned packh2(float a, float b) {
    __half2 h = __floats2half2_rn(a, b);
    return *reinterpret_cast<unsigned*>(&h);
}

__device__ __forceinline__ void mma_f16(float* c, const unsigned* a, const unsigned* b) {
    asm volatile(
        "mma.sync.aligned.m16n8k16.row.col.f32.f16.f16.f32 "
        "{%0,%1,%2,%3}, {%4,%5,%6,%7}, {%8,%9}, {%0,%1,%2,%3};"
        : "+f"(c[0]), "+f"(c[1]), "+f"(c[2]), "+f"(c[3])
        : "r"(a[0]), "r"(a[1]), "r"(a[2]), "r"(a[3]),
          "r"(b[0]), "r"(b[1]));
}

__device__ __forceinline__ void cp16(unsigned saddr, const void* g, int bytes) {
    asm volatile("cp.async.cg.shared.global [%0], [%1], 16, %2;"
                 :: "r"(saddr), "l"(g), "r"(bytes) : "memory");
}

__device__ __forceinline__ void ldsm4(unsigned& r0, unsigned& r1, unsigned& r2, unsigned& r3,
                                      const __half* p) {
    unsigned addr = (unsigned)__cvta_generic_to_shared(p);
    asm volatile("ldmatrix.sync.aligned.m8n8.x4.shared.b16 {%0,%1,%2,%3}, [%4];"
                 : "=r"(r0), "=r"(r1), "=r"(r2), "=r"(r3) : "r"(addr));
}

// ---------------- weight convert ----------------
__global__ void convw_k(const float* __restrict__ src, __half* __restrict__ dst,
                        int K, int N, long total)
{
    long idx = (long)blockIdx.x * blockDim.x + threadIdx.x;
    if (idx >= total) return;
    long per = (long)K * N;
    long m = idx / per, r = idx % per;
    int n = (int)(r / K), k = (int)(r % K);
    dst[idx] = __float2half(src[m * per + (size_t)k * N + n]);
}

__global__ void convg_k(const float* __restrict__ W, __half* __restrict__ dst)
{
    int idx = blockIdx.x * blockDim.x + threadIdx.x;
    int b = idx >> 17;
    int r = idx & 131071;
    int n = r >> 7, l = r & 127;
    int j = n >> 7, i = n & 127;
    dst[idx] = __float2half(W[(size_t)b * 131072 + (size_t)i * 1024 + j * 128 + l]);
}

// ---------------- CSR build (keyed on idx_kj) ----------------
__global__ void count_k(const int* __restrict__ key, int* __restrict__ cnt)
{
    int w = blockIdx.x * blockDim.x + threadIdx.x;
    if (w < NTRIP) atomicAdd(&cnt[key[w]], 1);
}

__global__ void scan_k(const int* __restrict__ cnt, int* __restrict__ off)
{
    __shared__ int buf[1024];
    __shared__ int carry;
    if (threadIdx.x == 0) carry = 0;
    __syncthreads();
    for (int base = 0; base < NEDGES; base += 1024) {
        int i = base + threadIdx.x;
        int v = (i < NEDGES) ? cnt[i] : 0;
        buf[threadIdx.x] = v;
        __syncthreads();
        for (int d = 1; d < 1024; d <<= 1) {
            int t = (threadIdx.x >= d) ? buf[threadIdx.x - d] : 0;
            __syncthreads();
            buf[threadIdx.x] += t;
            __syncthreads();
        }
        if (i < NEDGES) off[i] = carry + buf[threadIdx.x] - v;
        int total = buf[1023];
        __syncthreads();
        if (threadIdx.x == 0) carry += total;
        __syncthreads();
    }
    if (threadIdx.x == 0) off[NEDGES] = carry;
}

__global__ void place_k(const int* __restrict__ key, const int* __restrict__ off,
                        int* __restrict__ pos, int* __restrict__ perm)
{
    int w = blockIdx.x * blockDim.x + threadIdx.x;
    if (w >= NTRIP) return;
    int e = key[w];
    int p = off[e] + atomicAdd(&pos[e], 1);
    perm[p] = w;
}

// ---------------- fp16 tensor-core GEMM (embed + out-blocks) ----------------
#define AST 72
__global__ __launch_bounds__(256, 2) void gemm_h(
    const void* __restrict__ Av, int aHalf, const __half* __restrict__ Bh,
    const float* __restrict__ bias, const float* __restrict__ addv,
    float* __restrict__ Cf, __half* __restrict__ Chh,
    int M, int N, int K, int act,
    size_t aZ, size_t bZ, size_t biasZ, size_t cZ)
{
    __shared__ __half As[128][AST];
    __shared__ __half Bs[128][AST];

    const float* Af = (const float*)Av + blockIdx.z * aZ;
    const __half* Ah = (const __half*)Av + blockIdx.z * aZ;
    Bh += blockIdx.z * bZ;
    if (bias) bias += blockIdx.z * biasZ;

    const int tid = threadIdx.x;
    const int bM = blockIdx.y * 128;
    const int bN = blockIdx.x * 128;
    const int lane = tid & 31, warp = tid >> 5;
    const int gid = lane >> 2, tig = lane & 3;
    const int wm = warp >> 2, wn = warp & 3;

    const int aRowO = (lane & 7) + ((lane >> 3) & 1) * 8;
    const int aColO = ((lane >> 4) & 1) * 8;
    const int bRowO = (lane & 7) + ((lane >> 4) & 1) * 8;
    const int bColO = ((lane >> 3) & 1) * 8;

    float c[4][4][4];
#pragma unroll
    for (int i = 0; i < 4; i++)
#pragma unroll
        for (int j = 0; j < 4; j++)
#pragma unroll
            for (int q = 0; q < 4; q++) c[i][j][q] = 0.f;

    unsigned sA = (unsigned)__cvta_generic_to_shared(&As[0][0]);
    unsigned sB = (unsigned)__cvta_generic_to_shared(&Bs[0][0]);

    for (int kc = 0; kc < K; kc += 64) {
        if (kc) __syncthreads();

#pragma unroll
        for (int it = 0; it < 4; it++) {
            int f = it * 256 + tid;
            int row = f >> 3, c8 = (f & 7) * 8;
            cp16(sB + (row * AST + c8) * 2,
                 Bh + (size_t)(bN + row) * K + kc + c8, 16);
        }
        if (aHalf) {
#pragma unroll
            for (int it = 0; it < 4; it++) {
                int f = it * 256 + tid;
                int row = f >> 3, c8 = (f & 7) * 8;
                cp16(sA + (row * AST + c8) * 2,
                     Ah + (size_t)(bM + row) * K + kc + c8,
                     (bM + row) < M ? 16 : 0);
            }
        } else {
#pragma unroll
            for (int it = 0; it < 8; it++) {
                int f = it * 256 + tid;
                int row = f >> 4, c4 = (f & 15) * 4;
                float4 v = make_float4(0.f, 0.f, 0.f, 0.f);
                if (bM + row < M)
                    v = *(const float4*)(Af + (size_t)(bM + row) * K + kc + c4);
                *(uint2*)&As[row][c4] = make_uint2(packh2(v.x, v.y), packh2(v.z, v.w));
            }
        }
        asm volatile("cp.async.commit_group;" ::: "memory");
        asm volatile("cp.async.wait_group 0;" ::: "memory");
        __syncthreads();

#pragma unroll
        for (int kk = 0; kk < 64; kk += 16) {
            unsigned af[4][4], bf[4][2];
#pragma unroll
            for (int fm = 0; fm < 4; fm++) {
                int m0 = wm * 64 + fm * 16;
                ldsm4(af[fm][0], af[fm][1], af[fm][2], af[fm][3],
                      &As[m0 + aRowO][kk + aColO]);
            }
#pragma unroll
            for (int p = 0; p < 2; p++) {
                int n0 = wn * 32 + p * 16;
                ldsm4(bf[2 * p][0], bf[2 * p][1], bf[2 * p + 1][0], bf[2 * p + 1][1],
                      &Bs[n0 + bRowO][kk + bColO]);
            }
#pragma unroll
            for (int fm = 0; fm < 4; fm++)
#pragma unroll
                for (int fn = 0; fn < 4; fn++)
                    mma_f16(c[fm][fn], af[fm], bf[fn]);
        }
    }

    if (Cf)  Cf  += blockIdx.z * cZ;
    if (Chh) Chh += blockIdx.z * cZ;

#pragma unroll
    for (int fm = 0; fm < 4; fm++) {
#pragma unroll
        for (int half_ = 0; half_ < 2; half_++) {
            int row = bM + wm * 64 + fm * 16 + gid + half_ * 8;
            if (row >= M) continue;
#pragma unroll
            for (int fn = 0; fn < 4; fn++) {
                int col = bN + wn * 32 + fn * 8 + tig * 2;
                float v0 = c[fm][fn][half_ * 2 + 0] + (bias ? bias[col] : 0.f);
                float v1 = c[fm][fn][half_ * 2 + 1] + (bias ? bias[col + 1] : 0.f);
                if (act) { v0 = silu(v0); v1 = silu(v1); }
                size_t base = (size_t)row * N + col;
                if (addv) {
                    float2 av = *(const float2*)(addv + base);
                    v0 += av.x; v1 += av.y;
                }
                if (Cf)  *(float2*)(Cf + base) = make_float2(v0, v1);
                if (Chh) *(unsigned*)(Chh + base) = packh2(v0, v1);
            }
        }
    }
}

// ---------------- fused front: ji + kj(+rbf mul) + 8x G per 64-edge tile -------------
#define CST 136
__global__ __launch_bounds__(256) void front_k(
    const __half* __restrict__ xah, const float* __restrict__ rbf,
    const float* __restrict__ rbfw,
    const __half* __restrict__ Wji, const float* __restrict__ bji,
    const __half* __restrict__ Wkj, const float* __restrict__ bkj,
    const __half* __restrict__ WG,
    float* __restrict__ XJI, __nv_bfloat16* __restrict__ Gh, int M)
{
    __shared__ __half Ts[64][CST];    // A tile, later XKJ tile (full K=128)
    __shared__ __half Ws[128][AST];   // streamed weights (64-K chunks)

    const int tid = threadIdx.x;
    const int bM = blockIdx.x * 64;
    const int lane = tid & 31, warp = tid >> 5;
    const int gid = lane >> 2, tig = lane & 3;
    const int wm = warp >> 2, wn = warp & 3;   // warp tile 32x32

    const int aRowO = (lane & 7) + ((lane >> 3) & 1) * 8;
    const int aColO = ((lane >> 4) & 1) * 8;
    const int bRowO = (lane & 7) + ((lane >> 4) & 1) * 8;
    const int bColO = ((lane >> 3) & 1) * 8;

    unsigned sT = (unsigned)__cvta_generic_to_shared(&Ts[0][0]);
    unsigned sW = (unsigned)__cvta_generic_to_shared(&Ws[0][0]);

    // load A tile (64 rows x 128 halfs)
#pragma unroll
    for (int it = 0; it < 4; it++) {
        int f = it * 256 + tid;
        int row = f >> 4, c8 = (f & 15) * 8;
        cp16(sT + (row * CST + c8) * 2,
             xah + (size_t)(bM + row) * HD + c8, (bM + row) < M ? 16 : 0);
    }
    asm volatile("cp.async.commit_group;" ::: "memory");

    float acc[2][4][4];

    // ---- inline GEMM stage: acc = Ts(64x128) @ Wp(128xK128)^T ----
#define STAGE(Wp)                                                                   \
    {                                                                               \
        _Pragma("unroll")                                                           \
        for (int i = 0; i < 2; i++)                                                 \
            _Pragma("unroll")                                                       \
            for (int j = 0; j < 4; j++)                                             \
                _Pragma("unroll")                                                   \
                for (int q = 0; q < 4; q++) acc[i][j][q] = 0.f;                     \
        for (int kc = 0; kc < HD; kc += 64) {                                       \
            __syncthreads();                                                        \
            _Pragma("unroll")                                                       \
            for (int it = 0; it < 4; it++) {                                        \
                int f = it * 256 + tid;                                             \
                int row = f >> 3, c8 = (f & 7) * 8;                                 \
                cp16(sW + (row * AST + c8) * 2, (Wp) + (size_t)row * HD + kc + c8, 16); \
            }                                                                       \
            asm volatile("cp.async.commit_group;" ::: "memory");                    \
            asm volatile("cp.async.wait_group 0;" ::: "memory");                    \
            __syncthreads();                                                        \
            _Pragma("unroll")                                                       \
            for (int kk = 0; kk < 64; kk += 16) {                                   \
                unsigned af[2][4], bf[4][2];                                        \
                _Pragma("unroll")                                                   \
                for (int fm = 0; fm < 2; fm++) {                                    \
                    int m0 = wm * 32 + fm * 16;                                     \
                    ldsm4(af[fm][0], af[fm][1], af[fm][2], af[fm][3],               \
                          &Ts[m0 + aRowO][kc + kk + aColO]);                        \
                }                                                                   \
                _Pragma("unroll")                                                   \
                for (int p = 0; p < 2; p++) {                                       \
                    int n0 = wn * 32 + p * 16;                                      \
                    ldsm4(bf[2*p][0], bf[2*p][1], bf[2*p+1][0], bf[2*p+1][1],       \
                          &Ws[n0 + bRowO][kk + bColO]);                             \
                }                                                                   \
                _Pragma("unroll")                                                   \
                for (int fm = 0; fm < 2; fm++)                                      \
                    _Pragma("unroll")                                               \
                    for (int fn = 0; fn < 4; fn++)                                  \
                        mma_f16(acc[fm][fn], af[fm], bf[fn]);                       \
            }                                                                       \
        }                                                                           \
    }

    // ---- stage 1: ji -> XJI f32 ----
    STAGE(Wji);
#pragma unroll
    for (int fm = 0; fm < 2; fm++)
#pragma unroll
        for (int half_ = 0; half_ < 2; half_++) {
            int lrow = wm * 32 + fm * 16 + gid + half_ * 8;
            int grow = bM + lrow;
            if (grow >= M) continue;
#pragma unroll
            for (int fn = 0; fn < 4; fn++) {
                int col = wn * 32 + fn * 8 + tig * 2;
                float v0 = silu(acc[fm][fn][half_*2+0] + bji[col]);
                float v1 = silu(acc[fm][fn][half_*2+1] + bji[col+1]);
                *(float2*)(XJI + (size_t)grow * HD + col) = make_float2(v0, v1);
            }
        }

    // ---- stage 2: kj -> (silu + bias) * rbfp -> overwrite Ts ----
    STAGE(Wkj);
    __syncthreads();   // all kj mma reads of Ts done before overwrite
#pragma unroll
    for (int fm = 0; fm < 2; fm++)
#pragma unroll
        for (int half_ = 0; half_ < 2; half_++) {
            int lrow = wm * 32 + fm * 16 + gid + half_ * 8;
            int grow = bM + lrow;
            float rr[NR];
#pragma unroll
            for (int r = 0; r < NR; r++)
                rr[r] = (grow < M) ? rbf[(size_t)grow * NR + r] : 0.f;
#pragma unroll
            for (int fn = 0; fn < 4; fn++) {
                int col = wn * 32 + fn * 8 + tig * 2;
                float v0 = silu(acc[fm][fn][half_*2+0] + bkj[col]);
                float v1 = silu(acc[fm][fn][half_*2+1] + bkj[col+1]);
                float rp0 = 0.f, rp1 = 0.f;
#pragma unroll
                for (int r = 0; r < NR; r++) {
                    rp0 += rr[r] * rbfw[r * HD + col];
                    rp1 += rr[r] * rbfw[r * HD + col + 1];
                }
                *(unsigned*)&Ts[lrow][col] = packh2(v0 * rp0, v1 * rp1);
            }
        }

    // ---- stages 3..10: G_jj = XKJ @ WG_jj^T -> bf16 ----
    for (int jj = 0; jj < NB; jj++) {
        STAGE(WG + (size_t)jj * HDHD);
#pragma unroll
        for (int fm = 0; fm < 2; fm++)
#pragma unroll
            for (int half_ = 0; half_ < 2; half_++) {
                int lrow = wm * 32 + fm * 16 + gid + half_ * 8;
                int grow = bM + lrow;
                if (grow >= M) continue;
#pragma unroll
                for (int fn = 0; fn < 4; fn++) {
                    int col = wn * 32 + fn * 8 + tig * 2;
                    float v0 = acc[fm][fn][half_*2+0];
                    float v1 = acc[fm][fn][half_*2+1];
                    *(__nv_bfloat162*)(Gh + (size_t)grow * (NB * HD) + jj * HD + col) =
                        __float22bfloat162_rn(make_float2(v0, v1));
                }
            }
    }
#undef STAGE
}

// ---------------- fused 7-layer residual chain ----------------
__global__ __launch_bounds__(256) void chain_k(
    const float* __restrict__ XJI, const float* __restrict__ xa,
    const __half* __restrict__ Wbef, const __half* __restrict__ Wlin,
    const __half* __restrict__ Waft,
    const float* __restrict__ bbef, const float* __restrict__ blin,
    const float* __restrict__ baft,
    float* __restrict__ xb, __half* __restrict__ xbh, int M)
{
    __shared__ __half Act[64][CST];
    __shared__ __half Wb[128][AST];

    const int tid = threadIdx.x;
    const int bM = blockIdx.x * 64;
    const int lane = tid & 31, warp = tid >> 5;
    const int gid = lane >> 2, tig = lane & 3;
    const int wm = warp >> 2, wn = warp & 3;

    const int aRowO = (lane & 7) + ((lane >> 3) & 1) * 8;
    const int aColO = ((lane >> 4) & 1) * 8;
    const int bRowO = (lane & 7) + ((lane >> 4) & 1) * 8;
    const int bColO = ((lane >> 3) & 1) * 8;

    unsigned sW = (unsigned)__cvta_generic_to_shared(&Wb[0][0]);

#pragma unroll
    for (int it = 0; it < 8; it++) {
        int f = it * 256 + tid;
        int row = f >> 5, c4 = (f & 31) * 4;
        float4 v = make_float4(0.f, 0.f, 0.f, 0.f);
        if (bM + row < M)
            v = *(const float4*)(XJI + (size_t)(bM + row) * HD + c4);
        *(uint2*)&Act[row][c4] = make_uint2(packh2(v.x, v.y), packh2(v.z, v.w));
    }

    float skip[2][4][4];

    for (int s = 0; s < 7; s++) {
        const __half* Wp;
        const float* bp;
        if (s == 0)      { Wp = Wbef;              bp = bbef; }
        else if (s == 1) { Wp = Wbef + HDHD;       bp = bbef + HD; }
        else if (s == 2) { Wp = Wlin;              bp = blin; }
        else             { Wp = Waft + (s-3)*HDHD; bp = baft + (s-3)*HD; }

        float acc[2][4][4];
#pragma unroll
        for (int i = 0; i < 2; i++)
#pragma unroll
            for (int j = 0; j < 4; j++)
#pragma unroll
                for (int q = 0; q < 4; q++) acc[i][j][q] = 0.f;

        for (int kc = 0; kc < HD; kc += 64) {
            __syncthreads();
#pragma unroll
            for (int it = 0; it < 4; it++) {
                int f = it * 256 + tid;
                int row = f >> 3, c8 = (f & 7) * 8;
                cp16(sW + (row * AST + c8) * 2, Wp + (size_t)row * HD + kc + c8, 16);
            }
            asm volatile("cp.async.commit_group;" ::: "memory");
            asm volatile("cp.async.wait_group 0;" ::: "memory");
            __syncthreads();

#pragma unroll
            for (int kk = 0; kk < 64; kk += 16) {
                unsigned af[2][4], bf[4][2];
#pragma unroll
                for (int fm = 0; fm < 2; fm++) {
                    int m0 = wm * 32 + fm * 16;
                    ldsm4(af[fm][0], af[fm][1], af[fm][2], af[fm][3],
                          &Act[m0 + aRowO][kc + kk + aColO]);
                }
#pragma unroll
                for (int p = 0; p < 2; p++) {
                    int n0 = wn * 32 + p * 16;
                    ldsm4(bf[2*p][0], bf[2*p][1], bf[2*p+1][0], bf[2*p+1][1],
                          &Wb[n0 + bRowO][kk + bColO]);
                }
#pragma unroll
                for (int fm = 0; fm < 2; fm++)
#pragma unroll
                    for (int fn = 0; fn < 4; fn++)
                        mma_f16(acc[fm][fn], af[fm], bf[fn]);
            }
        }
        __syncthreads();

#pragma unroll
        for (int fm = 0; fm < 2; fm++) {
#pragma unroll
            for (int half_ = 0; half_ < 2; half_++) {
                int lrow = wm * 32 + fm * 16 + gid + half_ * 8;
                int grow = bM + lrow;
                int inb = grow < M;
#pragma unroll
                for (int fn = 0; fn < 4; fn++) {
                    int col = wn * 32 + fn * 8 + tig * 2;
                    float v0 = silu(acc[fm][fn][half_*2+0] + bp[col]);
                    float v1 = silu(acc[fm][fn][half_*2+1] + bp[col+1]);
                    size_t base = (size_t)grow * HD + col;
                    if (s == 1 && inb) {
                        float2 av = *(const float2*)(XJI + base);
                        v0 += av.x; v1 += av.y;
                    } else if (s == 2) {
                        if (inb) {
                            float2 av = *(const float2*)(xa + base);
                            v0 += av.x; v1 += av.y;
                        }
                        skip[fm][fn][half_*2+0] = v0;
                        skip[fm][fn][half_*2+1] = v1;
                    } else if (s == 4) {
                        v0 += skip[fm][fn][half_*2+0];
                        v1 += skip[fm][fn][half_*2+1];
                        skip[fm][fn][half_*2+0] = v0;
                        skip[fm][fn][half_*2+1] = v1;
                    } else if (s == 6) {
                        v0 += skip[fm][fn][half_*2+0];
                        v1 += skip[fm][fn][half_*2+1];
                    }
                    if (s < 6) {
                        *(unsigned*)&Act[lrow][col] = packh2(v0, v1);
                    } else if (inb) {
                        *(float2*)(xb + base) = make_float2(v0, v1);
                        *(unsigned*)(xbh + base) = packh2(v0, v1);
                    }
                }
            }
        }
    }
}

// ---------------- embedding ----------------
__global__ void embed_fill_k(const int* __restrict__ z, const int* __restrict__ ei,
                             const int* __restrict__ ej, const float* __restrict__ rbf,
                             const float* __restrict__ emb_table,
                             const float* __restrict__ erw, const float* __restrict__ erb,
                             __half* __restrict__ Aemb)
{
    int e = blockIdx.x, h = threadIdx.x;
    int zi = z[ei[e]], zj = z[ej[e]];
    float s = erb[h];
    const float* rr = rbf + (size_t)e * NR;
#pragma unroll
    for (int r = 0; r < NR; r++) s += rr[r] * erw[r * HD + h];
    size_t base = (size_t)e * (3 * HD);
    Aemb[base + h]           = __float2half(emb_table[(size_t)zi * HD + h]);
    Aemb[base + HD + h]      = __float2half(emb_table[(size_t)zj * HD + h]);
    Aemb[base + 2 * HD + h]  = __float2half(silu(s));
}

// ---------------- sbf projection, ALL blocks ----------------
__global__ void sbfp_all_k(const float* __restrict__ sbf, const float* __restrict__ w,
                           float* __restrict__ outp)
{
    __shared__ float ws[NBLK * NSNR * NB];
    for (int idx = threadIdx.x; idx < NBLK * NSNR * NB; idx += blockDim.x) ws[idx] = w[idx];
    __syncthreads();
    int t = blockIdx.x * blockDim.x + threadIdx.x;
    if (t >= NTRIP) return;
    float sr[NSNR];
    const float* s = sbf + (size_t)t * NSNR;
#pragma unroll
    for (int r = 0; r < NSNR; r++) sr[r] = s[r];
    float* op = outp + (size_t)t * (NBLK * NB);
#pragma unroll
    for (int b = 0; b < NBLK; b++) {
        float acc[NB];
#pragma unroll
        for (int j = 0; j < NB; j++) acc[j] = 0.f;
        for (int r = 0; r < NSNR; r++) {
            float sv = sr[r];
#pragma unroll
            for (int j = 0; j < NB; j++) acc[j] += sv * ws[b * NSNR * NB + r * NB + j];
        }
#pragma unroll
        for (int j = 0; j < NB; j++) op[b * NB + j] = acc[j];
    }
}

// ---------------- CSR-by-kj triplet scatter ----------------
__global__ __launch_bounds__(256) void trip_kj_k(
    const __nv_bfloat16* __restrict__ Gh, const float* __restrict__ sbfp,
    const int* __restrict__ idx_ji, const int* __restrict__ off,
    const int* __restrict__ perm, float* __restrict__ Mo)
{
    int e = blockIdx.x * (blockDim.x >> 5) + (threadIdx.x >> 5);
    if (e >= NEDGES) return;
    int lane = threadIdx.x & 31;
    int s0 = off[e], s1 = off[e + 1];
    if (s0 == s1) return;

    float f[NB][4];
    const __nv_bfloat16* gr = Gh + (size_t)e * (NB * HD) + lane * 4;
#pragma unroll
    for (int j = 0; j < NB; j++) {
        uint2 u = *(const uint2*)(gr + j * HD);
        __nv_bfloat162 p0 = *reinterpret_cast<__nv_bfloat162*>(&u.x);
        __nv_bfloat162 p1 = *reinterpret_cast<__nv_bfloat162*>(&u.y);
        float2 a = __bfloat1622float2(p0);
        float2 b = __bfloat1622float2(p1);
        f[j][0] = a.x; f[j][1] = a.y; f[j][2] = b.x; f[j][3] = b.y;
    }

    for (int idx = s0; idx < s1; idx++) {
        int w = perm[idx];
        int ji = idx_ji[w];
        float sv = (lane < NB) ? sbfp[(size_t)w * (NBLK * NB) + lane] : 0.f;
        float4 acc = make_float4(0.f, 0.f, 0.f, 0.f);
#pragma unroll
        for (int j = 0; j < NB; j++) {
            float s = __shfl_sync(0xffffffffu, sv, j);
            acc.x += s * f[j][0]; acc.y += s * f[j][1];
            acc.z += s * f[j][2]; acc.w += s * f[j][3];
        }
        float* mo = Mo + (size_t)ji * HD + lane * 4;
        atomicAdd(mo + 0, acc.x);
        atomicAdd(mo + 1, acc.y);
        atomicAdd(mo + 2, acc.z);
        atomicAdd(mo + 3, acc.w);
    }
}

// ---------------- batched out-block edge scatter ----------------
__global__ void edge_scatter7_k(const float* __restrict__ rbf, const float* __restrict__ orw,
                                const float* __restrict__ xsave, const int* __restrict__ ei,
                                float* __restrict__ atom)
{
    int e = blockIdx.x, k = blockIdx.y, h = threadIdx.x;
    const float* rr = rbf + (size_t)e * NR;
    const float* w = orw + (size_t)k * NR * HD;
    float rp = 0.f;
#pragma unroll
    for (int r = 0; r < NR; r++) rp += rr[r] * w[r * HD + h];
    float v = rp * xsave[(size_t)k * NEDGES * HD + (size_t)e * HD + h];
    atomicAdd(&atom[(size_t)k * NATOMS * HD + (size_t)ei[e] * HD + h], v);
}

// ---------------- batched final per-atom dot + graph segment sum ----------------
__global__ void dot7_k(const float* __restrict__ atom2, const float* __restrict__ ow,
                       const int* __restrict__ batch, float* __restrict__ out)
{
    int a = blockIdx.x * (blockDim.x >> 5) + (threadIdx.x >> 5);
    if (a >= NATOMS) return;
    int k = blockIdx.y;
    int lane = threadIdx.x & 31;
    const float* ar = atom2 + (size_t)k * NATOMS * HD + (size_t)a * HD + lane * 4;
    const float* wr = ow + (size_t)k * HD + lane * 4;
    float s = ar[0] * wr[0] + ar[1] * wr[1] + ar[2] * wr[2] + ar[3] * wr[3];
#pragma unroll
    for (int o = 16; o > 0; o >>= 1) s += __shfl_down_sync(0xffffffffu, s, o);
    if (lane == 0) atomicAdd(&out[batch[a]], s);
}

// ==========================================================================================
extern "C" void kernel_launch(void* const* d_in, const int* in_sizes, int n_in,
                              void* d_out, int out_size)
{
    const int*   z        = (const int*)  d_in[0];
    const float* rbf      = (const float*)d_in[1];
    const float* sbf      = (const float*)d_in[2];
    const int*   ei       = (const int*)  d_in[3];
    const int*   ej       = (const int*)  d_in[4];
    const int*   idx_kj   = (const int*)  d_in[5];
    const int*   idx_ji   = (const int*)  d_in[6];
    const int*   batch    = (const int*)  d_in[7];
    const float* emb_table= (const float*)d_in[8];
    const float* emb_rbf_w= (const float*)d_in[9];
    const float* emb_rbf_b= (const float*)d_in[10];
    const float* emb_w    = (const float*)d_in[11];
    const float* emb_b    = (const float*)d_in[12];
    const float* int_rbf_w= (const float*)d_in[13];
    const float* int_sbf_w= (const float*)d_in[14];
    const float* int_kj_w = (const float*)d_in[15];
    const float* int_kj_b = (const float*)d_in[16];
    const float* int_ji_w = (const float*)d_in[17];
    const float* int_ji_b = (const float*)d_in[18];
    const float* int_W    = (const float*)d_in[19];
    const float* int_bef_w= (const float*)d_in[20];
    const float* int_bef_b= (const float*)d_in[21];
    const float* int_lin_w= (const float*)d_in[22];
    const float* int_lin_b= (const float*)d_in[23];
    const float* int_aft_w= (const float*)d_in[24];
    const float* int_aft_b= (const float*)d_in[25];
    const float* out_rbf_w= (const float*)d_in[26];
    const float* out_lins_w=(const float*)d_in[27];
    const float* out_lins_b=(const float*)d_in[28];
    const float* out_w    = (const float*)d_in[29];
    float* out = (float*)d_out;

    float *XSAVE, *XJI, *SBFP, *ATOM7, *ATOM7B;
    __half *XSH, *AEMBh, *ATOMH, *ATOMH2, *WH;
    __nv_bfloat16* Gh;
    int *CNT, *OFF, *POS, *PERM;
    cudaGetSymbolAddress((void**)&XSAVE, g_XSAVE);
    cudaGetSymbolAddress((void**)&XSH,   g_XSH);
    cudaGetSymbolAddress((void**)&XJI,   g_XJI);
    cudaGetSymbolAddress((void**)&SBFP,  g_SBFP);
    cudaGetSymbolAddress((void**)&AEMBh, g_AEMBh);
    cudaGetSymbolAddress((void**)&Gh,    g_Gh);
    cudaGetSymbolAddress((void**)&ATOM7, g_ATOM7);
    cudaGetSymbolAddress((void**)&ATOM7B,g_ATOM7B);
    cudaGetSymbolAddress((void**)&ATOMH, g_ATOMH);
    cudaGetSymbolAddress((void**)&ATOMH2,g_ATOMH2);
    cudaGetSymbolAddress((void**)&WH,    g_WH);
    cudaGetSymbolAddress((void**)&CNT,   g_CNT);
    cudaGetSymbolAddress((void**)&OFF,   g_OFF);
    cudaGetSymbolAddress((void**)&POS,   g_POS);
    cudaGetSymbolAddress((void**)&PERM,  g_PERM);

    const dim3 gE(1, (NEDGES + 127) / 128);
    const dim3 gA7(1, (NATOMS + 127) / 128, 7);
    const size_t EH = (size_t)NEDGES * HD;
    const size_t AH7 = (size_t)NATOMS * HD;

    cudaMemsetAsync(out, 0, NGRAPHS * sizeof(float));
    cudaMemsetAsync(ATOM7, 0, (size_t)7 * AH7 * sizeof(float));
    cudaMemsetAsync(CNT, 0, NEDGES * sizeof(int));
    cudaMemsetAsync(POS, 0, NEDGES * sizeof(int));

    count_k<<<(NTRIP + 255) / 256, 256>>>(idx_kj, CNT);
    scan_k<<<1, 1024>>>(CNT, OFF);
    place_k<<<(NTRIP + 255) / 256, 256>>>(idx_kj, OFF, POS, PERM);

    auto cw = [&](const float* src, __half* dst, int K, int N, int cnt) {
        long total = (long)cnt * K * N;
        convw_k<<<(unsigned)((total + 255) / 256), 256>>>(src, dst, K, N, total);
    };
    cw(emb_w,      WH + WH_EMB, 3 * HD, HD, 1);
    cw(int_ji_w,   WH + WH_JI,  HD, HD, NBLK);
    cw(int_kj_w,   WH + WH_KJ,  HD, HD, NBLK);
    cw(int_bef_w,  WH + WH_BEF, HD, HD, NBLK * 2);
    cw(int_lin_w,  WH + WH_LIN, HD, HD, NBLK);
    cw(int_aft_w,  WH + WH_AFT, HD, HD, NBLK * 4);
    cw(out_lins_w, WH + WH_OUT, HD, HD, 7 * 3);
    convg_k<<<(NBLK * NB * HD * HD) / 256, 256>>>(int_W, WH + WH_G);

    sbfp_all_k<<<(NTRIP + 127) / 128, 128>>>(sbf, int_sbf_w, SBFP);

    embed_fill_k<<<NEDGES, HD>>>(z, ei, ej, rbf, emb_table, emb_rbf_w, emb_rbf_b, AEMBh);
    gemm_h<<<gE, 256>>>(AEMBh, 1, WH + WH_EMB, emb_b, nullptr,
                        XSAVE, XSH, NEDGES, HD, 3 * HD, 1, 0, 0, 0, 0);

    for (int b = 0; b < NBLK; b++) {
        float*  xa  = XSAVE + (size_t)b * EH;
        float*  xb  = XSAVE + (size_t)(b + 1) * EH;
        __half* xah = XSH   + (size_t)b * EH;
        __half* xbh = XSH   + (size_t)(b + 1) * EH;

        front_k<<<(NEDGES + 63) / 64, 256>>>(
            xah, rbf, int_rbf_w + (size_t)b * NR * HD,
            WH + WH_JI + (size_t)b * HDHD, int_ji_b + (size_t)b * HD,
            WH + WH_KJ + (size_t)b * HDHD, int_kj_b + (size_t)b * HD,
            WH + WH_G + (size_t)b * NB * HDHD,
            XJI, Gh, NEDGES);

        trip_kj_k<<<(NEDGES + 7) / 8, 256>>>(Gh, SBFP + (size_t)b * NB,
                                             idx_ji, OFF, PERM, XJI);

        chain_k<<<(NEDGES + 63) / 64, 256>>>(
            XJI, xa,
            WH + WH_BEF + (size_t)b * 2 * HDHD,
            WH + WH_LIN + (size_t)b * HDHD,
            WH + WH_AFT + (size_t)b * 4 * HDHD,
            int_bef_b + (size_t)b * 2 * HD,
            int_lin_b + (size_t)b * HD,
            int_aft_b + (size_t)b * 4 * HD,
            xb, xbh, NEDGES);
    }

    edge_scatter7_k<<<dim3(NEDGES, 7), HD>>>(rbf, out_rbf_w, XSAVE, ei, ATOM7);
    gemm_h<<<gA7, 256>>>(ATOM7, 0, WH + WH_OUT + 0 * HDHD, out_lins_b + 0 * HD,
                         nullptr, nullptr, ATOMH,
                         NATOMS, HD, HD, 1, AH7, (size_t)3 * HDHD, (size_t)3 * HD, AH7);
    gemm_h<<<gA7, 256>>>(ATOMH, 1, WH + WH_OUT + 1 * HDHD, out_lins_b + 1 * HD,
                         nullptr, nullptr, ATOMH2,
                         NATOMS, HD, HD, 1, AH7, (size_t)3 * HDHD, (size_t)3 * HD, AH7);
    gemm_h<<<gA7, 256>>>(ATOMH2, 1, WH + WH_OUT + 2 * HDHD, out_lins_b + 2 * HD,
                         nullptr, ATOM7B, nullptr,
                         NATOMS, HD, HD, 1, AH7, (size_t)3 * HDHD, (size_t)3 * HD, AH7);
    dot7_k<<<dim3((NATOMS + 7) / 8, 7), 256>>>(ATOM7B, out_w, batch, out);
}

// round 17
// speedup vs baseline: 1.4775x; 1.0115x over previous
#include <cuda_runtime.h>
#include <cuda_fp16.h>
#include <cuda_bf16.h>
#include <math.h>

#define NATOMS 8000
#define NEDGES 100000
#define NTRIP  500000
#define NGRAPHS 64
#define HD 128
#define NR 6
#define NSNR 42
#define NB 8
#define NBLK 6
#define HDHD (HD*HD)

// ---------------- device scratch ----------------
__device__ float  g_XSAVE[(size_t)(NBLK + 1) * NEDGES * HD];
__device__ __half g_XSH  [(size_t)(NBLK + 1) * NEDGES * HD];
__device__ float  g_XJI [NEDGES*HD];
__device__ float  g_SBFP[(size_t)NTRIP*NBLK*NB];
__device__ __half g_AEMBh[(size_t)NEDGES*3*HD];
__device__ __nv_bfloat16 g_Gh[(size_t)NEDGES*NB*HD];
__device__ float  g_ATOM7 [(size_t)7*NATOMS*HD];
__device__ float  g_ATOM7B[(size_t)7*NATOMS*HD];
__device__ __half g_ATOMH [(size_t)7*NATOMS*HD];
__device__ __half g_ATOMH2[(size_t)7*NATOMS*HD];
__device__ int    g_CNT [NEDGES];
__device__ int    g_OFF [NEDGES + 1];
__device__ int    g_POS [NEDGES];
__device__ int    g_PERM[NTRIP];
__device__ int    g_PART[128];

#define WH_EMB  0
#define WH_JI   (WH_EMB + 3*HDHD)
#define WH_KJ   (WH_JI  + NBLK*HDHD)
#define WH_BEF  (WH_KJ  + NBLK*HDHD)
#define WH_LIN  (WH_BEF + NBLK*2*HDHD)
#define WH_AFT  (WH_LIN + NBLK*HDHD)
#define WH_OUT  (WH_AFT + NBLK*4*HDHD)
#define WH_G    (WH_OUT + 7*3*HDHD)
#define WH_TOTAL (WH_G + NBLK*NB*HDHD)
__device__ __half g_WH[WH_TOTAL];

__device__ __forceinline__ float silu(float x) { return x / (1.0f + expf(-x)); }

__device__ __forceinline__ unsigned packh2(float a, float b) {
    __half2 h = __floats2half2_rn(a, b);
    return *reinterpret_cast<unsigned*>(&h);
}

__device__ __forceinline__ void mma_f16(float* c, const unsigned* a, const unsigned* b) {
    asm volatile(
        "mma.sync.aligned.m16n8k16.row.col.f32.f16.f16.f32 "
        "{%0,%1,%2,%3}, {%4,%5,%6,%7}, {%8,%9}, {%0,%1,%2,%3};"
        : "+f"(c[0]), "+f"(c[1]), "+f"(c[2]), "+f"(c[3])
        : "r"(a[0]), "r"(a[1]), "r"(a[2]), "r"(a[3]),
          "r"(b[0]), "r"(b[1]));
}

__device__ __forceinline__ void cp16(unsigned saddr, const void* g, int bytes) {
    asm volatile("cp.async.cg.shared.global [%0], [%1], 16, %2;"
                 :: "r"(saddr), "l"(g), "r"(bytes) : "memory");
}

__device__ __forceinline__ void ldsm4(unsigned& r0, unsigned& r1, unsigned& r2, unsigned& r3,
                                      const __half* p) {
    unsigned addr = (unsigned)__cvta_generic_to_shared(p);
    asm volatile("ldmatrix.sync.aligned.m8n8.x4.shared.b16 {%0,%1,%2,%3}, [%4];"
                 : "=r"(r0), "=r"(r1), "=r"(r2), "=r"(r3) : "r"(addr));
}

// ---------------- weight convert ----------------
__global__ void convw_k(const float* __restrict__ src, __half* __restrict__ dst,
                        int K, int N, long total)
{
    long idx = (long)blockIdx.x * blockDim.x + threadIdx.x;
    if (idx >= total) return;
    long per = (long)K * N;
    long m = idx / per, r = idx % per;
    int n = (int)(r / K), k = (int)(r % K);
    dst[idx] = __float2half(src[m * per + (size_t)k * N + n]);
}

__global__ void convg_k(const float* __restrict__ W, __half* __restrict__ dst)
{
    int idx = blockIdx.x * blockDim.x + threadIdx.x;
    int b = idx >> 17;
    int r = idx & 131071;
    int n = r >> 7, l = r & 127;
    int j = n >> 7, i = n & 127;
    dst[idx] = __float2half(W[(size_t)b * 131072 + (size_t)i * 1024 + j * 128 + l]);
}

// ---------------- CSR build: count / parallel scan / place ----------------
__global__ void count_k(const int* __restrict__ key, int* __restrict__ cnt)
{
    int w = blockIdx.x * blockDim.x + threadIdx.x;
    if (w < NTRIP) atomicAdd(&cnt[key[w]], 1);
}

__global__ void bsum_k(const int* __restrict__ cnt, int* __restrict__ part)
{
    __shared__ int s[256];
    int base = blockIdx.x * 1024;
    int v = 0;
    for (int i = threadIdx.x; i < 1024; i += 256) {
        int idx = base + i;
        v += (idx < NEDGES) ? cnt[idx] : 0;
    }
    s[threadIdx.x] = v;
    __syncthreads();
    for (int d = 128; d > 0; d >>= 1) {
        if (threadIdx.x < d) s[threadIdx.x] += s[threadIdx.x + d];
        __syncthreads();
    }
    if (threadIdx.x == 0) part[blockIdx.x] = s[0];
}

__global__ void pscan_k(int* __restrict__ part, int n)
{
    if (threadIdx.x == 0) {
        int acc = 0;
        for (int i = 0; i < n; i++) { int t = part[i]; part[i] = acc; acc += t; }
        part[n] = acc;
    }
}

__global__ void offs_k(const int* __restrict__ cnt, const int* __restrict__ part,
                       int* __restrict__ off, int nblk)
{
    __shared__ int s[1024];
    int i = blockIdx.x * 1024 + threadIdx.x;
    int v = (i < NEDGES) ? cnt[i] : 0;
    s[threadIdx.x] = v;
    __syncthreads();
    for (int d = 1; d < 1024; d <<= 1) {
        int t = (threadIdx.x >= d) ? s[threadIdx.x - d] : 0;
        __syncthreads();
        s[threadIdx.x] += t;
        __syncthreads();
    }
    if (i < NEDGES) off[i] = part[blockIdx.x] + s[threadIdx.x] - v;
    if (i == NEDGES - 1) off[NEDGES] = part[nblk];
}

__global__ void place_k(const int* __restrict__ key, const int* __restrict__ off,
                        int* __restrict__ pos, int* __restrict__ perm)
{
    int w = blockIdx.x * blockDim.x + threadIdx.x;
    if (w >= NTRIP) return;
    int e = key[w];
    int p = off[e] + atomicAdd(&pos[e], 1);
    perm[p] = w;
}

// ---------------- fp16 tensor-core GEMM (embed + out-blocks) ----------------
#define AST 72
__global__ __launch_bounds__(256, 2) void gemm_h(
    const void* __restrict__ Av, int aHalf, const __half* __restrict__ Bh,
    const float* __restrict__ bias, const float* __restrict__ addv,
    float* __restrict__ Cf, __half* __restrict__ Chh,
    int M, int N, int K, int act,
    size_t aZ, size_t bZ, size_t biasZ, size_t cZ)
{
    __shared__ __half As[128][AST];
    __shared__ __half Bs[128][AST];

    const float* Af = (const float*)Av + blockIdx.z * aZ;
    const __half* Ah = (const __half*)Av + blockIdx.z * aZ;
    Bh += blockIdx.z * bZ;
    if (bias) bias += blockIdx.z * biasZ;

    const int tid = threadIdx.x;
    const int bM = blockIdx.y * 128;
    const int bN = blockIdx.x * 128;
    const int lane = tid & 31, warp = tid >> 5;
    const int gid = lane >> 2, tig = lane & 3;
    const int wm = warp >> 2, wn = warp & 3;

    const int aRowO = (lane & 7) + ((lane >> 3) & 1) * 8;
    const int aColO = ((lane >> 4) & 1) * 8;
    const int bRowO = (lane & 7) + ((lane >> 4) & 1) * 8;
    const int bColO = ((lane >> 3) & 1) * 8;

    float c[4][4][4];
#pragma unroll
    for (int i = 0; i < 4; i++)
#pragma unroll
        for (int j = 0; j < 4; j++)
#pragma unroll
            for (int q = 0; q < 4; q++) c[i][j][q] = 0.f;

    unsigned sA = (unsigned)__cvta_generic_to_shared(&As[0][0]);
    unsigned sB = (unsigned)__cvta_generic_to_shared(&Bs[0][0]);

    for (int kc = 0; kc < K; kc += 64) {
        if (kc) __syncthreads();

#pragma unroll
        for (int it = 0; it < 4; it++) {
            int f = it * 256 + tid;
            int row = f >> 3, c8 = (f & 7) * 8;
            cp16(sB + (row * AST + c8) * 2,
                 Bh + (size_t)(bN + row) * K + kc + c8, 16);
        }
        if (aHalf) {
#pragma unroll
            for (int it = 0; it < 4; it++) {
                int f = it * 256 + tid;
                int row = f >> 3, c8 = (f & 7) * 8;
                cp16(sA + (row * AST + c8) * 2,
                     Ah + (size_t)(bM + row) * K + kc + c8,
                     (bM + row) < M ? 16 : 0);
            }
        } else {
#pragma unroll
            for (int it = 0; it < 8; it++) {
                int f = it * 256 + tid;
                int row = f >> 4, c4 = (f & 15) * 4;
                float4 v = make_float4(0.f, 0.f, 0.f, 0.f);
                if (bM + row < M)
                    v = *(const float4*)(Af + (size_t)(bM + row) * K + kc + c4);
                *(uint2*)&As[row][c4] = make_uint2(packh2(v.x, v.y), packh2(v.z, v.w));
            }
        }
        asm volatile("cp.async.commit_group;" ::: "memory");
        asm volatile("cp.async.wait_group 0;" ::: "memory");
        __syncthreads();

#pragma unroll
        for (int kk = 0; kk < 64; kk += 16) {
            unsigned af[4][4], bf[4][2];
#pragma unroll
            for (int fm = 0; fm < 4; fm++) {
                int m0 = wm * 64 + fm * 16;
                ldsm4(af[fm][0], af[fm][1], af[fm][2], af[fm][3],
                      &As[m0 + aRowO][kk + aColO]);
            }
#pragma unroll
            for (int p = 0; p < 2; p++) {
                int n0 = wn * 32 + p * 16;
                ldsm4(bf[2 * p][0], bf[2 * p][1], bf[2 * p + 1][0], bf[2 * p + 1][1],
                      &Bs[n0 + bRowO][kk + bColO]);
            }
#pragma unroll
            for (int fm = 0; fm < 4; fm++)
#pragma unroll
                for (int fn = 0; fn < 4; fn++)
                    mma_f16(c[fm][fn], af[fm], bf[fn]);
        }
    }

    if (Cf)  Cf  += blockIdx.z * cZ;
    if (Chh) Chh += blockIdx.z * cZ;

#pragma unroll
    for (int fm = 0; fm < 4; fm++) {
#pragma unroll
        for (int half_ = 0; half_ < 2; half_++) {
            int row = bM + wm * 64 + fm * 16 + gid + half_ * 8;
            if (row >= M) continue;
#pragma unroll
            for (int fn = 0; fn < 4; fn++) {
                int col = bN + wn * 32 + fn * 8 + tig * 2;
                float v0 = c[fm][fn][half_ * 2 + 0] + (bias ? bias[col] : 0.f);
                float v1 = c[fm][fn][half_ * 2 + 1] + (bias ? bias[col + 1] : 0.f);
                if (act) { v0 = silu(v0); v1 = silu(v1); }
                size_t base = (size_t)row * N + col;
                if (addv) {
                    float2 av = *(const float2*)(addv + base);
                    v0 += av.x; v1 += av.y;
                }
                if (Cf)  *(float2*)(Cf + base) = make_float2(v0, v1);
                if (Chh) *(unsigned*)(Chh + base) = packh2(v0, v1);
            }
        }
    }
}

// =============== pipelined 64-row-tile stage machinery ===============
// W3: double-buffered 32-k weight chunks [2][128][AST2]; TILE: 64x CST half tile.
#define AST2 40
#define CST 136

// STAGE_P computes acc = TILE(64x128) @ Wp(128x128)^T with pipelined weight stream.
#define STAGE_P(Wp, TILE)                                                              \
    {                                                                                  \
        _Pragma("unroll")                                                              \
        for (int i = 0; i < 2; i++)                                                    \
            _Pragma("unroll")                                                          \
            for (int j = 0; j < 4; j++)                                                \
                _Pragma("unroll")                                                      \
                for (int q = 0; q < 4; q++) acc[i][j][q] = 0.f;                        \
        /* issue chunk 0 */                                                            \
        _Pragma("unroll")                                                              \
        for (int it = 0; it < 2; it++) {                                               \
            int f = it * 256 + tid;                                                    \
            int row = f >> 2, c8 = (f & 3) * 8;                                        \
            cp16(sW + ((0 * 128 + row) * AST2 + c8) * 2,                               \
                 (Wp) + (size_t)row * HD + 0 + c8, 16);                                \
        }                                                                              \
        asm volatile("cp.async.commit_group;" ::: "memory");                           \
        _Pragma("unroll")                                                              \
        for (int cc = 0; cc < 4; cc++) {                                               \
            if (cc < 3) {                                                              \
                int nb = (cc + 1) & 1;                                                 \
                _Pragma("unroll")                                                      \
                for (int it = 0; it < 2; it++) {                                       \
                    int f = it * 256 + tid;                                            \
                    int row = f >> 2, c8 = (f & 3) * 8;                                \
                    cp16(sW + ((nb * 128 + row) * AST2 + c8) * 2,                      \
                         (Wp) + (size_t)row * HD + (cc + 1) * 32 + c8, 16);            \
                }                                                                      \
                asm volatile("cp.async.commit_group;" ::: "memory");                   \
                asm volatile("cp.async.wait_group 1;" ::: "memory");                   \
            } else {                                                                   \
                asm volatile("cp.async.wait_group 0;" ::: "memory");                   \
            }                                                                          \
            __syncthreads();                                                           \
            _Pragma("unroll")                                                          \
            for (int kk = 0; kk < 32; kk += 16) {                                      \
                unsigned af[2][4], bf[4][2];                                           \
                _Pragma("unroll")                                                      \
                for (int fm = 0; fm < 2; fm++) {                                       \
                    int m0 = wm * 32 + fm * 16;                                        \
                    ldsm4(af[fm][0], af[fm][1], af[fm][2], af[fm][3],                  \
                          &TILE[m0 + aRowO][cc * 32 + kk + aColO]);                    \
                }                                                                      \
                _Pragma("unroll")                                                      \
                for (int p = 0; p < 2; p++) {                                          \
                    int n0 = wn * 32 + p * 16;                                         \
                    ldsm4(bf[2*p][0], bf[2*p][1], bf[2*p+1][0], bf[2*p+1][1],          \
                          &W3[cc & 1][n0 + bRowO][kk + bColO]);                        \
                }                                                                      \
                _Pragma("unroll")                                                      \
                for (int fm = 0; fm < 2; fm++)                                         \
                    _Pragma("unroll")                                                  \
                    for (int fn = 0; fn < 4; fn++)                                     \
                        mma_f16(acc[fm][fn], af[fm], bf[fn]);                          \
            }                                                                          \
            __syncthreads();                                                           \
        }                                                                              \
    }

// ---------------- fused front: ji + kj(+rbf mul) + 8x G per 64-edge tile -------------
__global__ __launch_bounds__(256) void front_k(
    const __half* __restrict__ xah, const float* __restrict__ rbf,
    const float* __restrict__ rbfw,
    const __half* __restrict__ Wji, const float* __restrict__ bji,
    const __half* __restrict__ Wkj, const float* __restrict__ bkj,
    const __half* __restrict__ WG,
    float* __restrict__ XJI, __nv_bfloat16* __restrict__ Gh, int M)
{
    __shared__ __half Ts[64][CST];        // 17.4 KB
    __shared__ __half W3[2][128][AST2];   // 20.5 KB

    const int tid = threadIdx.x;
    const int bM = blockIdx.x * 64;
    const int lane = tid & 31, warp = tid >> 5;
    const int gid = lane >> 2, tig = lane & 3;
    const int wm = warp >> 2, wn = warp & 3;

    const int aRowO = (lane & 7) + ((lane >> 3) & 1) * 8;
    const int aColO = ((lane >> 4) & 1) * 8;
    const int bRowO = (lane & 7) + ((lane >> 4) & 1) * 8;
    const int bColO = ((lane >> 3) & 1) * 8;

    unsigned sT = (unsigned)__cvta_generic_to_shared(&Ts[0][0]);
    unsigned sW = (unsigned)__cvta_generic_to_shared(&W3[0][0][0]);

    // load A tile (64 rows x 128 halfs) -- extra cp.async group ahead of chunk0
#pragma unroll
    for (int it = 0; it < 4; it++) {
        int f = it * 256 + tid;
        int row = f >> 4, c8 = (f & 15) * 8;
        cp16(sT + (row * CST + c8) * 2,
             xah + (size_t)(bM + row) * HD + c8, (bM + row) < M ? 16 : 0);
    }
    asm volatile("cp.async.commit_group;" ::: "memory");

    float acc[2][4][4];

    // ---- stage 1: ji -> XJI f32 ----
    STAGE_P(Wji, Ts);
#pragma unroll
    for (int fm = 0; fm < 2; fm++)
#pragma unroll
        for (int half_ = 0; half_ < 2; half_++) {
            int lrow = wm * 32 + fm * 16 + gid + half_ * 8;
            int grow = bM + lrow;
            if (grow >= M) continue;
#pragma unroll
            for (int fn = 0; fn < 4; fn++) {
                int col = wn * 32 + fn * 8 + tig * 2;
                float v0 = silu(acc[fm][fn][half_*2+0] + bji[col]);
                float v1 = silu(acc[fm][fn][half_*2+1] + bji[col+1]);
                *(float2*)(XJI + (size_t)grow * HD + col) = make_float2(v0, v1);
            }
        }

    // ---- stage 2: kj -> (silu + bias) * rbfp -> overwrite Ts ----
    STAGE_P(Wkj, Ts);
    // trailing sync of STAGE_P guarantees all Ts reads done
#pragma unroll
    for (int fm = 0; fm < 2; fm++)
#pragma unroll
        for (int half_ = 0; half_ < 2; half_++) {
            int lrow = wm * 32 + fm * 16 + gid + half_ * 8;
            int grow = bM + lrow;
            float rr[NR];
#pragma unroll
            for (int r = 0; r < NR; r++)
                rr[r] = (grow < M) ? rbf[(size_t)grow * NR + r] : 0.f;
#pragma unroll
            for (int fn = 0; fn < 4; fn++) {
                int col = wn * 32 + fn * 8 + tig * 2;
                float v0 = silu(acc[fm][fn][half_*2+0] + bkj[col]);
                float v1 = silu(acc[fm][fn][half_*2+1] + bkj[col+1]);
                float rp0 = 0.f, rp1 = 0.f;
#pragma unroll
                for (int r = 0; r < NR; r++) {
                    rp0 += rr[r] * rbfw[r * HD + col];
                    rp1 += rr[r] * rbfw[r * HD + col + 1];
                }
                *(unsigned*)&Ts[lrow][col] = packh2(v0 * rp0, v1 * rp1);
            }
        }
    __syncthreads();   // Ts writes visible before stage-3 ldsm

    // ---- stages 3..10: G_jj = XKJ @ WG_jj^T -> bf16 ----
    for (int jj = 0; jj < NB; jj++) {
        const __half* Wp = WG + (size_t)jj * HDHD;
        STAGE_P(Wp, Ts);
#pragma unroll
        for (int fm = 0; fm < 2; fm++)
#pragma unroll
            for (int half_ = 0; half_ < 2; half_++) {
                int lrow = wm * 32 + fm * 16 + gid + half_ * 8;
                int grow = bM + lrow;
                if (grow >= M) continue;
#pragma unroll
                for (int fn = 0; fn < 4; fn++) {
                    int col = wn * 32 + fn * 8 + tig * 2;
                    *(__nv_bfloat162*)(Gh + (size_t)grow * (NB * HD) + jj * HD + col) =
                        __float22bfloat162_rn(make_float2(acc[fm][fn][half_*2+0],
                                                          acc[fm][fn][half_*2+1]));
                }
            }
    }
}

// ---------------- fused 7-layer residual chain (pipelined) ----------------
__global__ __launch_bounds__(256) void chain_k(
    const float* __restrict__ XJI, const float* __restrict__ xa,
    const __half* __restrict__ Wbef, const __half* __restrict__ Wlin,
    const __half* __restrict__ Waft,
    const float* __restrict__ bbef, const float* __restrict__ blin,
    const float* __restrict__ baft,
    float* __restrict__ xb, __half* __restrict__ xbh, int M)
{
    __shared__ __half Act[64][CST];
    __shared__ __half W3[2][128][AST2];

    const int tid = threadIdx.x;
    const int bM = blockIdx.x * 64;
    const int lane = tid & 31, warp = tid >> 5;
    const int gid = lane >> 2, tig = lane & 3;
    const int wm = warp >> 2, wn = warp & 3;

    const int aRowO = (lane & 7) + ((lane >> 3) & 1) * 8;
    const int aColO = ((lane >> 4) & 1) * 8;
    const int bRowO = (lane & 7) + ((lane >> 4) & 1) * 8;
    const int bColO = ((lane >> 3) & 1) * 8;

    unsigned sW = (unsigned)__cvta_generic_to_shared(&W3[0][0][0]);

#pragma unroll
    for (int it = 0; it < 8; it++) {
        int f = it * 256 + tid;
        int row = f >> 5, c4 = (f & 31) * 4;
        float4 v = make_float4(0.f, 0.f, 0.f, 0.f);
        if (bM + row < M)
            v = *(const float4*)(XJI + (size_t)(bM + row) * HD + c4);
        *(uint2*)&Act[row][c4] = make_uint2(packh2(v.x, v.y), packh2(v.z, v.w));
    }

    float skip[2][4][4];
    float acc[2][4][4];

    for (int s = 0; s < 7; s++) {
        const __half* Wp;
        const float* bp;
        if (s == 0)      { Wp = Wbef;              bp = bbef; }
        else if (s == 1) { Wp = Wbef + HDHD;       bp = bbef + HD; }
        else if (s == 2) { Wp = Wlin;              bp = blin; }
        else             { Wp = Waft + (s-3)*HDHD; bp = baft + (s-3)*HD; }

        STAGE_P(Wp, Act);
        // trailing sync: Act reads complete before epilogue writes

#pragma unroll
        for (int fm = 0; fm < 2; fm++) {
#pragma unroll
            for (int half_ = 0; half_ < 2; half_++) {
                int lrow = wm * 32 + fm * 16 + gid + half_ * 8;
                int grow = bM + lrow;
                int inb = grow < M;
#pragma unroll
                for (int fn = 0; fn < 4; fn++) {
                    int col = wn * 32 + fn * 8 + tig * 2;
                    float v0 = silu(acc[fm][fn][half_*2+0] + bp[col]);
                    float v1 = silu(acc[fm][fn][half_*2+1] + bp[col+1]);
                    size_t base = (size_t)grow * HD + col;
                    if (s == 1 && inb) {
                        float2 av = *(const float2*)(XJI + base);
                        v0 += av.x; v1 += av.y;
                    } else if (s == 2) {
                        if (inb) {
                            float2 av = *(const float2*)(xa + base);
                            v0 += av.x; v1 += av.y;
                        }
                        skip[fm][fn][half_*2+0] = v0;
                        skip[fm][fn][half_*2+1] = v1;
                    } else if (s == 4) {
                        v0 += skip[fm][fn][half_*2+0];
                        v1 += skip[fm][fn][half_*2+1];
                        skip[fm][fn][half_*2+0] = v0;
                        skip[fm][fn][half_*2+1] = v1;
                    } else if (s == 6) {
                        v0 += skip[fm][fn][half_*2+0];
                        v1 += skip[fm][fn][half_*2+1];
                    }
                    if (s < 6) {
                        *(unsigned*)&Act[lrow][col] = packh2(v0, v1);
                    } else if (inb) {
                        *(float2*)(xb + base) = make_float2(v0, v1);
                        *(unsigned*)(xbh + base) = packh2(v0, v1);
                    }
                }
            }
        }
        __syncthreads();   // Act writes visible before next stage's ldsm
    }
}

// ---------------- embedding ----------------
__global__ void embed_fill_k(const int* __restrict__ z, const int* __restrict__ ei,
                             const int* __restrict__ ej, const float* __restrict__ rbf,
                             const float* __restrict__ emb_table,
                             const float* __restrict__ erw, const float* __restrict__ erb,
                             __half* __restrict__ Aemb)
{
    int e = blockIdx.x, h = threadIdx.x;
    int zi = z[ei[e]], zj = z[ej[e]];
    float s = erb[h];
    const float* rr = rbf + (size_t)e * NR;
#pragma unroll
    for (int r = 0; r < NR; r++) s += rr[r] * erw[r * HD + h];
    size_t base = (size_t)e * (3 * HD);
    Aemb[base + h]           = __float2half(emb_table[(size_t)zi * HD + h]);
    Aemb[base + HD + h]      = __float2half(emb_table[(size_t)zj * HD + h]);
    Aemb[base + 2 * HD + h]  = __float2half(silu(s));
}

// ---------------- sbf projection, ALL blocks ----------------
__global__ void sbfp_all_k(const float* __restrict__ sbf, const float* __restrict__ w,
                           float* __restrict__ outp)
{
    __shared__ float ws[NBLK * NSNR * NB];
    for (int idx = threadIdx.x; idx < NBLK * NSNR * NB; idx += blockDim.x) ws[idx] = w[idx];
    __syncthreads();
    int t = blockIdx.x * blockDim.x + threadIdx.x;
    if (t >= NTRIP) return;
    float sr[NSNR];
    const float* s = sbf + (size_t)t * NSNR;
#pragma unroll
    for (int r = 0; r < NSNR; r++) sr[r] = s[r];
    float* op = outp + (size_t)t * (NBLK * NB);
#pragma unroll
    for (int b = 0; b < NBLK; b++) {
        float acc[NB];
#pragma unroll
        for (int j = 0; j < NB; j++) acc[j] = 0.f;
        for (int r = 0; r < NSNR; r++) {
            float sv = sr[r];
#pragma unroll
            for (int j = 0; j < NB; j++) acc[j] += sv * ws[b * NSNR * NB + r * NB + j];
        }
#pragma unroll
        for (int j = 0; j < NB; j++) op[b * NB + j] = acc[j];
    }
}

// ---------------- CSR-by-kj triplet scatter ----------------
__global__ __launch_bounds__(256) void trip_kj_k(
    const __nv_bfloat16* __restrict__ Gh, const float* __restrict__ sbfp,
    const int* __restrict__ idx_ji, const int* __restrict__ off,
    const int* __restrict__ perm, float* __restrict__ Mo)
{
    int e = blockIdx.x * (blockDim.x >> 5) + (threadIdx.x >> 5);
    if (e >= NEDGES) return;
    int lane = threadIdx.x & 31;
    int s0 = off[e], s1 = off[e + 1];
    if (s0 == s1) return;

    float f[NB][4];
    const __nv_bfloat16* gr = Gh + (size_t)e * (NB * HD) + lane * 4;
#pragma unroll
    for (int j = 0; j < NB; j++) {
        uint2 u = *(const uint2*)(gr + j * HD);
        __nv_bfloat162 p0 = *reinterpret_cast<__nv_bfloat162*>(&u.x);
        __nv_bfloat162 p1 = *reinterpret_cast<__nv_bfloat162*>(&u.y);
        float2 a = __bfloat1622float2(p0);
        float2 b = __bfloat1622float2(p1);
        f[j][0] = a.x; f[j][1] = a.y; f[j][2] = b.x; f[j][3] = b.y;
    }

    for (int idx = s0; idx < s1; idx++) {
        int w = perm[idx];
        int ji = idx_ji[w];
        float sv = (lane < NB) ? sbfp[(size_t)w * (NBLK * NB) + lane] : 0.f;
        float4 acc = make_float4(0.f, 0.f, 0.f, 0.f);
#pragma unroll
        for (int j = 0; j < NB; j++) {
            float s = __shfl_sync(0xffffffffu, sv, j);
            acc.x += s * f[j][0]; acc.y += s * f[j][1];
            acc.z += s * f[j][2]; acc.w += s * f[j][3];
        }
        float* mo = Mo + (size_t)ji * HD + lane * 4;
        atomicAdd(mo + 0, acc.x);
        atomicAdd(mo + 1, acc.y);
        atomicAdd(mo + 2, acc.z);
        atomicAdd(mo + 3, acc.w);
    }
}

// ---------------- batched out-block edge scatter ----------------
__global__ void edge_scatter7_k(const float* __restrict__ rbf, const float* __restrict__ orw,
                                const float* __restrict__ xsave, const int* __restrict__ ei,
                                float* __restrict__ atom)
{
    int e = blockIdx.x, k = blockIdx.y, h = threadIdx.x;
    const float* rr = rbf + (size_t)e * NR;
    const float* w = orw + (size_t)k * NR * HD;
    float rp = 0.f;
#pragma unroll
    for (int r = 0; r < NR; r++) rp += rr[r] * w[r * HD + h];
    float v = rp * xsave[(size_t)k * NEDGES * HD + (size_t)e * HD + h];
    atomicAdd(&atom[(size_t)k * NATOMS * HD + (size_t)ei[e] * HD + h], v);
}

// ---------------- batched final per-atom dot + graph segment sum ----------------
__global__ void dot7_k(const float* __restrict__ atom2, const float* __restrict__ ow,
                       const int* __restrict__ batch, float* __restrict__ out)
{
    int a = blockIdx.x * (blockDim.x >> 5) + (threadIdx.x >> 5);
    if (a >= NATOMS) return;
    int k = blockIdx.y;
    int lane = threadIdx.x & 31;
    const float* ar = atom2 + (size_t)k * NATOMS * HD + (size_t)a * HD + lane * 4;
    const float* wr = ow + (size_t)k * HD + lane * 4;
    float s = ar[0] * wr[0] + ar[1] * wr[1] + ar[2] * wr[2] + ar[3] * wr[3];
#pragma unroll
    for (int o = 16; o > 0; o >>= 1) s += __shfl_down_sync(0xffffffffu, s, o);
    if (lane == 0) atomicAdd(&out[batch[a]], s);
}

// ==========================================================================================
extern "C" void kernel_launch(void* const* d_in, const int* in_sizes, int n_in,
                              void* d_out, int out_size)
{
    const int*   z        = (const int*)  d_in[0];
    const float* rbf      = (const float*)d_in[1];
    const float* sbf      = (const float*)d_in[2];
    const int*   ei       = (const int*)  d_in[3];
    const int*   ej       = (const int*)  d_in[4];
    const int*   idx_kj   = (const int*)  d_in[5];
    const int*   idx_ji   = (const int*)  d_in[6];
    const int*   batch    = (const int*)  d_in[7];
    const float* emb_table= (const float*)d_in[8];
    const float* emb_rbf_w= (const float*)d_in[9];
    const float* emb_rbf_b= (const float*)d_in[10];
    const float* emb_w    = (const float*)d_in[11];
    const float* emb_b    = (const float*)d_in[12];
    const float* int_rbf_w= (const float*)d_in[13];
    const float* int_sbf_w= (const float*)d_in[14];
    const float* int_kj_w = (const float*)d_in[15];
    const float* int_kj_b = (const float*)d_in[16];
    const float* int_ji_w = (const float*)d_in[17];
    const float* int_ji_b = (const float*)d_in[18];
    const float* int_W    = (const float*)d_in[19];
    const float* int_bef_w= (const float*)d_in[20];
    const float* int_bef_b= (const float*)d_in[21];
    const float* int_lin_w= (const float*)d_in[22];
    const float* int_lin_b= (const float*)d_in[23];
    const float* int_aft_w= (const float*)d_in[24];
    const float* int_aft_b= (const float*)d_in[25];
    const float* out_rbf_w= (const float*)d_in[26];
    const float* out_lins_w=(const float*)d_in[27];
    const float* out_lins_b=(const float*)d_in[28];
    const float* out_w    = (const float*)d_in[29];
    float* out = (float*)d_out;

    float *XSAVE, *XJI, *SBFP, *ATOM7, *ATOM7B;
    __half *XSH, *AEMBh, *ATOMH, *ATOMH2, *WH;
    __nv_bfloat16* Gh;
    int *CNT, *OFF, *POS, *PERM, *PART;
    cudaGetSymbolAddress((void**)&XSAVE, g_XSAVE);
    cudaGetSymbolAddress((void**)&XSH,   g_XSH);
    cudaGetSymbolAddress((void**)&XJI,   g_XJI);
    cudaGetSymbolAddress((void**)&SBFP,  g_SBFP);
    cudaGetSymbolAddress((void**)&AEMBh, g_AEMBh);
    cudaGetSymbolAddress((void**)&Gh,    g_Gh);
    cudaGetSymbolAddress((void**)&ATOM7, g_ATOM7);
    cudaGetSymbolAddress((void**)&ATOM7B,g_ATOM7B);
    cudaGetSymbolAddress((void**)&ATOMH, g_ATOMH);
    cudaGetSymbolAddress((void**)&ATOMH2,g_ATOMH2);
    cudaGetSymbolAddress((void**)&WH,    g_WH);
    cudaGetSymbolAddress((void**)&CNT,   g_CNT);
    cudaGetSymbolAddress((void**)&OFF,   g_OFF);
    cudaGetSymbolAddress((void**)&POS,   g_POS);
    cudaGetSymbolAddress((void**)&PERM,  g_PERM);
    cudaGetSymbolAddress((void**)&PART,  g_PART);

    const dim3 gE(1, (NEDGES + 127) / 128);
    const dim3 gA7(1, (NATOMS + 127) / 128, 7);
    const size_t EH = (size_t)NEDGES * HD;
    const size_t AH7 = (size_t)NATOMS * HD;
    const int NSCAN = (NEDGES + 1023) / 1024;   // 98

    cudaMemsetAsync(out, 0, NGRAPHS * sizeof(float));
    cudaMemsetAsync(ATOM7, 0, (size_t)7 * AH7 * sizeof(float));
    cudaMemsetAsync(CNT, 0, NEDGES * sizeof(int));
    cudaMemsetAsync(POS, 0, NEDGES * sizeof(int));

    // ---- CSR build by idx_kj (parallel scan) ----
    count_k<<<(NTRIP + 255) / 256, 256>>>(idx_kj, CNT);
    bsum_k<<<NSCAN, 256>>>(CNT, PART);
    pscan_k<<<1, 32>>>(PART, NSCAN);
    offs_k<<<NSCAN, 1024>>>(CNT, PART, OFF, NSCAN);
    place_k<<<(NTRIP + 255) / 256, 256>>>(idx_kj, OFF, POS, PERM);

    auto cw = [&](const float* src, __half* dst, int K, int N, int cnt) {
        long total = (long)cnt * K * N;
        convw_k<<<(unsigned)((total + 255) / 256), 256>>>(src, dst, K, N, total);
    };
    cw(emb_w,      WH + WH_EMB, 3 * HD, HD, 1);
    cw(int_ji_w,   WH + WH_JI,  HD, HD, NBLK);
    cw(int_kj_w,   WH + WH_KJ,  HD, HD, NBLK);
    cw(int_bef_w,  WH + WH_BEF, HD, HD, NBLK * 2);
    cw(int_lin_w,  WH + WH_LIN, HD, HD, NBLK);
    cw(int_aft_w,  WH + WH_AFT, HD, HD, NBLK * 4);
    cw(out_lins_w, WH + WH_OUT, HD, HD, 7 * 3);
    convg_k<<<(NBLK * NB * HD * HD) / 256, 256>>>(int_W, WH + WH_G);

    sbfp_all_k<<<(NTRIP + 127) / 128, 128>>>(sbf, int_sbf_w, SBFP);

    embed_fill_k<<<NEDGES, HD>>>(z, ei, ej, rbf, emb_table, emb_rbf_w, emb_rbf_b, AEMBh);
    gemm_h<<<gE, 256>>>(AEMBh, 1, WH + WH_EMB, emb_b, nullptr,
                        XSAVE, XSH, NEDGES, HD, 3 * HD, 1, 0, 0, 0, 0);

    for (int b = 0; b < NBLK; b++) {
        float*  xa  = XSAVE + (size_t)b * EH;
        float*  xb  = XSAVE + (size_t)(b + 1) * EH;
        __half* xah = XSH   + (size_t)b * EH;
        __half* xbh = XSH   + (size_t)(b + 1) * EH;

        front_k<<<(NEDGES + 63) / 64, 256>>>(
            xah, rbf, int_rbf_w + (size_t)b * NR * HD,
            WH + WH_JI + (size_t)b * HDHD, int_ji_b + (size_t)b * HD,
            WH + WH_KJ + (size_t)b * HDHD, int_kj_b + (size_t)b * HD,
            WH + WH_G + (size_t)b * NB * HDHD,
            XJI, Gh, NEDGES);

        trip_kj_k<<<(NEDGES + 7) / 8, 256>>>(Gh, SBFP + (size_t)b * NB,
                                             idx_ji, OFF, PERM, XJI);

        chain_k<<<(NEDGES + 63) / 64, 256>>>(
            XJI, xa,
            WH + WH_BEF + (size_t)b * 2 * HDHD,
            WH + WH_LIN + (size_t)b * HDHD,
            WH + WH_AFT + (size_t)b * 4 * HDHD,
            int_bef_b + (size_t)b * 2 * HD,
            int_lin_b + (size_t)b * HD,
            int_aft_b + (size_t)b * 4 * HD,
            xb, xbh, NEDGES);
    }

    edge_scatter7_k<<<dim3(NEDGES, 7), HD>>>(rbf, out_rbf_w, XSAVE, ei, ATOM7);
    gemm_h<<<gA7, 256>>>(ATOM7, 0, WH + WH_OUT + 0 * HDHD, out_lins_b + 0 * HD,
                         nullptr, nullptr, ATOMH,
                         NATOMS, HD, HD, 1, AH7, (size_t)3 * HDHD, (size_t)3 * HD, AH7);
    gemm_h<<<gA7, 256>>>(ATOMH, 1, WH + WH_OUT + 1 * HDHD, out_lins_b + 1 * HD,
                         nullptr, nullptr, ATOMH2,
                         NATOMS, HD, HD, 1, AH7, (size_t)3 * HDHD, (size_t)3 * HD, AH7);
    gemm_h<<<gA7, 256>>>(ATOMH2, 1, WH + WH_OUT + 2 * HDHD, out_lins_b + 2 * HD,
                         nullptr, ATOM7B, nullptr,
                         NATOMS, HD, HD, 1, AH7, (size_t)3 * HDHD, (size_t)3 * HD, AH7);
    dot7_k<<<dim3((NATOMS + 7) / 8, 7), 256>>>(ATOM7B, out_w, batch, out);
}